// round 7
// baseline (speedup 1.0000x reference)
#include <cuda_runtime.h>
#include <cuda_bf16.h>
#include <cstdint>
#include <cstddef>

static constexpr int B_  = 2;
static constexpr int T_  = 2048;
static constexpr int C_  = 1024;
static constexpr int H_  = 16;
static constexpr int HD_ = 64;
static constexpr int C3_ = 3 * C_;
static constexpr int M_  = B_ * T_;      // 4096

// ---------------------------------------------------------------------------
// Scratch (__device__ globals; no allocation allowed)
// ---------------------------------------------------------------------------
__device__ __nv_bfloat16 g_xhi[(size_t)M_ * C_];
__device__ __nv_bfloat16 g_xlo[(size_t)M_ * C_];
__device__ __nv_bfloat16 g_wahi[(size_t)C3_ * C_];
__device__ __nv_bfloat16 g_walo[(size_t)C3_ * C_];
__device__ __nv_bfloat16 g_wphi[(size_t)C_ * C_];
__device__ __nv_bfloat16 g_wplo[(size_t)C_ * C_];
__device__ __nv_bfloat16 g_yhi[(size_t)M_ * C_];
__device__ __nv_bfloat16 g_ylo[(size_t)M_ * C_];
// head-major [B][H][T][64] split operands for flash
__device__ __nv_bfloat16 g_qh[(size_t)M_ * C_];
__device__ __nv_bfloat16 g_ql[(size_t)M_ * C_];
__device__ __nv_bfloat16 g_kh[(size_t)M_ * C_];
__device__ __nv_bfloat16 g_kl[(size_t)M_ * C_];
__device__ __nv_bfloat16 g_vh[(size_t)M_ * C_];
__device__ __nv_bfloat16 g_vl[(size_t)M_ * C_];

// ---------------------------------------------------------------------------
// Helpers
// ---------------------------------------------------------------------------
__device__ __forceinline__ uint32_t smem_u32(const void* p) {
    uint32_t a;
    asm("{ .reg .u64 t; cvta.to.shared.u64 t, %1; cvt.u32.u64 %0, t; }" : "=r"(a) : "l"(p));
    return a;
}
#define SWZ128(o) ((o) ^ (((o) >> 3) & 0x70))

__device__ __forceinline__ void cp_async16(uint32_t dst, const void* src) {
    asm volatile("cp.async.cg.shared.global [%0], [%1], 16;" :: "r"(dst), "l"(src));
}
__device__ __forceinline__ void ldsm4(uint32_t& r0, uint32_t& r1, uint32_t& r2, uint32_t& r3,
                                      uint32_t addr) {
    asm volatile("ldmatrix.sync.aligned.m8n8.x4.shared.b16 {%0,%1,%2,%3}, [%4];"
                 : "=r"(r0), "=r"(r1), "=r"(r2), "=r"(r3) : "r"(addr));
}
__device__ __forceinline__ void ldsm4t(uint32_t& r0, uint32_t& r1, uint32_t& r2, uint32_t& r3,
                                       uint32_t addr) {
    asm volatile("ldmatrix.sync.aligned.m8n8.x4.trans.shared.b16 {%0,%1,%2,%3}, [%4];"
                 : "=r"(r0), "=r"(r1), "=r"(r2), "=r"(r3) : "r"(addr));
}
__device__ __forceinline__ void mma16816(float* c, const uint32_t* a, const uint32_t* b) {
    asm volatile(
        "mma.sync.aligned.m16n8k16.row.col.f32.bf16.bf16.f32 "
        "{%0,%1,%2,%3}, {%4,%5,%6,%7}, {%8,%9}, {%0,%1,%2,%3};"
        : "+f"(c[0]), "+f"(c[1]), "+f"(c[2]), "+f"(c[3])
        : "r"(a[0]), "r"(a[1]), "r"(a[2]), "r"(a[3]), "r"(b[0]), "r"(b[1]));
}
__device__ __forceinline__ void split2(float a, float b, uint32_t& hi, uint32_t& lo) {
    __nv_bfloat16 ha = __float2bfloat16_rn(a), hb = __float2bfloat16_rn(b);
    __nv_bfloat162 H(ha, hb);
    __nv_bfloat162 L(__float2bfloat16_rn(a - __bfloat162float(ha)),
                     __float2bfloat16_rn(b - __bfloat162float(hb)));
    hi = *reinterpret_cast<uint32_t*>(&H);
    lo = *reinterpret_cast<uint32_t*>(&L);
}

// ---------------------------------------------------------------------------
// Split fp32 -> (hi, lo) bf16 (for x, w_attn, w_proj)
// ---------------------------------------------------------------------------
__global__ __launch_bounds__(256)
void split_f32(const float* __restrict__ in, __nv_bfloat16* __restrict__ hi,
               __nv_bfloat16* __restrict__ lo, int n4)
{
    int i = blockIdx.x * blockDim.x + threadIdx.x;
    if (i >= n4) return;
    float4 v = reinterpret_cast<const float4*>(in)[i];
    uint32_t h0, l0, h1, l1;
    split2(v.x, v.y, h0, l0);
    split2(v.z, v.w, h1, l1);
    reinterpret_cast<uint32_t*>(hi)[2 * i]     = h0;
    reinterpret_cast<uint32_t*>(hi)[2 * i + 1] = h1;
    reinterpret_cast<uint32_t*>(lo)[2 * i]     = l0;
    reinterpret_cast<uint32_t*>(lo)[2 * i + 1] = l1;
}

// ===========================================================================
// Shared GEMM mainloop machinery: 128x128 tile, BK=32 interleaved hi/lo rows,
// 3-slot cp.async ring (3 x 32KB), ONE __syncthreads per chunk, depth-2
// prefetch. acc += Ahi*Bhi + Alo*Bhi + Ahi*Blo.
// ===========================================================================
static constexpr int GSMEM = 98304;   // 3 x 32KB ring; epilogue staging reuses it

struct GemmCtx {
    uint32_t smem_base;
    int tid, lane, wid, wr, wc, m0, n0;
};

__device__ __forceinline__ void gemm_mainloop(
    const GemmCtx& cx,
    const __nv_bfloat16* __restrict__ Ahi, const __nv_bfloat16* __restrict__ Alo,
    const __nv_bfloat16* __restrict__ Bhi, const __nv_bfloat16* __restrict__ Blo,
    int K, float acc[4][4][4])
{
    const int tid = cx.tid, lane = cx.lane;
    const int NC = K >> 5;

    auto load_chunk = [&](int cg) {
        const uint32_t As = cx.smem_base + (cg % 3) * 32768;
        const uint32_t Bs = As + 16384;
        const int k0 = cg * 32;
#pragma unroll
        for (int i = 0; i < 4; i++) {
            const int u = tid + 256 * i;
            const int row = u >> 3, ch = u & 7;     // ch 0-3: hi, 4-7: lo
            const __nv_bfloat16* srcA = (ch < 4 ? Ahi : Alo) +
                (size_t)(cx.m0 + row) * K + k0 + (ch & 3) * 8;
            cp_async16(As + SWZ128(row * 128 + ch * 16), srcA);
            const __nv_bfloat16* srcB = (ch < 4 ? Bhi : Blo) +
                (size_t)(cx.n0 + row) * K + k0 + (ch & 3) * 8;
            cp_async16(Bs + SWZ128(row * 128 + ch * 16), srcB);
        }
        asm volatile("cp.async.commit_group;");
    };

    load_chunk(0);
    load_chunk(1);
    for (int cg = 0; cg < NC; cg++) {
        if (cg + 1 < NC) asm volatile("cp.async.wait_group 1;");
        else             asm volatile("cp.async.wait_group 0;");
        __syncthreads();
        if (cg + 2 < NC) load_chunk(cg + 2);

        const uint32_t As = cx.smem_base + (cg % 3) * 32768;
        const uint32_t Bs = As + 16384;
#pragma unroll
        for (int ks = 0; ks < 2; ks++) {
            uint32_t bh[4][2], bl[4][2];
#pragma unroll
            for (int p = 0; p < 2; p++) {
                const int g = lane >> 3;
                const int r = cx.wc + p * 16 + (g >> 1) * 8 + (lane & 7);
                const int cb = ks * 32 + (g & 1) * 16;
                ldsm4(bh[2 * p][0], bh[2 * p][1], bh[2 * p + 1][0], bh[2 * p + 1][1],
                      Bs + SWZ128(r * 128 + cb));
                ldsm4(bl[2 * p][0], bl[2 * p][1], bl[2 * p + 1][0], bl[2 * p + 1][1],
                      Bs + SWZ128(r * 128 + 64 + cb));
            }
#pragma unroll
            for (int mi = 0; mi < 4; mi++) {
                const int r = cx.wr + mi * 16 + (lane & 15);
                const int cb = ks * 32 + (lane >> 4) * 16;
                uint32_t ah[4], al[4];
                ldsm4(ah[0], ah[1], ah[2], ah[3], As + SWZ128(r * 128 + cb));
                ldsm4(al[0], al[1], al[2], al[3], As + SWZ128(r * 128 + 64 + cb));
#pragma unroll
                for (int ni = 0; ni < 4; ni++) {
                    mma16816(acc[mi][ni], ah, bh[ni]);
                    mma16816(acc[mi][ni], al, bh[ni]);
                    mma16816(acc[mi][ni], ah, bl[ni]);
                }
            }
        }
    }
}

// ---------------------------------------------------------------------------
// Fused qkv GEMM: x @ w_attn^T, then per-tile RMSNorm+RoPE+split epilogue,
// writing head-major bf16 hi/lo q/k/v directly. N=3072, K=1024.
// ---------------------------------------------------------------------------
__global__ __launch_bounds__(256, 2)
void gemm_qkv_fused(const __nv_bfloat16* __restrict__ Ahi,
                    const __nv_bfloat16* __restrict__ Alo,
                    const __nv_bfloat16* __restrict__ Bhi,
                    const __nv_bfloat16* __restrict__ Blo,
                    const float* __restrict__ fcos, const float* __restrict__ fsin,
                    const float* __restrict__ qnw,  const float* __restrict__ knw,
                    __nv_bfloat16* __restrict__ qh, __nv_bfloat16* __restrict__ ql,
                    __nv_bfloat16* __restrict__ kh, __nv_bfloat16* __restrict__ kl,
                    __nv_bfloat16* __restrict__ vh, __nv_bfloat16* __restrict__ vl)
{
    extern __shared__ char smem[];
    GemmCtx cx;
    cx.smem_base = smem_u32(smem);
    cx.tid = threadIdx.x; cx.lane = cx.tid & 31; cx.wid = cx.tid >> 5;
    cx.wr = (cx.wid >> 2) * 64; cx.wc = (cx.wid & 3) * 32;
    cx.m0 = blockIdx.y * 128; cx.n0 = blockIdx.x * 128;

    float acc[4][4][4];
#pragma unroll
    for (int mi = 0; mi < 4; mi++)
#pragma unroll
        for (int ni = 0; ni < 4; ni++)
#pragma unroll
            for (int e = 0; e < 4; e++) acc[mi][ni][e] = 0.f;

    gemm_mainloop(cx, Ahi, Alo, Bhi, Blo, C_, acc);

    // ---- stage tile to smem (fp32, stride 130) ----
    __syncthreads();
    constexpr int SLD = 130;
    float* stg = reinterpret_cast<float*>(smem);
    const int lane = cx.lane, wid = cx.wid;
#pragma unroll
    for (int mi = 0; mi < 4; mi++) {
        const int r0 = cx.wr + mi * 16 + (lane >> 2);
#pragma unroll
        for (int ni = 0; ni < 4; ni++) {
            const int cc = cx.wc + ni * 8 + (lane & 3) * 2;
            *reinterpret_cast<float2*>(&stg[r0 * SLD + cc]) =
                make_float2(acc[mi][ni][0], acc[mi][ni][1]);
            *reinterpret_cast<float2*>(&stg[(r0 + 8) * SLD + cc]) =
                make_float2(acc[mi][ni][2], acc[mi][ni][3]);
        }
    }
    __syncthreads();

    // ---- per-(row, head) norm/rope/split; 256 tasks, 32 per warp ----
    const int kind  = cx.n0 >> 10;             // 0:q 1:k 2:v
    const int hbase = (cx.n0 & 1023) >> 6;
    const float* wv = (kind == 0) ? qnw : knw;
    const float w0 = (kind < 2) ? wv[2 * lane] : 0.f;
    const float w1 = (kind < 2) ? wv[2 * lane + 1] : 0.f;

    for (int i = 0; i < 32; i++) {
        const int t = wid * 32 + i;
        const int r = t >> 1, hh = t & 1;
        const int bt = cx.m0 + r;
        const int tt = bt & (T_ - 1);
        const int b = bt >> 11;
        const int h = hbase + hh;
        const float f0 = stg[r * SLD + hh * 64 + 2 * lane];
        const float f1 = stg[r * SLD + hh * 64 + 2 * lane + 1];
        const size_t ho = (((size_t)(b * H_ + h) * T_) + tt) * HD_ + 2 * lane;
        uint32_t hi, lo;
        if (kind < 2) {
            float ss = f0 * f0 + f1 * f1;
#pragma unroll
            for (int off = 16; off > 0; off >>= 1)
                ss += __shfl_xor_sync(0xffffffffu, ss, off);
            const float rms = rsqrtf(ss * (1.f / HD_) + 1e-6f);
            const float x0 = f0 * rms * w0;
            const float x1 = f1 * rms * w1;
            const float c = fcos[tt * 32 + lane];
            const float s = fsin[tt * 32 + lane];
            split2(x0 * c - x1 * s, x0 * s + x1 * c, hi, lo);
            if (kind == 0) {
                *reinterpret_cast<uint32_t*>(qh + ho) = hi;
                *reinterpret_cast<uint32_t*>(ql + ho) = lo;
            } else {
                *reinterpret_cast<uint32_t*>(kh + ho) = hi;
                *reinterpret_cast<uint32_t*>(kl + ho) = lo;
            }
        } else {
            split2(f0, f1, hi, lo);
            *reinterpret_cast<uint32_t*>(vh + ho) = hi;
            *reinterpret_cast<uint32_t*>(vl + ho) = lo;
        }
    }
}

// ---------------------------------------------------------------------------
// Plain split-bf16 GEMM (NT) for the output projection (fp32 epilogue).
// ---------------------------------------------------------------------------
__global__ __launch_bounds__(256, 2)
void gemm_mma_split(const __nv_bfloat16* __restrict__ Ahi,
                    const __nv_bfloat16* __restrict__ Alo,
                    const __nv_bfloat16* __restrict__ Bhi,
                    const __nv_bfloat16* __restrict__ Blo,
                    float* __restrict__ Cout, int N, int K)
{
    extern __shared__ char smem[];
    GemmCtx cx;
    cx.smem_base = smem_u32(smem);
    cx.tid = threadIdx.x; cx.lane = cx.tid & 31; cx.wid = cx.tid >> 5;
    cx.wr = (cx.wid >> 2) * 64; cx.wc = (cx.wid & 3) * 32;
    cx.m0 = blockIdx.y * 128; cx.n0 = blockIdx.x * 128;

    float acc[4][4][4];
#pragma unroll
    for (int mi = 0; mi < 4; mi++)
#pragma unroll
        for (int ni = 0; ni < 4; ni++)
#pragma unroll
            for (int e = 0; e < 4; e++) acc[mi][ni][e] = 0.f;

    gemm_mainloop(cx, Ahi, Alo, Bhi, Blo, K, acc);

    const int lane = cx.lane;
#pragma unroll
    for (int mi = 0; mi < 4; mi++) {
        const int m = cx.m0 + cx.wr + mi * 16 + (lane >> 2);
#pragma unroll
        for (int ni = 0; ni < 4; ni++) {
            const int n = cx.n0 + cx.wc + ni * 8 + (lane & 3) * 2;
            *reinterpret_cast<float2*>(Cout + (size_t)m * N + n) =
                make_float2(acc[mi][ni][0], acc[mi][ni][1]);
            *reinterpret_cast<float2*>(Cout + (size_t)(m + 8) * N + n) =
                make_float2(acc[mi][ni][2], acc[mi][ni][3]);
        }
    }
}

// ---------------------------------------------------------------------------
// mma.sync flash attention, causal, split-bf16 (unchanged from R5/R6).
// ---------------------------------------------------------------------------
static constexpr int FSMEM = 98304;

__global__ __launch_bounds__(256, 2)
void flash_mma(const __nv_bfloat16* __restrict__ qh, const __nv_bfloat16* __restrict__ ql,
               const __nv_bfloat16* __restrict__ kh, const __nv_bfloat16* __restrict__ kl,
               const __nv_bfloat16* __restrict__ vh, const __nv_bfloat16* __restrict__ vl,
               __nv_bfloat16* __restrict__ yhi, __nv_bfloat16* __restrict__ ylo)
{
    extern __shared__ char smem[];
    const uint32_t sb = smem_u32(smem);
    const int tid = threadIdx.x, lane = tid & 31, wid = tid >> 5;
    const int gid = lane >> 2, tig = lane & 3;
    const int bh = blockIdx.y;
    const int q0 = (gridDim.x - 1 - blockIdx.x) * 128;
    const size_t head = (size_t)bh * T_ * HD_;

    const uint32_t QHI = sb, QLO = sb + 16384;
    auto KV = [&](int buf, int t) -> uint32_t { return sb + 32768 + buf * 32768 + t * 8192; };

    {
#pragma unroll
        for (int i = 0; i < 4; i++) {
            int u = tid + 256 * i, r = u >> 3, ch = u & 7;
            uint32_t so = SWZ128(r * 128 + ch * 16);
            size_t go = head + (size_t)(q0 + r) * HD_ + ch * 8;
            cp_async16(QHI + so, qh + go);
            cp_async16(QLO + so, ql + go);
        }
#pragma unroll
        for (int i = 0; i < 2; i++) {
            int u = tid + 256 * i, r = u >> 3, ch = u & 7;
            uint32_t so = SWZ128(r * 128 + ch * 16);
            size_t go = head + (size_t)r * HD_ + ch * 8;
            cp_async16(KV(0, 0) + so, kh + go);
            cp_async16(KV(0, 1) + so, kl + go);
            cp_async16(KV(0, 2) + so, vh + go);
            cp_async16(KV(0, 3) + so, vl + go);
        }
        asm volatile("cp.async.commit_group;");
    }

    float O[8][4];
#pragma unroll
    for (int nt = 0; nt < 8; nt++)
#pragma unroll
        for (int e = 0; e < 4; e++) O[nt][e] = 0.f;
    float mrow0 = -1e30f, mrow1 = -1e30f, lrow0 = 0.f, lrow1 = 0.f;

    const int warp_top = q0 + wid * 16;
    const int niter = (q0 + 128) / 64;

    for (int it = 0; it < niter; it++) {
        asm volatile("cp.async.wait_group 0;");
        __syncthreads();
        const int cur = it & 1;
        if (it + 1 < niter) {
            const int nxt = 1 - cur;
            const size_t koff = head + (size_t)(it + 1) * 64 * HD_;
#pragma unroll
            for (int i = 0; i < 2; i++) {
                int u = tid + 256 * i, r = u >> 3, ch = u & 7;
                uint32_t so = SWZ128(r * 128 + ch * 16);
                size_t go = koff + (size_t)r * HD_ + ch * 8;
                cp_async16(KV(nxt, 0) + so, kh + go);
                cp_async16(KV(nxt, 1) + so, kl + go);
                cp_async16(KV(nxt, 2) + so, vh + go);
                cp_async16(KV(nxt, 3) + so, vl + go);
            }
            asm volatile("cp.async.commit_group;");
        }

        const int j0 = it * 64;
        if (j0 > warp_top + 15) continue;

        float S[8][4];
#pragma unroll
        for (int nt = 0; nt < 8; nt++)
#pragma unroll
            for (int e = 0; e < 4; e++) S[nt][e] = 0.f;

        const uint32_t Kb0 = KV(cur, 0), Kb1 = KV(cur, 1);
#pragma unroll
        for (int pass = 0; pass < 3; pass++) {
            const uint32_t Qb = (pass == 1) ? QLO : QHI;
            const uint32_t Kb = (pass == 2) ? Kb1 : Kb0;
#pragma unroll
            for (int ks = 0; ks < 4; ks++) {
                const int k0 = ks * 16;
                uint32_t a[4];
                ldsm4(a[0], a[1], a[2], a[3],
                      Qb + SWZ128((wid * 16 + (lane & 15)) * 128 + (k0 + (lane >> 4) * 8) * 2));
                uint32_t b[8][2];
#pragma unroll
                for (int p = 0; p < 4; p++) {
                    const int g = lane >> 3;
                    const int r = p * 16 + (g >> 1) * 8 + (lane & 7);
                    ldsm4(b[2 * p][0], b[2 * p][1], b[2 * p + 1][0], b[2 * p + 1][1],
                          Kb + SWZ128(r * 128 + (k0 + (g & 1) * 8) * 2));
                }
#pragma unroll
                for (int nt = 0; nt < 8; nt++) mma16816(S[nt], a, b[nt]);
            }
        }

        const int qi0 = warp_top + gid;
        if (j0 + 63 > warp_top) {
#pragma unroll
            for (int nt = 0; nt < 8; nt++)
#pragma unroll
                for (int e = 0; e < 4; e++) {
                    const int kj = j0 + nt * 8 + 2 * tig + (e & 1);
                    const int qi = qi0 + ((e >= 2) ? 8 : 0);
                    S[nt][e] = (kj <= qi) ? S[nt][e] * 0.125f : -1e30f;
                }
        } else {
#pragma unroll
            for (int nt = 0; nt < 8; nt++)
#pragma unroll
                for (int e = 0; e < 4; e++) S[nt][e] *= 0.125f;
        }

        float mx0 = -1e30f, mx1 = -1e30f;
#pragma unroll
        for (int nt = 0; nt < 8; nt++) {
            mx0 = fmaxf(mx0, fmaxf(S[nt][0], S[nt][1]));
            mx1 = fmaxf(mx1, fmaxf(S[nt][2], S[nt][3]));
        }
        mx0 = fmaxf(mx0, __shfl_xor_sync(0xffffffffu, mx0, 1));
        mx0 = fmaxf(mx0, __shfl_xor_sync(0xffffffffu, mx0, 2));
        mx1 = fmaxf(mx1, __shfl_xor_sync(0xffffffffu, mx1, 1));
        mx1 = fmaxf(mx1, __shfl_xor_sync(0xffffffffu, mx1, 2));
        const float mn0 = fmaxf(mrow0, mx0), mn1 = fmaxf(mrow1, mx1);
        const float al0 = __expf(mrow0 - mn0), al1 = __expf(mrow1 - mn1);
        float ps0 = 0.f, ps1 = 0.f;
#pragma unroll
        for (int nt = 0; nt < 8; nt++) {
            S[nt][0] = __expf(S[nt][0] - mn0);
            S[nt][1] = __expf(S[nt][1] - mn0);
            S[nt][2] = __expf(S[nt][2] - mn1);
            S[nt][3] = __expf(S[nt][3] - mn1);
            ps0 += S[nt][0] + S[nt][1];
            ps1 += S[nt][2] + S[nt][3];
        }
        ps0 += __shfl_xor_sync(0xffffffffu, ps0, 1);
        ps0 += __shfl_xor_sync(0xffffffffu, ps0, 2);
        ps1 += __shfl_xor_sync(0xffffffffu, ps1, 1);
        ps1 += __shfl_xor_sync(0xffffffffu, ps1, 2);
        lrow0 = lrow0 * al0 + ps0;
        lrow1 = lrow1 * al1 + ps1;
        mrow0 = mn0;
        mrow1 = mn1;
#pragma unroll
        for (int nt = 0; nt < 8; nt++) {
            O[nt][0] *= al0; O[nt][1] *= al0;
            O[nt][2] *= al1; O[nt][3] *= al1;
        }

        uint32_t Phi[4][4], Plo[4][4];
#pragma unroll
        for (int kt = 0; kt < 4; kt++) {
            split2(S[2 * kt][0],     S[2 * kt][1],     Phi[kt][0], Plo[kt][0]);
            split2(S[2 * kt][2],     S[2 * kt][3],     Phi[kt][1], Plo[kt][1]);
            split2(S[2 * kt + 1][0], S[2 * kt + 1][1], Phi[kt][2], Plo[kt][2]);
            split2(S[2 * kt + 1][2], S[2 * kt + 1][3], Phi[kt][3], Plo[kt][3]);
        }

        const uint32_t Vh = KV(cur, 2), Vlb = KV(cur, 3);
#pragma unroll
        for (int ks = 0; ks < 4; ks++) {
            uint32_t vb[8][2];
#pragma unroll
            for (int p = 0; p < 4; p++) {
                const int g = lane >> 3;
                const int r = ks * 16 + (g & 1) * 8 + (lane & 7);
                const int cb = (p * 16 + (g >> 1) * 8) * 2;
                ldsm4t(vb[2 * p][0], vb[2 * p][1], vb[2 * p + 1][0], vb[2 * p + 1][1],
                       Vh + SWZ128(r * 128 + cb));
            }
#pragma unroll
            for (int nt = 0; nt < 8; nt++) mma16816(O[nt], Phi[ks], vb[nt]);
#pragma unroll
            for (int nt = 0; nt < 8; nt++) mma16816(O[nt], Plo[ks], vb[nt]);
#pragma unroll
            for (int p = 0; p < 4; p++) {
                const int g = lane >> 3;
                const int r = ks * 16 + (g & 1) * 8 + (lane & 7);
                const int cb = (p * 16 + (g >> 1) * 8) * 2;
                ldsm4t(vb[2 * p][0], vb[2 * p][1], vb[2 * p + 1][0], vb[2 * p + 1][1],
                       Vlb + SWZ128(r * 128 + cb));
            }
#pragma unroll
            for (int nt = 0; nt < 8; nt++) mma16816(O[nt], Phi[ks], vb[nt]);
        }
    }

    const float inv0 = 1.0f / lrow0, inv1 = 1.0f / lrow1;
    const int b = bh >> 4, h = bh & 15;
    const size_t row0 = ((size_t)(b * T_ + warp_top + gid)) * C_ + h * HD_;
    const size_t row1 = row0 + (size_t)8 * C_;
#pragma unroll
    for (int nt = 0; nt < 8; nt++) {
        const int col = nt * 8 + 2 * tig;
        uint32_t hi, lo;
        split2(O[nt][0] * inv0, O[nt][1] * inv0, hi, lo);
        *reinterpret_cast<uint32_t*>(yhi + row0 + col) = hi;
        *reinterpret_cast<uint32_t*>(ylo + row0 + col) = lo;
        split2(O[nt][2] * inv1, O[nt][3] * inv1, hi, lo);
        *reinterpret_cast<uint32_t*>(yhi + row1 + col) = hi;
        *reinterpret_cast<uint32_t*>(ylo + row1 + col) = lo;
    }
}

// ---------------------------------------------------------------------------
extern "C" void kernel_launch(void* const* d_in, const int* in_sizes, int n_in,
                              void* d_out, int out_size)
{
    const float* x      = (const float*)d_in[0];
    const float* fcos   = (const float*)d_in[1];
    const float* fsin   = (const float*)d_in[2];
    const float* w_attn = (const float*)d_in[3];
    const float* w_proj = (const float*)d_in[4];
    const float* qw     = (const float*)d_in[5];
    const float* kw     = (const float*)d_in[6];
    float* out = (float*)d_out;

    __nv_bfloat16 *xhi, *xlo, *wahi, *walo, *wphi, *wplo, *yhi, *ylo;
    __nv_bfloat16 *qh, *ql, *kh, *kl, *vh, *vl;
    cudaGetSymbolAddress((void**)&xhi,  g_xhi);
    cudaGetSymbolAddress((void**)&xlo,  g_xlo);
    cudaGetSymbolAddress((void**)&wahi, g_wahi);
    cudaGetSymbolAddress((void**)&walo, g_walo);
    cudaGetSymbolAddress((void**)&wphi, g_wphi);
    cudaGetSymbolAddress((void**)&wplo, g_wplo);
    cudaGetSymbolAddress((void**)&yhi,  g_yhi);
    cudaGetSymbolAddress((void**)&ylo,  g_ylo);
    cudaGetSymbolAddress((void**)&qh,   g_qh);
    cudaGetSymbolAddress((void**)&ql,   g_ql);
    cudaGetSymbolAddress((void**)&kh,   g_kh);
    cudaGetSymbolAddress((void**)&kl,   g_kl);
    cudaGetSymbolAddress((void**)&vh,   g_vh);
    cudaGetSymbolAddress((void**)&vl,   g_vl);

    cudaFuncSetAttribute(gemm_qkv_fused, cudaFuncAttributeMaxDynamicSharedMemorySize, GSMEM);
    cudaFuncSetAttribute(gemm_mma_split, cudaFuncAttributeMaxDynamicSharedMemorySize, GSMEM);
    cudaFuncSetAttribute(flash_mma, cudaFuncAttributeMaxDynamicSharedMemorySize, FSMEM);

    // 1) split inputs to (hi, lo) bf16
    {
        int n4 = (M_ * C_) / 4;
        split_f32<<<(n4 + 255) / 256, 256>>>(x, xhi, xlo, n4);
        n4 = (C3_ * C_) / 4;
        split_f32<<<(n4 + 255) / 256, 256>>>(w_attn, wahi, walo, n4);
        n4 = (C_ * C_) / 4;
        split_f32<<<(n4 + 255) / 256, 256>>>(w_proj, wphi, wplo, n4);
    }

    // 2) fused qkv GEMM + RMSNorm + RoPE + split -> head-major bf16
    {
        dim3 g(C3_ / 128, M_ / 128);
        gemm_qkv_fused<<<g, 256, GSMEM>>>(xhi, xlo, wahi, walo, fcos, fsin, qw, kw,
                                          qh, ql, kh, kl, vh, vl);
    }

    // 3) causal flash attention (tensor-core) -> yhi/ylo
    {
        dim3 g(T_ / 128, B_ * H_);
        flash_mma<<<g, 256, FSMEM>>>(qh, ql, kh, kl, vh, vl, yhi, ylo);
    }

    // 4) out = y @ w_proj^T
    {
        dim3 g(C_ / 128, M_ / 128);
        gemm_mma_split<<<g, 256, GSMEM>>>(yhi, ylo, wphi, wplo, out, C_, C_);
    }
}

// round 8
// speedup vs baseline: 1.4671x; 1.4671x over previous
#include <cuda_runtime.h>
#include <cuda_fp16.h>
#include <cstdint>
#include <cstddef>

static constexpr int B_  = 2;
static constexpr int T_  = 2048;
static constexpr int C_  = 1024;
static constexpr int H_  = 16;
static constexpr int HD_ = 64;
static constexpr int C3_ = 3 * C_;
static constexpr int M_  = B_ * T_;      // 4096

// ---------------------------------------------------------------------------
// Scratch (__device__ globals; no allocation allowed)
// ---------------------------------------------------------------------------
__device__ float g_qkv[(size_t)M_ * C3_];            // fp32 qkv (50 MB)
__device__ __half g_xf[(size_t)M_ * C_];             // x fp16 1-term
__device__ __half g_wah[(size_t)C3_ * C_];           // w_attn hi
__device__ __half g_wal[(size_t)C3_ * C_];           // w_attn lo
__device__ __half g_wph[(size_t)C_ * C_];
__device__ __half g_wpl[(size_t)C_ * C_];
__device__ __half g_yf[(size_t)M_ * C_];             // attention out fp16 1-term
// head-major [B][H][T][64]
__device__ __half g_qh[(size_t)M_ * C_];
__device__ __half g_ql[(size_t)M_ * C_];
__device__ __half g_kh[(size_t)M_ * C_];             // K 1-term
__device__ __half g_vh[(size_t)M_ * C_];             // V 1-term

// ---------------------------------------------------------------------------
// Helpers
// ---------------------------------------------------------------------------
__device__ __forceinline__ uint32_t smem_u32(const void* p) {
    uint32_t a;
    asm("{ .reg .u64 t; cvta.to.shared.u64 t, %1; cvt.u32.u64 %0, t; }" : "=r"(a) : "l"(p));
    return a;
}
#define SWZ128(o) ((o) ^ (((o) >> 3) & 0x70))

__device__ __forceinline__ void cp_async16(uint32_t dst, const void* src) {
    asm volatile("cp.async.cg.shared.global [%0], [%1], 16;" :: "r"(dst), "l"(src));
}
__device__ __forceinline__ void ldsm4(uint32_t& r0, uint32_t& r1, uint32_t& r2, uint32_t& r3,
                                      uint32_t addr) {
    asm volatile("ldmatrix.sync.aligned.m8n8.x4.shared.b16 {%0,%1,%2,%3}, [%4];"
                 : "=r"(r0), "=r"(r1), "=r"(r2), "=r"(r3) : "r"(addr));
}
__device__ __forceinline__ void ldsm4t(uint32_t& r0, uint32_t& r1, uint32_t& r2, uint32_t& r3,
                                       uint32_t addr) {
    asm volatile("ldmatrix.sync.aligned.m8n8.x4.trans.shared.b16 {%0,%1,%2,%3}, [%4];"
                 : "=r"(r0), "=r"(r1), "=r"(r2), "=r"(r3) : "r"(addr));
}
__device__ __forceinline__ void mma16816h(float* c, const uint32_t* a, const uint32_t* b) {
    asm volatile(
        "mma.sync.aligned.m16n8k16.row.col.f32.f16.f16.f32 "
        "{%0,%1,%2,%3}, {%4,%5,%6,%7}, {%8,%9}, {%0,%1,%2,%3};"
        : "+f"(c[0]), "+f"(c[1]), "+f"(c[2]), "+f"(c[3])
        : "r"(a[0]), "r"(a[1]), "r"(a[2]), "r"(a[3]), "r"(b[0]), "r"(b[1]));
}
__device__ __forceinline__ uint32_t pack_h2(float a, float b) {
    __half2 h(__float2half_rn(a), __float2half_rn(b));
    return *reinterpret_cast<uint32_t*>(&h);
}
__device__ __forceinline__ void split2h(float a, float b, uint32_t& hi, uint32_t& lo) {
    __half ha = __float2half_rn(a), hb = __float2half_rn(b);
    __half2 H(ha, hb);
    __half2 L(__float2half_rn(a - __half2float(ha)), __float2half_rn(b - __half2float(hb)));
    hi = *reinterpret_cast<uint32_t*>(&H);
    lo = *reinterpret_cast<uint32_t*>(&L);
}

// ---------------------------------------------------------------------------
// fp32 -> fp16 convert (activations, 1-term)
// ---------------------------------------------------------------------------
__global__ __launch_bounds__(256)
void conv_f16(const float* __restrict__ in, __half* __restrict__ out, int n4)
{
    int i = blockIdx.x * blockDim.x + threadIdx.x;
    if (i >= n4) return;
    float4 v = reinterpret_cast<const float4*>(in)[i];
    reinterpret_cast<uint32_t*>(out)[2 * i]     = pack_h2(v.x, v.y);
    reinterpret_cast<uint32_t*>(out)[2 * i + 1] = pack_h2(v.z, v.w);
}

// fp32 -> (hi, lo) fp16 split (weights, 2-term)
__global__ __launch_bounds__(256)
void split_f16(const float* __restrict__ in, __half* __restrict__ hi,
               __half* __restrict__ lo, int n4)
{
    int i = blockIdx.x * blockDim.x + threadIdx.x;
    if (i >= n4) return;
    float4 v = reinterpret_cast<const float4*>(in)[i];
    uint32_t h0, l0, h1, l1;
    split2h(v.x, v.y, h0, l0);
    split2h(v.z, v.w, h1, l1);
    reinterpret_cast<uint32_t*>(hi)[2 * i]     = h0;
    reinterpret_cast<uint32_t*>(hi)[2 * i + 1] = h1;
    reinterpret_cast<uint32_t*>(lo)[2 * i]     = l0;
    reinterpret_cast<uint32_t*>(lo)[2 * i + 1] = l1;
}

// ---------------------------------------------------------------------------
// fp16 2-term GEMM (NT): C[m][n] = sum_k A[m][k] * (Bhi+Blo)[n][k]
// A 1-term fp16; B split. 128x128 tile, BK=64, 8 warps (64x32 warp tiles),
// double-buffered smem chunks of 48KB (A 16K | Bh 16K | Bl 16K).
// ---------------------------------------------------------------------------
static constexpr int GSMEM = 98304;   // 2 x 49152

__global__ __launch_bounds__(256, 2)
void gemm_f16_2t(const __half* __restrict__ A,
                 const __half* __restrict__ Bhi, const __half* __restrict__ Blo,
                 float* __restrict__ Cout, int N, int K)
{
    extern __shared__ char smem[];
    const uint32_t smem_base = smem_u32(smem);
    const int tid  = threadIdx.x;
    const int lane = tid & 31;
    const int wid  = tid >> 5;
    const int wr = (wid >> 2) * 64;
    const int wc = (wid & 3) * 32;
    const int m0 = blockIdx.y * 128;
    const int n0 = blockIdx.x * 128;

    float acc[4][4][4];
#pragma unroll
    for (int mi = 0; mi < 4; mi++)
#pragma unroll
        for (int ni = 0; ni < 4; ni++)
#pragma unroll
            for (int e = 0; e < 4; e++) acc[mi][ni][e] = 0.f;

    const int NC = K >> 6;      // 64-wide chunks

    auto load_chunk = [&](int cg) {
        const uint32_t base = smem_base + (cg & 1) * 49152;
        const int k0 = cg * 64;
#pragma unroll
        for (int i = 0; i < 4; i++) {
            const int u = tid + 256 * i;          // 0..1023
            const int row = u >> 3, ch = u & 7;   // 8 x 16B per 128B row
            const uint32_t so = SWZ128(row * 128 + ch * 16);
            cp_async16(base + so,         A   + (size_t)(m0 + row) * K + k0 + ch * 8);
            cp_async16(base + 16384 + so, Bhi + (size_t)(n0 + row) * K + k0 + ch * 8);
            cp_async16(base + 32768 + so, Blo + (size_t)(n0 + row) * K + k0 + ch * 8);
        }
        asm volatile("cp.async.commit_group;");
    };

    load_chunk(0);
    for (int cg = 0; cg < NC; cg++) {
        if (cg + 1 < NC) {
            load_chunk(cg + 1);
            asm volatile("cp.async.wait_group 1;");
        } else {
            asm volatile("cp.async.wait_group 0;");
        }
        __syncthreads();

        const uint32_t As = smem_base + (cg & 1) * 49152;
        const uint32_t Bh = As + 16384;
        const uint32_t Bl = As + 32768;
#pragma unroll
        for (int ks = 0; ks < 4; ks++) {
            const int cbb = ks * 32;
            uint32_t bh[4][2], bl[4][2];
#pragma unroll
            for (int p = 0; p < 2; p++) {
                const int g = lane >> 3;
                const int r = wc + p * 16 + (g >> 1) * 8 + (lane & 7);
                const int cb = cbb + (g & 1) * 16;
                ldsm4(bh[2 * p][0], bh[2 * p][1], bh[2 * p + 1][0], bh[2 * p + 1][1],
                      Bh + SWZ128(r * 128 + cb));
                ldsm4(bl[2 * p][0], bl[2 * p][1], bl[2 * p + 1][0], bl[2 * p + 1][1],
                      Bl + SWZ128(r * 128 + cb));
            }
#pragma unroll
            for (int mi = 0; mi < 4; mi++) {
                const int r = wr + mi * 16 + (lane & 15);
                const int cb = cbb + (lane >> 4) * 16;
                uint32_t a[4];
                ldsm4(a[0], a[1], a[2], a[3], As + SWZ128(r * 128 + cb));
#pragma unroll
                for (int ni = 0; ni < 4; ni++) {
                    mma16816h(acc[mi][ni], a, bh[ni]);
                    mma16816h(acc[mi][ni], a, bl[ni]);
                }
            }
        }
        __syncthreads();
    }

#pragma unroll
    for (int mi = 0; mi < 4; mi++) {
        const int m = m0 + wr + mi * 16 + (lane >> 2);
#pragma unroll
        for (int ni = 0; ni < 4; ni++) {
            const int n = n0 + wc + ni * 8 + (lane & 3) * 2;
            *reinterpret_cast<float2*>(Cout + (size_t)m * N + n) =
                make_float2(acc[mi][ni][0], acc[mi][ni][1]);
            *reinterpret_cast<float2*>(Cout + (size_t)(m + 8) * N + n) =
                make_float2(acc[mi][ni][2], acc[mi][ni][3]);
        }
    }
}

// ---------------------------------------------------------------------------
// Fused per-head RMSNorm + RoPE + fp16 conversion, head-major [B][H][T][64].
// Q -> 2-term (qh, ql); K, V -> 1-term. One warp per (bt, h).
// ---------------------------------------------------------------------------
__global__ __launch_bounds__(256)
void norm_rope_split(const float* __restrict__ qkv, const float* __restrict__ cosT,
                     const float* __restrict__ sinT, const float* __restrict__ qw,
                     const float* __restrict__ kw,
                     __half* __restrict__ qh, __half* __restrict__ ql,
                     __half* __restrict__ kh, __half* __restrict__ vh)
{
    const int gw = (blockIdx.x * blockDim.x + threadIdx.x) >> 5;
    const int lane = threadIdx.x & 31;
    const int h = gw & (H_ - 1);
    const int bt = gw >> 4;
    const int t = bt & (T_ - 1);
    const int b = bt >> 11;

    const float* qp = qkv + (size_t)bt * C3_ + h * HD_;
    const float* kp = qp + C_;
    const float* vp = qp + 2 * C_;
    const size_t ho = (((size_t)(b * H_ + h) * T_) + t) * HD_ + 2 * lane;
    const float c = cosT[t * (HD_ / 2) + lane];
    const float s = sinT[t * (HD_ / 2) + lane];

    {
        float2 v = *reinterpret_cast<const float2*>(qp + 2 * lane);
        float ss = v.x * v.x + v.y * v.y;
#pragma unroll
        for (int off = 16; off > 0; off >>= 1) ss += __shfl_xor_sync(0xffffffffu, ss, off);
        float rms = rsqrtf(ss * (1.f / HD_) + 1e-6f);
        float x0 = v.x * rms * qw[2 * lane];
        float x1 = v.y * rms * qw[2 * lane + 1];
        uint32_t hi, lo;
        split2h(x0 * c - x1 * s, x0 * s + x1 * c, hi, lo);
        *reinterpret_cast<uint32_t*>(qh + ho) = hi;
        *reinterpret_cast<uint32_t*>(ql + ho) = lo;
    }
    {
        float2 v = *reinterpret_cast<const float2*>(kp + 2 * lane);
        float ss = v.x * v.x + v.y * v.y;
#pragma unroll
        for (int off = 16; off > 0; off >>= 1) ss += __shfl_xor_sync(0xffffffffu, ss, off);
        float rms = rsqrtf(ss * (1.f / HD_) + 1e-6f);
        float x0 = v.x * rms * kw[2 * lane];
        float x1 = v.y * rms * kw[2 * lane + 1];
        *reinterpret_cast<uint32_t*>(kh + ho) = pack_h2(x0 * c - x1 * s, x0 * s + x1 * c);
    }
    {
        float2 v = *reinterpret_cast<const float2*>(vp + 2 * lane);
        *reinterpret_cast<uint32_t*>(vh + ho) = pack_h2(v.x, v.y);
    }
}

// ---------------------------------------------------------------------------
// fp16 flash attention, causal. Q 2-term, K 1-term, P 2-term, V 1-term.
// BQ=128 (8 warps x 16 rows), BKV=64.
// smem: QH 16K, QL 16K, 2 x (K 8K + V 8K) = 64 KB.
// ---------------------------------------------------------------------------
static constexpr int FSMEM = 65536;

__global__ __launch_bounds__(256, 2)
void flash_mma(const __half* __restrict__ qh, const __half* __restrict__ ql,
               const __half* __restrict__ kh, const __half* __restrict__ vh,
               __half* __restrict__ yf)
{
    extern __shared__ char smem[];
    const uint32_t sb = smem_u32(smem);
    const int tid = threadIdx.x, lane = tid & 31, wid = tid >> 5;
    const int gid = lane >> 2, tig = lane & 3;
    const int bh = blockIdx.y;
    const int q0 = (gridDim.x - 1 - blockIdx.x) * 128;   // heavy tiles first
    const size_t head = (size_t)bh * T_ * HD_;

    const uint32_t QHI = sb, QLO = sb + 16384;
    auto KV = [&](int buf, int t) -> uint32_t { return sb + 32768 + buf * 16384 + t * 8192; };

    {
#pragma unroll
        for (int i = 0; i < 4; i++) {
            int u = tid + 256 * i, r = u >> 3, ch = u & 7;
            uint32_t so = SWZ128(r * 128 + ch * 16);
            size_t go = head + (size_t)(q0 + r) * HD_ + ch * 8;
            cp_async16(QHI + so, qh + go);
            cp_async16(QLO + so, ql + go);
        }
#pragma unroll
        for (int i = 0; i < 2; i++) {
            int u = tid + 256 * i, r = u >> 3, ch = u & 7;
            uint32_t so = SWZ128(r * 128 + ch * 16);
            size_t go = head + (size_t)r * HD_ + ch * 8;
            cp_async16(KV(0, 0) + so, kh + go);
            cp_async16(KV(0, 1) + so, vh + go);
        }
        asm volatile("cp.async.commit_group;");
    }

    float O[8][4];
#pragma unroll
    for (int nt = 0; nt < 8; nt++)
#pragma unroll
        for (int e = 0; e < 4; e++) O[nt][e] = 0.f;
    float mrow0 = -1e30f, mrow1 = -1e30f, lrow0 = 0.f, lrow1 = 0.f;

    const int warp_top = q0 + wid * 16;
    const int niter = (q0 + 128) / 64;

    for (int it = 0; it < niter; it++) {
        asm volatile("cp.async.wait_group 0;");
        __syncthreads();
        const int cur = it & 1;
        if (it + 1 < niter) {
            const int nxt = 1 - cur;
            const size_t koff = head + (size_t)(it + 1) * 64 * HD_;
#pragma unroll
            for (int i = 0; i < 2; i++) {
                int u = tid + 256 * i, r = u >> 3, ch = u & 7;
                uint32_t so = SWZ128(r * 128 + ch * 16);
                size_t go = koff + (size_t)r * HD_ + ch * 8;
                cp_async16(KV(nxt, 0) + so, kh + go);
                cp_async16(KV(nxt, 1) + so, vh + go);
            }
            asm volatile("cp.async.commit_group;");
        }

        const int j0 = it * 64;
        if (j0 > warp_top + 15) continue;   // warp fully masked this tile

        // ---- S = scale * (Qh K^T + Ql K^T) ----
        float S[8][4];
#pragma unroll
        for (int nt = 0; nt < 8; nt++)
#pragma unroll
            for (int e = 0; e < 4; e++) S[nt][e] = 0.f;

        const uint32_t Kb = KV(cur, 0);
#pragma unroll
        for (int ks = 0; ks < 4; ks++) {
            const int k0 = ks * 16;
            uint32_t b[8][2];
#pragma unroll
            for (int p = 0; p < 4; p++) {
                const int g = lane >> 3;
                const int r = p * 16 + (g >> 1) * 8 + (lane & 7);
                ldsm4(b[2 * p][0], b[2 * p][1], b[2 * p + 1][0], b[2 * p + 1][1],
                      Kb + SWZ128(r * 128 + (k0 + (g & 1) * 8) * 2));
            }
            const uint32_t qoff = SWZ128((wid * 16 + (lane & 15)) * 128 +
                                         (k0 + (lane >> 4) * 8) * 2);
            uint32_t aH[4], aL[4];
            ldsm4(aH[0], aH[1], aH[2], aH[3], QHI + qoff);
            ldsm4(aL[0], aL[1], aL[2], aL[3], QLO + qoff);
#pragma unroll
            for (int nt = 0; nt < 8; nt++) mma16816h(S[nt], aH, b[nt]);
#pragma unroll
            for (int nt = 0; nt < 8; nt++) mma16816h(S[nt], aL, b[nt]);
        }

        // ---- scale + causal mask ----
        const int qi0 = warp_top + gid;
        if (j0 + 63 > warp_top) {
#pragma unroll
            for (int nt = 0; nt < 8; nt++)
#pragma unroll
                for (int e = 0; e < 4; e++) {
                    const int kj = j0 + nt * 8 + 2 * tig + (e & 1);
                    const int qi = qi0 + ((e >= 2) ? 8 : 0);
                    S[nt][e] = (kj <= qi) ? S[nt][e] * 0.125f : -1e30f;
                }
        } else {
#pragma unroll
            for (int nt = 0; nt < 8; nt++)
#pragma unroll
                for (int e = 0; e < 4; e++) S[nt][e] *= 0.125f;
        }

        // ---- online softmax (2 rows per thread) ----
        float mx0 = -1e30f, mx1 = -1e30f;
#pragma unroll
        for (int nt = 0; nt < 8; nt++) {
            mx0 = fmaxf(mx0, fmaxf(S[nt][0], S[nt][1]));
            mx1 = fmaxf(mx1, fmaxf(S[nt][2], S[nt][3]));
        }
        mx0 = fmaxf(mx0, __shfl_xor_sync(0xffffffffu, mx0, 1));
        mx0 = fmaxf(mx0, __shfl_xor_sync(0xffffffffu, mx0, 2));
        mx1 = fmaxf(mx1, __shfl_xor_sync(0xffffffffu, mx1, 1));
        mx1 = fmaxf(mx1, __shfl_xor_sync(0xffffffffu, mx1, 2));
        const float mn0 = fmaxf(mrow0, mx0), mn1 = fmaxf(mrow1, mx1);
        const float al0 = __expf(mrow0 - mn0), al1 = __expf(mrow1 - mn1);
        float ps0 = 0.f, ps1 = 0.f;
#pragma unroll
        for (int nt = 0; nt < 8; nt++) {
            S[nt][0] = __expf(S[nt][0] - mn0);
            S[nt][1] = __expf(S[nt][1] - mn0);
            S[nt][2] = __expf(S[nt][2] - mn1);
            S[nt][3] = __expf(S[nt][3] - mn1);
            ps0 += S[nt][0] + S[nt][1];
            ps1 += S[nt][2] + S[nt][3];
        }
        ps0 += __shfl_xor_sync(0xffffffffu, ps0, 1);
        ps0 += __shfl_xor_sync(0xffffffffu, ps0, 2);
        ps1 += __shfl_xor_sync(0xffffffffu, ps1, 1);
        ps1 += __shfl_xor_sync(0xffffffffu, ps1, 2);
        lrow0 = lrow0 * al0 + ps0;
        lrow1 = lrow1 * al1 + ps1;
        mrow0 = mn0;
        mrow1 = mn1;
#pragma unroll
        for (int nt = 0; nt < 8; nt++) {
            O[nt][0] *= al0; O[nt][1] *= al0;
            O[nt][2] *= al1; O[nt][3] *= al1;
        }

        // ---- pack P hi/lo fp16 fragments (S acc layout == A frag layout) ----
        uint32_t Phi[4][4], Plo[4][4];
#pragma unroll
        for (int kt = 0; kt < 4; kt++) {
            split2h(S[2 * kt][0],     S[2 * kt][1],     Phi[kt][0], Plo[kt][0]);
            split2h(S[2 * kt][2],     S[2 * kt][3],     Phi[kt][1], Plo[kt][1]);
            split2h(S[2 * kt + 1][0], S[2 * kt + 1][1], Phi[kt][2], Plo[kt][2]);
            split2h(S[2 * kt + 1][2], S[2 * kt + 1][3], Phi[kt][3], Plo[kt][3]);
        }

        // ---- O += (Phi + Plo) V ----
        const uint32_t Vb = KV(cur, 1);
#pragma unroll
        for (int ks = 0; ks < 4; ks++) {
            uint32_t vb[8][2];
#pragma unroll
            for (int p = 0; p < 4; p++) {
                const int g = lane >> 3;
                const int r = ks * 16 + (g & 1) * 8 + (lane & 7);
                const int cb = (p * 16 + (g >> 1) * 8) * 2;
                ldsm4t(vb[2 * p][0], vb[2 * p][1], vb[2 * p + 1][0], vb[2 * p + 1][1],
                       Vb + SWZ128(r * 128 + cb));
            }
#pragma unroll
            for (int nt = 0; nt < 8; nt++) mma16816h(O[nt], Phi[ks], vb[nt]);
#pragma unroll
            for (int nt = 0; nt < 8; nt++) mma16816h(O[nt], Plo[ks], vb[nt]);
        }
    }

    // ---- epilogue: y = O / l -> fp16, layout [bt][h*64+d] ----
    const float inv0 = 1.0f / lrow0, inv1 = 1.0f / lrow1;
    const int b = bh >> 4, h = bh & 15;
    const size_t row0 = ((size_t)(b * T_ + warp_top + gid)) * C_ + h * HD_;
    const size_t row1 = row0 + (size_t)8 * C_;
#pragma unroll
    for (int nt = 0; nt < 8; nt++) {
        const int col = nt * 8 + 2 * tig;
        *reinterpret_cast<uint32_t*>(yf + row0 + col) = pack_h2(O[nt][0] * inv0, O[nt][1] * inv0);
        *reinterpret_cast<uint32_t*>(yf + row1 + col) = pack_h2(O[nt][2] * inv1, O[nt][3] * inv1);
    }
}

// ---------------------------------------------------------------------------
extern "C" void kernel_launch(void* const* d_in, const int* in_sizes, int n_in,
                              void* d_out, int out_size)
{
    const float* x      = (const float*)d_in[0];
    const float* fcos   = (const float*)d_in[1];
    const float* fsin   = (const float*)d_in[2];
    const float* w_attn = (const float*)d_in[3];
    const float* w_proj = (const float*)d_in[4];
    const float* qw     = (const float*)d_in[5];
    const float* kw     = (const float*)d_in[6];
    float* out = (float*)d_out;

    float* qkv;
    __half *xf, *wah, *wal, *wph, *wpl, *yf, *qh, *ql, *kh, *vh;
    cudaGetSymbolAddress((void**)&qkv, g_qkv);
    cudaGetSymbolAddress((void**)&xf,  g_xf);
    cudaGetSymbolAddress((void**)&wah, g_wah);
    cudaGetSymbolAddress((void**)&wal, g_wal);
    cudaGetSymbolAddress((void**)&wph, g_wph);
    cudaGetSymbolAddress((void**)&wpl, g_wpl);
    cudaGetSymbolAddress((void**)&yf,  g_yf);
    cudaGetSymbolAddress((void**)&qh,  g_qh);
    cudaGetSymbolAddress((void**)&ql,  g_ql);
    cudaGetSymbolAddress((void**)&kh,  g_kh);
    cudaGetSymbolAddress((void**)&vh,  g_vh);

    cudaFuncSetAttribute(gemm_f16_2t, cudaFuncAttributeMaxDynamicSharedMemorySize, GSMEM);
    cudaFuncSetAttribute(flash_mma, cudaFuncAttributeMaxDynamicSharedMemorySize, FSMEM);

    // 1) convert/split inputs
    {
        int n4 = (M_ * C_) / 4;
        conv_f16<<<(n4 + 255) / 256, 256>>>(x, xf, n4);
        n4 = (C3_ * C_) / 4;
        split_f16<<<(n4 + 255) / 256, 256>>>(w_attn, wah, wal, n4);
        n4 = (C_ * C_) / 4;
        split_f16<<<(n4 + 255) / 256, 256>>>(w_proj, wph, wpl, n4);
    }

    // 2) qkv = x @ w_attn^T  (fp16 2-term)
    {
        dim3 g(C3_ / 128, M_ / 128);
        gemm_f16_2t<<<g, 256, GSMEM>>>(xf, wah, wal, qkv, C3_, C_);
    }

    // 3) RMSNorm + RoPE + fp16 conversion, head-major
    norm_rope_split<<<(B_ * T_ * H_) / 8, 256>>>(qkv, fcos, fsin, qw, kw, qh, ql, kh, vh);

    // 4) causal flash attention -> yf (fp16)
    {
        dim3 g(T_ / 128, B_ * H_);
        flash_mma<<<g, 256, FSMEM>>>(qh, ql, kh, vh, yf);
    }

    // 5) out = y @ w_proj^T  (fp16 2-term)
    {
        dim3 g(C_ / 128, M_ / 128);
        gemm_f16_2t<<<g, 256, GSMEM>>>(yf, wph, wpl, out, C_, C_);
    }
}

// round 9
// speedup vs baseline: 1.7769x; 1.2112x over previous
#include <cuda_runtime.h>
#include <cuda_fp16.h>
#include <cstdint>
#include <cstddef>

static constexpr int B_  = 2;
static constexpr int T_  = 2048;
static constexpr int C_  = 1024;
static constexpr int H_  = 16;
static constexpr int HD_ = 64;
static constexpr int C3_ = 3 * C_;
static constexpr int M_  = B_ * T_;      // 4096

// ---------------------------------------------------------------------------
// Scratch (__device__ globals; no allocation allowed)
// ---------------------------------------------------------------------------
__device__ float g_qkv[(size_t)M_ * C3_];            // fp32 qkv (50 MB)
__device__ __half g_xf[(size_t)M_ * C_];             // x fp16 1-term
__device__ __half g_waf[(size_t)C3_ * C_];           // w_attn fp16 1-term
__device__ __half g_wph[(size_t)C_ * C_];            // w_proj hi
__device__ __half g_wpl[(size_t)C_ * C_];            // w_proj lo
__device__ __half g_yf[(size_t)M_ * C_];             // attention out fp16
// head-major [B][H][T][64]
__device__ __half g_qh[(size_t)M_ * C_];
__device__ __half g_ql[(size_t)M_ * C_];
__device__ __half g_kh[(size_t)M_ * C_];             // K 1-term
__device__ __half g_vh[(size_t)M_ * C_];             // V 1-term

// ---------------------------------------------------------------------------
// Helpers
// ---------------------------------------------------------------------------
__device__ __forceinline__ uint32_t smem_u32(const void* p) {
    uint32_t a;
    asm("{ .reg .u64 t; cvta.to.shared.u64 t, %1; cvt.u32.u64 %0, t; }" : "=r"(a) : "l"(p));
    return a;
}
#define SWZ128(o) ((o) ^ (((o) >> 3) & 0x70))

__device__ __forceinline__ void cp_async16(uint32_t dst, const void* src) {
    asm volatile("cp.async.cg.shared.global [%0], [%1], 16;" :: "r"(dst), "l"(src));
}
__device__ __forceinline__ void ldsm4(uint32_t& r0, uint32_t& r1, uint32_t& r2, uint32_t& r3,
                                      uint32_t addr) {
    asm volatile("ldmatrix.sync.aligned.m8n8.x4.shared.b16 {%0,%1,%2,%3}, [%4];"
                 : "=r"(r0), "=r"(r1), "=r"(r2), "=r"(r3) : "r"(addr));
}
__device__ __forceinline__ void ldsm4t(uint32_t& r0, uint32_t& r1, uint32_t& r2, uint32_t& r3,
                                       uint32_t addr) {
    asm volatile("ldmatrix.sync.aligned.m8n8.x4.trans.shared.b16 {%0,%1,%2,%3}, [%4];"
                 : "=r"(r0), "=r"(r1), "=r"(r2), "=r"(r3) : "r"(addr));
}
__device__ __forceinline__ void mma16816h(float* c, const uint32_t* a, const uint32_t* b) {
    asm volatile(
        "mma.sync.aligned.m16n8k16.row.col.f32.f16.f16.f32 "
        "{%0,%1,%2,%3}, {%4,%5,%6,%7}, {%8,%9}, {%0,%1,%2,%3};"
        : "+f"(c[0]), "+f"(c[1]), "+f"(c[2]), "+f"(c[3])
        : "r"(a[0]), "r"(a[1]), "r"(a[2]), "r"(a[3]), "r"(b[0]), "r"(b[1]));
}
__device__ __forceinline__ uint32_t pack_h2(float a, float b) {
    __half2 h(__float2half_rn(a), __float2half_rn(b));
    return *reinterpret_cast<uint32_t*>(&h);
}
__device__ __forceinline__ void split2h(float a, float b, uint32_t& hi, uint32_t& lo) {
    __half ha = __float2half_rn(a), hb = __float2half_rn(b);
    __half2 H(ha, hb);
    __half2 L(__float2half_rn(a - __half2float(ha)), __float2half_rn(b - __half2float(hb)));
    hi = *reinterpret_cast<uint32_t*>(&H);
    lo = *reinterpret_cast<uint32_t*>(&L);
}

// ---------------------------------------------------------------------------
// fp32 -> fp16 convert (1-term)
// ---------------------------------------------------------------------------
__global__ __launch_bounds__(256)
void conv_f16(const float* __restrict__ in, __half* __restrict__ out, int n4)
{
    int i = blockIdx.x * blockDim.x + threadIdx.x;
    if (i >= n4) return;
    float4 v = reinterpret_cast<const float4*>(in)[i];
    reinterpret_cast<uint32_t*>(out)[2 * i]     = pack_h2(v.x, v.y);
    reinterpret_cast<uint32_t*>(out)[2 * i + 1] = pack_h2(v.z, v.w);
}

// fp32 -> (hi, lo) fp16 split (2-term)
__global__ __launch_bounds__(256)
void split_f16(const float* __restrict__ in, __half* __restrict__ hi,
               __half* __restrict__ lo, int n4)
{
    int i = blockIdx.x * blockDim.x + threadIdx.x;
    if (i >= n4) return;
    float4 v = reinterpret_cast<const float4*>(in)[i];
    uint32_t h0, l0, h1, l1;
    split2h(v.x, v.y, h0, l0);
    split2h(v.z, v.w, h1, l1);
    reinterpret_cast<uint32_t*>(hi)[2 * i]     = h0;
    reinterpret_cast<uint32_t*>(hi)[2 * i + 1] = h1;
    reinterpret_cast<uint32_t*>(lo)[2 * i]     = l0;
    reinterpret_cast<uint32_t*>(lo)[2 * i + 1] = l1;
}

// ---------------------------------------------------------------------------
// Plain fp16 GEMM (NT): C = A @ B^T. 128x128 tile, BK=64, 8 warps,
// double-buffered 32KB stages. Used for qkv (error budget spent here).
// ---------------------------------------------------------------------------
static constexpr int GSMEM1 = 65536;   // 2 x 32768

__global__ __launch_bounds__(256, 2)
void gemm_f16_1t(const __half* __restrict__ A, const __half* __restrict__ Bw,
                 float* __restrict__ Cout, int N, int K)
{
    extern __shared__ char smem[];
    const uint32_t smem_base = smem_u32(smem);
    const int tid  = threadIdx.x;
    const int lane = tid & 31;
    const int wid  = tid >> 5;
    const int wr = (wid >> 2) * 64;
    const int wc = (wid & 3) * 32;
    const int m0 = blockIdx.y * 128;
    const int n0 = blockIdx.x * 128;

    float acc[4][4][4];
#pragma unroll
    for (int mi = 0; mi < 4; mi++)
#pragma unroll
        for (int ni = 0; ni < 4; ni++)
#pragma unroll
            for (int e = 0; e < 4; e++) acc[mi][ni][e] = 0.f;

    const int NC = K >> 6;

    auto load_chunk = [&](int cg) {
        const uint32_t base = smem_base + (cg & 1) * 32768;
        const int k0 = cg * 64;
#pragma unroll
        for (int i = 0; i < 4; i++) {
            const int u = tid + 256 * i;
            const int row = u >> 3, ch = u & 7;
            const uint32_t so = SWZ128(row * 128 + ch * 16);
            cp_async16(base + so,         A  + (size_t)(m0 + row) * K + k0 + ch * 8);
            cp_async16(base + 16384 + so, Bw + (size_t)(n0 + row) * K + k0 + ch * 8);
        }
        asm volatile("cp.async.commit_group;");
    };

    load_chunk(0);
    for (int cg = 0; cg < NC; cg++) {
        if (cg + 1 < NC) {
            load_chunk(cg + 1);
            asm volatile("cp.async.wait_group 1;");
        } else {
            asm volatile("cp.async.wait_group 0;");
        }
        __syncthreads();

        const uint32_t As = smem_base + (cg & 1) * 32768;
        const uint32_t Bs = As + 16384;
#pragma unroll
        for (int ks = 0; ks < 4; ks++) {
            const int cbb = ks * 32;
            uint32_t b[4][2];
#pragma unroll
            for (int p = 0; p < 2; p++) {
                const int g = lane >> 3;
                const int r = wc + p * 16 + (g >> 1) * 8 + (lane & 7);
                const int cb = cbb + (g & 1) * 16;
                ldsm4(b[2 * p][0], b[2 * p][1], b[2 * p + 1][0], b[2 * p + 1][1],
                      Bs + SWZ128(r * 128 + cb));
            }
#pragma unroll
            for (int mi = 0; mi < 4; mi++) {
                const int r = wr + mi * 16 + (lane & 15);
                const int cb = cbb + (lane >> 4) * 16;
                uint32_t a[4];
                ldsm4(a[0], a[1], a[2], a[3], As + SWZ128(r * 128 + cb));
#pragma unroll
                for (int ni = 0; ni < 4; ni++)
                    mma16816h(acc[mi][ni], a, b[ni]);
            }
        }
        __syncthreads();
    }

#pragma unroll
    for (int mi = 0; mi < 4; mi++) {
        const int m = m0 + wr + mi * 16 + (lane >> 2);
#pragma unroll
        for (int ni = 0; ni < 4; ni++) {
            const int n = n0 + wc + ni * 8 + (lane & 3) * 2;
            *reinterpret_cast<float2*>(Cout + (size_t)m * N + n) =
                make_float2(acc[mi][ni][0], acc[mi][ni][1]);
            *reinterpret_cast<float2*>(Cout + (size_t)(m + 8) * N + n) =
                make_float2(acc[mi][ni][2], acc[mi][ni][3]);
        }
    }
}

// ---------------------------------------------------------------------------
// fp16 2-term GEMM (NT): C = A @ (Bhi+Blo)^T. Used for the output projection.
// ---------------------------------------------------------------------------
static constexpr int GSMEM2 = 98304;   // 2 x 49152

__global__ __launch_bounds__(256, 2)
void gemm_f16_2t(const __half* __restrict__ A,
                 const __half* __restrict__ Bhi, const __half* __restrict__ Blo,
                 float* __restrict__ Cout, int N, int K)
{
    extern __shared__ char smem[];
    const uint32_t smem_base = smem_u32(smem);
    const int tid  = threadIdx.x;
    const int lane = tid & 31;
    const int wid  = tid >> 5;
    const int wr = (wid >> 2) * 64;
    const int wc = (wid & 3) * 32;
    const int m0 = blockIdx.y * 128;
    const int n0 = blockIdx.x * 128;

    float acc[4][4][4];
#pragma unroll
    for (int mi = 0; mi < 4; mi++)
#pragma unroll
        for (int ni = 0; ni < 4; ni++)
#pragma unroll
            for (int e = 0; e < 4; e++) acc[mi][ni][e] = 0.f;

    const int NC = K >> 6;

    auto load_chunk = [&](int cg) {
        const uint32_t base = smem_base + (cg & 1) * 49152;
        const int k0 = cg * 64;
#pragma unroll
        for (int i = 0; i < 4; i++) {
            const int u = tid + 256 * i;
            const int row = u >> 3, ch = u & 7;
            const uint32_t so = SWZ128(row * 128 + ch * 16);
            cp_async16(base + so,         A   + (size_t)(m0 + row) * K + k0 + ch * 8);
            cp_async16(base + 16384 + so, Bhi + (size_t)(n0 + row) * K + k0 + ch * 8);
            cp_async16(base + 32768 + so, Blo + (size_t)(n0 + row) * K + k0 + ch * 8);
        }
        asm volatile("cp.async.commit_group;");
    };

    load_chunk(0);
    for (int cg = 0; cg < NC; cg++) {
        if (cg + 1 < NC) {
            load_chunk(cg + 1);
            asm volatile("cp.async.wait_group 1;");
        } else {
            asm volatile("cp.async.wait_group 0;");
        }
        __syncthreads();

        const uint32_t As = smem_base + (cg & 1) * 49152;
        const uint32_t Bh = As + 16384;
        const uint32_t Bl = As + 32768;
#pragma unroll
        for (int ks = 0; ks < 4; ks++) {
            const int cbb = ks * 32;
            uint32_t bh[4][2], bl[4][2];
#pragma unroll
            for (int p = 0; p < 2; p++) {
                const int g = lane >> 3;
                const int r = wc + p * 16 + (g >> 1) * 8 + (lane & 7);
                const int cb = cbb + (g & 1) * 16;
                ldsm4(bh[2 * p][0], bh[2 * p][1], bh[2 * p + 1][0], bh[2 * p + 1][1],
                      Bh + SWZ128(r * 128 + cb));
                ldsm4(bl[2 * p][0], bl[2 * p][1], bl[2 * p + 1][0], bl[2 * p + 1][1],
                      Bl + SWZ128(r * 128 + cb));
            }
#pragma unroll
            for (int mi = 0; mi < 4; mi++) {
                const int r = wr + mi * 16 + (lane & 15);
                const int cb = cbb + (lane >> 4) * 16;
                uint32_t a[4];
                ldsm4(a[0], a[1], a[2], a[3], As + SWZ128(r * 128 + cb));
#pragma unroll
                for (int ni = 0; ni < 4; ni++) {
                    mma16816h(acc[mi][ni], a, bh[ni]);
                    mma16816h(acc[mi][ni], a, bl[ni]);
                }
            }
        }
        __syncthreads();
    }

#pragma unroll
    for (int mi = 0; mi < 4; mi++) {
        const int m = m0 + wr + mi * 16 + (lane >> 2);
#pragma unroll
        for (int ni = 0; ni < 4; ni++) {
            const int n = n0 + wc + ni * 8 + (lane & 3) * 2;
            *reinterpret_cast<float2*>(Cout + (size_t)m * N + n) =
                make_float2(acc[mi][ni][0], acc[mi][ni][1]);
            *reinterpret_cast<float2*>(Cout + (size_t)(m + 8) * N + n) =
                make_float2(acc[mi][ni][2], acc[mi][ni][3]);
        }
    }
}

// ---------------------------------------------------------------------------
// Fused per-head RMSNorm + RoPE + fp16 conversion, head-major [B][H][T][64].
// Q -> 2-term (qh, ql); K, V -> 1-term. One warp per (bt, h).
// ---------------------------------------------------------------------------
__global__ __launch_bounds__(256)
void norm_rope_split(const float* __restrict__ qkv, const float* __restrict__ cosT,
                     const float* __restrict__ sinT, const float* __restrict__ qw,
                     const float* __restrict__ kw,
                     __half* __restrict__ qh, __half* __restrict__ ql,
                     __half* __restrict__ kh, __half* __restrict__ vh)
{
    const int gw = (blockIdx.x * blockDim.x + threadIdx.x) >> 5;
    const int lane = threadIdx.x & 31;
    const int h = gw & (H_ - 1);
    const int bt = gw >> 4;
    const int t = bt & (T_ - 1);
    const int b = bt >> 11;

    const float* qp = qkv + (size_t)bt * C3_ + h * HD_;
    const float* kp = qp + C_;
    const float* vp = qp + 2 * C_;
    const size_t ho = (((size_t)(b * H_ + h) * T_) + t) * HD_ + 2 * lane;
    const float c = cosT[t * (HD_ / 2) + lane];
    const float s = sinT[t * (HD_ / 2) + lane];

    {
        float2 v = *reinterpret_cast<const float2*>(qp + 2 * lane);
        float ss = v.x * v.x + v.y * v.y;
#pragma unroll
        for (int off = 16; off > 0; off >>= 1) ss += __shfl_xor_sync(0xffffffffu, ss, off);
        float rms = rsqrtf(ss * (1.f / HD_) + 1e-6f);
        float x0 = v.x * rms * qw[2 * lane];
        float x1 = v.y * rms * qw[2 * lane + 1];
        uint32_t hi, lo;
        split2h(x0 * c - x1 * s, x0 * s + x1 * c, hi, lo);
        *reinterpret_cast<uint32_t*>(qh + ho) = hi;
        *reinterpret_cast<uint32_t*>(ql + ho) = lo;
    }
    {
        float2 v = *reinterpret_cast<const float2*>(kp + 2 * lane);
        float ss = v.x * v.x + v.y * v.y;
#pragma unroll
        for (int off = 16; off > 0; off >>= 1) ss += __shfl_xor_sync(0xffffffffu, ss, off);
        float rms = rsqrtf(ss * (1.f / HD_) + 1e-6f);
        float x0 = v.x * rms * kw[2 * lane];
        float x1 = v.y * rms * kw[2 * lane + 1];
        *reinterpret_cast<uint32_t*>(kh + ho) = pack_h2(x0 * c - x1 * s, x0 * s + x1 * c);
    }
    {
        float2 v = *reinterpret_cast<const float2*>(vp + 2 * lane);
        *reinterpret_cast<uint32_t*>(vh + ho) = pack_h2(v.x, v.y);
    }
}

// ---------------------------------------------------------------------------
// fp16 flash attention, causal. Q 2-term, K 1-term, P 2-term, V 1-term.
// (unchanged from R8)
// ---------------------------------------------------------------------------
static constexpr int FSMEM = 65536;

__global__ __launch_bounds__(256, 2)
void flash_mma(const __half* __restrict__ qh, const __half* __restrict__ ql,
               const __half* __restrict__ kh, const __half* __restrict__ vh,
               __half* __restrict__ yf)
{
    extern __shared__ char smem[];
    const uint32_t sb = smem_u32(smem);
    const int tid = threadIdx.x, lane = tid & 31, wid = tid >> 5;
    const int gid = lane >> 2, tig = lane & 3;
    const int bh = blockIdx.y;
    const int q0 = (gridDim.x - 1 - blockIdx.x) * 128;
    const size_t head = (size_t)bh * T_ * HD_;

    const uint32_t QHI = sb, QLO = sb + 16384;
    auto KV = [&](int buf, int t) -> uint32_t { return sb + 32768 + buf * 16384 + t * 8192; };

    {
#pragma unroll
        for (int i = 0; i < 4; i++) {
            int u = tid + 256 * i, r = u >> 3, ch = u & 7;
            uint32_t so = SWZ128(r * 128 + ch * 16);
            size_t go = head + (size_t)(q0 + r) * HD_ + ch * 8;
            cp_async16(QHI + so, qh + go);
            cp_async16(QLO + so, ql + go);
        }
#pragma unroll
        for (int i = 0; i < 2; i++) {
            int u = tid + 256 * i, r = u >> 3, ch = u & 7;
            uint32_t so = SWZ128(r * 128 + ch * 16);
            size_t go = head + (size_t)r * HD_ + ch * 8;
            cp_async16(KV(0, 0) + so, kh + go);
            cp_async16(KV(0, 1) + so, vh + go);
        }
        asm volatile("cp.async.commit_group;");
    }

    float O[8][4];
#pragma unroll
    for (int nt = 0; nt < 8; nt++)
#pragma unroll
        for (int e = 0; e < 4; e++) O[nt][e] = 0.f;
    float mrow0 = -1e30f, mrow1 = -1e30f, lrow0 = 0.f, lrow1 = 0.f;

    const int warp_top = q0 + wid * 16;
    const int niter = (q0 + 128) / 64;

    for (int it = 0; it < niter; it++) {
        asm volatile("cp.async.wait_group 0;");
        __syncthreads();
        const int cur = it & 1;
        if (it + 1 < niter) {
            const int nxt = 1 - cur;
            const size_t koff = head + (size_t)(it + 1) * 64 * HD_;
#pragma unroll
            for (int i = 0; i < 2; i++) {
                int u = tid + 256 * i, r = u >> 3, ch = u & 7;
                uint32_t so = SWZ128(r * 128 + ch * 16);
                size_t go = koff + (size_t)r * HD_ + ch * 8;
                cp_async16(KV(nxt, 0) + so, kh + go);
                cp_async16(KV(nxt, 1) + so, vh + go);
            }
            asm volatile("cp.async.commit_group;");
        }

        const int j0 = it * 64;
        if (j0 > warp_top + 15) continue;

        float S[8][4];
#pragma unroll
        for (int nt = 0; nt < 8; nt++)
#pragma unroll
            for (int e = 0; e < 4; e++) S[nt][e] = 0.f;

        const uint32_t Kb = KV(cur, 0);
#pragma unroll
        for (int ks = 0; ks < 4; ks++) {
            const int k0 = ks * 16;
            uint32_t b[8][2];
#pragma unroll
            for (int p = 0; p < 4; p++) {
                const int g = lane >> 3;
                const int r = p * 16 + (g >> 1) * 8 + (lane & 7);
                ldsm4(b[2 * p][0], b[2 * p][1], b[2 * p + 1][0], b[2 * p + 1][1],
                      Kb + SWZ128(r * 128 + (k0 + (g & 1) * 8) * 2));
            }
            const uint32_t qoff = SWZ128((wid * 16 + (lane & 15)) * 128 +
                                         (k0 + (lane >> 4) * 8) * 2);
            uint32_t aH[4], aL[4];
            ldsm4(aH[0], aH[1], aH[2], aH[3], QHI + qoff);
            ldsm4(aL[0], aL[1], aL[2], aL[3], QLO + qoff);
#pragma unroll
            for (int nt = 0; nt < 8; nt++) mma16816h(S[nt], aH, b[nt]);
#pragma unroll
            for (int nt = 0; nt < 8; nt++) mma16816h(S[nt], aL, b[nt]);
        }

        const int qi0 = warp_top + gid;
        if (j0 + 63 > warp_top) {
#pragma unroll
            for (int nt = 0; nt < 8; nt++)
#pragma unroll
                for (int e = 0; e < 4; e++) {
                    const int kj = j0 + nt * 8 + 2 * tig + (e & 1);
                    const int qi = qi0 + ((e >= 2) ? 8 : 0);
                    S[nt][e] = (kj <= qi) ? S[nt][e] * 0.125f : -1e30f;
                }
        } else {
#pragma unroll
            for (int nt = 0; nt < 8; nt++)
#pragma unroll
                for (int e = 0; e < 4; e++) S[nt][e] *= 0.125f;
        }

        float mx0 = -1e30f, mx1 = -1e30f;
#pragma unroll
        for (int nt = 0; nt < 8; nt++) {
            mx0 = fmaxf(mx0, fmaxf(S[nt][0], S[nt][1]));
            mx1 = fmaxf(mx1, fmaxf(S[nt][2], S[nt][3]));
        }
        mx0 = fmaxf(mx0, __shfl_xor_sync(0xffffffffu, mx0, 1));
        mx0 = fmaxf(mx0, __shfl_xor_sync(0xffffffffu, mx0, 2));
        mx1 = fmaxf(mx1, __shfl_xor_sync(0xffffffffu, mx1, 1));
        mx1 = fmaxf(mx1, __shfl_xor_sync(0xffffffffu, mx1, 2));
        const float mn0 = fmaxf(mrow0, mx0), mn1 = fmaxf(mrow1, mx1);
        const float al0 = __expf(mrow0 - mn0), al1 = __expf(mrow1 - mn1);
        float ps0 = 0.f, ps1 = 0.f;
#pragma unroll
        for (int nt = 0; nt < 8; nt++) {
            S[nt][0] = __expf(S[nt][0] - mn0);
            S[nt][1] = __expf(S[nt][1] - mn0);
            S[nt][2] = __expf(S[nt][2] - mn1);
            S[nt][3] = __expf(S[nt][3] - mn1);
            ps0 += S[nt][0] + S[nt][1];
            ps1 += S[nt][2] + S[nt][3];
        }
        ps0 += __shfl_xor_sync(0xffffffffu, ps0, 1);
        ps0 += __shfl_xor_sync(0xffffffffu, ps0, 2);
        ps1 += __shfl_xor_sync(0xffffffffu, ps1, 1);
        ps1 += __shfl_xor_sync(0xffffffffu, ps1, 2);
        lrow0 = lrow0 * al0 + ps0;
        lrow1 = lrow1 * al1 + ps1;
        mrow0 = mn0;
        mrow1 = mn1;
#pragma unroll
        for (int nt = 0; nt < 8; nt++) {
            O[nt][0] *= al0; O[nt][1] *= al0;
            O[nt][2] *= al1; O[nt][3] *= al1;
        }

        uint32_t Phi[4][4], Plo[4][4];
#pragma unroll
        for (int kt = 0; kt < 4; kt++) {
            split2h(S[2 * kt][0],     S[2 * kt][1],     Phi[kt][0], Plo[kt][0]);
            split2h(S[2 * kt][2],     S[2 * kt][3],     Phi[kt][1], Plo[kt][1]);
            split2h(S[2 * kt + 1][0], S[2 * kt + 1][1], Phi[kt][2], Plo[kt][2]);
            split2h(S[2 * kt + 1][2], S[2 * kt + 1][3], Phi[kt][3], Plo[kt][3]);
        }

        const uint32_t Vb = KV(cur, 1);
#pragma unroll
        for (int ks = 0; ks < 4; ks++) {
            uint32_t vb[8][2];
#pragma unroll
            for (int p = 0; p < 4; p++) {
                const int g = lane >> 3;
                const int r = ks * 16 + (g & 1) * 8 + (lane & 7);
                const int cb = (p * 16 + (g >> 1) * 8) * 2;
                ldsm4t(vb[2 * p][0], vb[2 * p][1], vb[2 * p + 1][0], vb[2 * p + 1][1],
                       Vb + SWZ128(r * 128 + cb));
            }
#pragma unroll
            for (int nt = 0; nt < 8; nt++) mma16816h(O[nt], Phi[ks], vb[nt]);
#pragma unroll
            for (int nt = 0; nt < 8; nt++) mma16816h(O[nt], Plo[ks], vb[nt]);
        }
    }

    const float inv0 = 1.0f / lrow0, inv1 = 1.0f / lrow1;
    const int b = bh >> 4, h = bh & 15;
    const size_t row0 = ((size_t)(b * T_ + warp_top + gid)) * C_ + h * HD_;
    const size_t row1 = row0 + (size_t)8 * C_;
#pragma unroll
    for (int nt = 0; nt < 8; nt++) {
        const int col = nt * 8 + 2 * tig;
        *reinterpret_cast<uint32_t*>(yf + row0 + col) = pack_h2(O[nt][0] * inv0, O[nt][1] * inv0);
        *reinterpret_cast<uint32_t*>(yf + row1 + col) = pack_h2(O[nt][2] * inv1, O[nt][3] * inv1);
    }
}

// ---------------------------------------------------------------------------
extern "C" void kernel_launch(void* const* d_in, const int* in_sizes, int n_in,
                              void* d_out, int out_size)
{
    const float* x      = (const float*)d_in[0];
    const float* fcos   = (const float*)d_in[1];
    const float* fsin   = (const float*)d_in[2];
    const float* w_attn = (const float*)d_in[3];
    const float* w_proj = (const float*)d_in[4];
    const float* qw     = (const float*)d_in[5];
    const float* kw     = (const float*)d_in[6];
    float* out = (float*)d_out;

    float* qkv;
    __half *xf, *waf, *wph, *wpl, *yf, *qh, *ql, *kh, *vh;
    cudaGetSymbolAddress((void**)&qkv, g_qkv);
    cudaGetSymbolAddress((void**)&xf,  g_xf);
    cudaGetSymbolAddress((void**)&waf, g_waf);
    cudaGetSymbolAddress((void**)&wph, g_wph);
    cudaGetSymbolAddress((void**)&wpl, g_wpl);
    cudaGetSymbolAddress((void**)&yf,  g_yf);
    cudaGetSymbolAddress((void**)&qh,  g_qh);
    cudaGetSymbolAddress((void**)&ql,  g_ql);
    cudaGetSymbolAddress((void**)&kh,  g_kh);
    cudaGetSymbolAddress((void**)&vh,  g_vh);

    cudaFuncSetAttribute(gemm_f16_1t, cudaFuncAttributeMaxDynamicSharedMemorySize, GSMEM1);
    cudaFuncSetAttribute(gemm_f16_2t, cudaFuncAttributeMaxDynamicSharedMemorySize, GSMEM2);
    cudaFuncSetAttribute(flash_mma, cudaFuncAttributeMaxDynamicSharedMemorySize, FSMEM);

    // 1) convert/split inputs
    {
        int n4 = (M_ * C_) / 4;
        conv_f16<<<(n4 + 255) / 256, 256>>>(x, xf, n4);
        n4 = (C3_ * C_) / 4;
        conv_f16<<<(n4 + 255) / 256, 256>>>(w_attn, waf, n4);
        n4 = (C_ * C_) / 4;
        split_f16<<<(n4 + 255) / 256, 256>>>(w_proj, wph, wpl, n4);
    }

    // 2) qkv = x @ w_attn^T  (plain fp16 — error budget spent here)
    {
        dim3 g(C3_ / 128, M_ / 128);
        gemm_f16_1t<<<g, 256, GSMEM1>>>(xf, waf, qkv, C3_, C_);
    }

    // 3) RMSNorm + RoPE + fp16 conversion, head-major
    norm_rope_split<<<(B_ * T_ * H_) / 8, 256>>>(qkv, fcos, fsin, qw, kw, qh, ql, kh, vh);

    // 4) causal flash attention -> yf (fp16)
    {
        dim3 g(T_ / 128, B_ * H_);
        flash_mma<<<g, 256, FSMEM>>>(qh, ql, kh, vh, yf);
    }

    // 5) out = y @ w_proj^T  (fp16 2-term)
    {
        dim3 g(C_ / 128, M_ / 128);
        gemm_f16_2t<<<g, 256, GSMEM2>>>(yf, wph, wpl, out, C_, C_);
    }
}

// round 10
// speedup vs baseline: 2.1420x; 1.2054x over previous
#include <cuda_runtime.h>
#include <cuda_fp16.h>
#include <cstdint>
#include <cstddef>

static constexpr int B_  = 2;
static constexpr int T_  = 2048;
static constexpr int C_  = 1024;
static constexpr int H_  = 16;
static constexpr int HD_ = 64;
static constexpr int C3_ = 3 * C_;
static constexpr int M_  = B_ * T_;      // 4096

// ---------------------------------------------------------------------------
// Scratch (__device__ globals; no allocation allowed)
// ---------------------------------------------------------------------------
__device__ float g_qkv[(size_t)M_ * C3_];            // fp32 qkv (50 MB)
__device__ __half g_xf[(size_t)M_ * C_];             // x fp16
__device__ __half g_waf[(size_t)C3_ * C_];           // w_attn fp16
__device__ __half g_wph[(size_t)C_ * C_];            // w_proj hi
__device__ __half g_wpl[(size_t)C_ * C_];            // w_proj lo
__device__ __half g_yf[(size_t)M_ * C_];             // attention out fp16
// head-major [B][H][T][64], all 1-term fp16
__device__ __half g_qh[(size_t)M_ * C_];
__device__ __half g_kh[(size_t)M_ * C_];
__device__ __half g_vh[(size_t)M_ * C_];

// ---------------------------------------------------------------------------
// Helpers
// ---------------------------------------------------------------------------
__device__ __forceinline__ uint32_t smem_u32(const void* p) {
    uint32_t a;
    asm("{ .reg .u64 t; cvta.to.shared.u64 t, %1; cvt.u32.u64 %0, t; }" : "=r"(a) : "l"(p));
    return a;
}
#define SWZ128(o) ((o) ^ (((o) >> 3) & 0x70))

__device__ __forceinline__ void cp_async16(uint32_t dst, const void* src) {
    asm volatile("cp.async.cg.shared.global [%0], [%1], 16;" :: "r"(dst), "l"(src));
}
__device__ __forceinline__ void ldsm4(uint32_t& r0, uint32_t& r1, uint32_t& r2, uint32_t& r3,
                                      uint32_t addr) {
    asm volatile("ldmatrix.sync.aligned.m8n8.x4.shared.b16 {%0,%1,%2,%3}, [%4];"
                 : "=r"(r0), "=r"(r1), "=r"(r2), "=r"(r3) : "r"(addr));
}
__device__ __forceinline__ void ldsm4t(uint32_t& r0, uint32_t& r1, uint32_t& r2, uint32_t& r3,
                                       uint32_t addr) {
    asm volatile("ldmatrix.sync.aligned.m8n8.x4.trans.shared.b16 {%0,%1,%2,%3}, [%4];"
                 : "=r"(r0), "=r"(r1), "=r"(r2), "=r"(r3) : "r"(addr));
}
__device__ __forceinline__ void mma16816h(float* c, const uint32_t* a, const uint32_t* b) {
    asm volatile(
        "mma.sync.aligned.m16n8k16.row.col.f32.f16.f16.f32 "
        "{%0,%1,%2,%3}, {%4,%5,%6,%7}, {%8,%9}, {%0,%1,%2,%3};"
        : "+f"(c[0]), "+f"(c[1]), "+f"(c[2]), "+f"(c[3])
        : "r"(a[0]), "r"(a[1]), "r"(a[2]), "r"(a[3]), "r"(b[0]), "r"(b[1]));
}
__device__ __forceinline__ uint32_t pack_h2(float a, float b) {
    __half2 h(__float2half_rn(a), __float2half_rn(b));
    return *reinterpret_cast<uint32_t*>(&h);
}
__device__ __forceinline__ void split2h(float a, float b, uint32_t& hi, uint32_t& lo) {
    __half ha = __float2half_rn(a), hb = __float2half_rn(b);
    __half2 H(ha, hb);
    __half2 L(__float2half_rn(a - __half2float(ha)), __float2half_rn(b - __half2float(hb)));
    hi = *reinterpret_cast<uint32_t*>(&H);
    lo = *reinterpret_cast<uint32_t*>(&L);
}

// ---------------------------------------------------------------------------
// fp32 -> fp16 convert (1-term)
// ---------------------------------------------------------------------------
__global__ __launch_bounds__(256)
void conv_f16(const float* __restrict__ in, __half* __restrict__ out, int n4)
{
    int i = blockIdx.x * blockDim.x + threadIdx.x;
    if (i >= n4) return;
    float4 v = reinterpret_cast<const float4*>(in)[i];
    reinterpret_cast<uint32_t*>(out)[2 * i]     = pack_h2(v.x, v.y);
    reinterpret_cast<uint32_t*>(out)[2 * i + 1] = pack_h2(v.z, v.w);
}

// fp32 -> (hi, lo) fp16 split (2-term, for w_proj)
__global__ __launch_bounds__(256)
void split_f16(const float* __restrict__ in, __half* __restrict__ hi,
               __half* __restrict__ lo, int n4)
{
    int i = blockIdx.x * blockDim.x + threadIdx.x;
    if (i >= n4) return;
    float4 v = reinterpret_cast<const float4*>(in)[i];
    uint32_t h0, l0, h1, l1;
    split2h(v.x, v.y, h0, l0);
    split2h(v.z, v.w, h1, l1);
    reinterpret_cast<uint32_t*>(hi)[2 * i]     = h0;
    reinterpret_cast<uint32_t*>(hi)[2 * i + 1] = h1;
    reinterpret_cast<uint32_t*>(lo)[2 * i]     = l0;
    reinterpret_cast<uint32_t*>(lo)[2 * i + 1] = l1;
}

// ---------------------------------------------------------------------------
// Plain fp16 GEMM (NT): C = A @ B^T (qkv projection)
// ---------------------------------------------------------------------------
static constexpr int GSMEM1 = 65536;   // 2 x 32768

__global__ __launch_bounds__(256, 2)
void gemm_f16_1t(const __half* __restrict__ A, const __half* __restrict__ Bw,
                 float* __restrict__ Cout, int N, int K)
{
    extern __shared__ char smem[];
    const uint32_t smem_base = smem_u32(smem);
    const int tid  = threadIdx.x;
    const int lane = tid & 31;
    const int wid  = tid >> 5;
    const int wr = (wid >> 2) * 64;
    const int wc = (wid & 3) * 32;
    const int m0 = blockIdx.y * 128;
    const int n0 = blockIdx.x * 128;

    float acc[4][4][4];
#pragma unroll
    for (int mi = 0; mi < 4; mi++)
#pragma unroll
        for (int ni = 0; ni < 4; ni++)
#pragma unroll
            for (int e = 0; e < 4; e++) acc[mi][ni][e] = 0.f;

    const int NC = K >> 6;

    auto load_chunk = [&](int cg) {
        const uint32_t base = smem_base + (cg & 1) * 32768;
        const int k0 = cg * 64;
#pragma unroll
        for (int i = 0; i < 4; i++) {
            const int u = tid + 256 * i;
            const int row = u >> 3, ch = u & 7;
            const uint32_t so = SWZ128(row * 128 + ch * 16);
            cp_async16(base + so,         A  + (size_t)(m0 + row) * K + k0 + ch * 8);
            cp_async16(base + 16384 + so, Bw + (size_t)(n0 + row) * K + k0 + ch * 8);
        }
        asm volatile("cp.async.commit_group;");
    };

    load_chunk(0);
    for (int cg = 0; cg < NC; cg++) {
        if (cg + 1 < NC) {
            load_chunk(cg + 1);
            asm volatile("cp.async.wait_group 1;");
        } else {
            asm volatile("cp.async.wait_group 0;");
        }
        __syncthreads();

        const uint32_t As = smem_base + (cg & 1) * 32768;
        const uint32_t Bs = As + 16384;
#pragma unroll
        for (int ks = 0; ks < 4; ks++) {
            const int cbb = ks * 32;
            uint32_t b[4][2];
#pragma unroll
            for (int p = 0; p < 2; p++) {
                const int g = lane >> 3;
                const int r = wc + p * 16 + (g >> 1) * 8 + (lane & 7);
                const int cb = cbb + (g & 1) * 16;
                ldsm4(b[2 * p][0], b[2 * p][1], b[2 * p + 1][0], b[2 * p + 1][1],
                      Bs + SWZ128(r * 128 + cb));
            }
#pragma unroll
            for (int mi = 0; mi < 4; mi++) {
                const int r = wr + mi * 16 + (lane & 15);
                const int cb = cbb + (lane >> 4) * 16;
                uint32_t a[4];
                ldsm4(a[0], a[1], a[2], a[3], As + SWZ128(r * 128 + cb));
#pragma unroll
                for (int ni = 0; ni < 4; ni++)
                    mma16816h(acc[mi][ni], a, b[ni]);
            }
        }
        __syncthreads();
    }

#pragma unroll
    for (int mi = 0; mi < 4; mi++) {
        const int m = m0 + wr + mi * 16 + (lane >> 2);
#pragma unroll
        for (int ni = 0; ni < 4; ni++) {
            const int n = n0 + wc + ni * 8 + (lane & 3) * 2;
            *reinterpret_cast<float2*>(Cout + (size_t)m * N + n) =
                make_float2(acc[mi][ni][0], acc[mi][ni][1]);
            *reinterpret_cast<float2*>(Cout + (size_t)(m + 8) * N + n) =
                make_float2(acc[mi][ni][2], acc[mi][ni][3]);
        }
    }
}

// ---------------------------------------------------------------------------
// fp16 2-term GEMM (NT): C = A @ (Bhi+Blo)^T (output projection)
// ---------------------------------------------------------------------------
static constexpr int GSMEM2 = 98304;   // 2 x 49152

__global__ __launch_bounds__(256, 2)
void gemm_f16_2t(const __half* __restrict__ A,
                 const __half* __restrict__ Bhi, const __half* __restrict__ Blo,
                 float* __restrict__ Cout, int N, int K)
{
    extern __shared__ char smem[];
    const uint32_t smem_base = smem_u32(smem);
    const int tid  = threadIdx.x;
    const int lane = tid & 31;
    const int wid  = tid >> 5;
    const int wr = (wid >> 2) * 64;
    const int wc = (wid & 3) * 32;
    const int m0 = blockIdx.y * 128;
    const int n0 = blockIdx.x * 128;

    float acc[4][4][4];
#pragma unroll
    for (int mi = 0; mi < 4; mi++)
#pragma unroll
        for (int ni = 0; ni < 4; ni++)
#pragma unroll
            for (int e = 0; e < 4; e++) acc[mi][ni][e] = 0.f;

    const int NC = K >> 6;

    auto load_chunk = [&](int cg) {
        const uint32_t base = smem_base + (cg & 1) * 49152;
        const int k0 = cg * 64;
#pragma unroll
        for (int i = 0; i < 4; i++) {
            const int u = tid + 256 * i;
            const int row = u >> 3, ch = u & 7;
            const uint32_t so = SWZ128(row * 128 + ch * 16);
            cp_async16(base + so,         A   + (size_t)(m0 + row) * K + k0 + ch * 8);
            cp_async16(base + 16384 + so, Bhi + (size_t)(n0 + row) * K + k0 + ch * 8);
            cp_async16(base + 32768 + so, Blo + (size_t)(n0 + row) * K + k0 + ch * 8);
        }
        asm volatile("cp.async.commit_group;");
    };

    load_chunk(0);
    for (int cg = 0; cg < NC; cg++) {
        if (cg + 1 < NC) {
            load_chunk(cg + 1);
            asm volatile("cp.async.wait_group 1;");
        } else {
            asm volatile("cp.async.wait_group 0;");
        }
        __syncthreads();

        const uint32_t As = smem_base + (cg & 1) * 49152;
        const uint32_t Bh = As + 16384;
        const uint32_t Bl = As + 32768;
#pragma unroll
        for (int ks = 0; ks < 4; ks++) {
            const int cbb = ks * 32;
            uint32_t bh[4][2], bl[4][2];
#pragma unroll
            for (int p = 0; p < 2; p++) {
                const int g = lane >> 3;
                const int r = wc + p * 16 + (g >> 1) * 8 + (lane & 7);
                const int cb = cbb + (g & 1) * 16;
                ldsm4(bh[2 * p][0], bh[2 * p][1], bh[2 * p + 1][0], bh[2 * p + 1][1],
                      Bh + SWZ128(r * 128 + cb));
                ldsm4(bl[2 * p][0], bl[2 * p][1], bl[2 * p + 1][0], bl[2 * p + 1][1],
                      Bl + SWZ128(r * 128 + cb));
            }
#pragma unroll
            for (int mi = 0; mi < 4; mi++) {
                const int r = wr + mi * 16 + (lane & 15);
                const int cb = cbb + (lane >> 4) * 16;
                uint32_t a[4];
                ldsm4(a[0], a[1], a[2], a[3], As + SWZ128(r * 128 + cb));
#pragma unroll
                for (int ni = 0; ni < 4; ni++) {
                    mma16816h(acc[mi][ni], a, bh[ni]);
                    mma16816h(acc[mi][ni], a, bl[ni]);
                }
            }
        }
        __syncthreads();
    }

#pragma unroll
    for (int mi = 0; mi < 4; mi++) {
        const int m = m0 + wr + mi * 16 + (lane >> 2);
#pragma unroll
        for (int ni = 0; ni < 4; ni++) {
            const int n = n0 + wc + ni * 8 + (lane & 3) * 2;
            *reinterpret_cast<float2*>(Cout + (size_t)m * N + n) =
                make_float2(acc[mi][ni][0], acc[mi][ni][1]);
            *reinterpret_cast<float2*>(Cout + (size_t)(m + 8) * N + n) =
                make_float2(acc[mi][ni][2], acc[mi][ni][3]);
        }
    }
}

// ---------------------------------------------------------------------------
// Fused per-head RMSNorm + RoPE + fp16 conversion, head-major [B][H][T][64].
// Q, K, V all 1-term. One warp per (bt, h).
// ---------------------------------------------------------------------------
__global__ __launch_bounds__(256)
void norm_rope_split(const float* __restrict__ qkv, const float* __restrict__ cosT,
                     const float* __restrict__ sinT, const float* __restrict__ qw,
                     const float* __restrict__ kw,
                     __half* __restrict__ qh, __half* __restrict__ kh,
                     __half* __restrict__ vh)
{
    const int gw = (blockIdx.x * blockDim.x + threadIdx.x) >> 5;
    const int lane = threadIdx.x & 31;
    const int h = gw & (H_ - 1);
    const int bt = gw >> 4;
    const int t = bt & (T_ - 1);
    const int b = bt >> 11;

    const float* qp = qkv + (size_t)bt * C3_ + h * HD_;
    const float* kp = qp + C_;
    const float* vp = qp + 2 * C_;
    const size_t ho = (((size_t)(b * H_ + h) * T_) + t) * HD_ + 2 * lane;
    const float c = cosT[t * (HD_ / 2) + lane];
    const float s = sinT[t * (HD_ / 2) + lane];

    {
        float2 v = *reinterpret_cast<const float2*>(qp + 2 * lane);
        float ss = v.x * v.x + v.y * v.y;
#pragma unroll
        for (int off = 16; off > 0; off >>= 1) ss += __shfl_xor_sync(0xffffffffu, ss, off);
        float rms = rsqrtf(ss * (1.f / HD_) + 1e-6f);
        float x0 = v.x * rms * qw[2 * lane];
        float x1 = v.y * rms * qw[2 * lane + 1];
        *reinterpret_cast<uint32_t*>(qh + ho) = pack_h2(x0 * c - x1 * s, x0 * s + x1 * c);
    }
    {
        float2 v = *reinterpret_cast<const float2*>(kp + 2 * lane);
        float ss = v.x * v.x + v.y * v.y;
#pragma unroll
        for (int off = 16; off > 0; off >>= 1) ss += __shfl_xor_sync(0xffffffffu, ss, off);
        float rms = rsqrtf(ss * (1.f / HD_) + 1e-6f);
        float x0 = v.x * rms * kw[2 * lane];
        float x1 = v.y * rms * kw[2 * lane + 1];
        *reinterpret_cast<uint32_t*>(kh + ho) = pack_h2(x0 * c - x1 * s, x0 * s + x1 * c);
    }
    {
        float2 v = *reinterpret_cast<const float2*>(vp + 2 * lane);
        *reinterpret_cast<uint32_t*>(vh + ho) = pack_h2(v.x, v.y);
    }
}

// ---------------------------------------------------------------------------
// fp16 flash attention, causal. Q, K, P, V all 1-term fp16.
// BQ=128 (8 warps x 16 rows), BKV=64.
// smem: Q 16K + 2 x (K 8K + V 8K) = 48 KB.
// ---------------------------------------------------------------------------
static constexpr int FSMEM = 49152;

__global__ __launch_bounds__(256, 2)
void flash_mma(const __half* __restrict__ qh, const __half* __restrict__ kh,
               const __half* __restrict__ vh, __half* __restrict__ yf)
{
    extern __shared__ char smem[];
    const uint32_t sb = smem_u32(smem);
    const int tid = threadIdx.x, lane = tid & 31, wid = tid >> 5;
    const int gid = lane >> 2, tig = lane & 3;
    const int bh = blockIdx.y;
    const int q0 = (gridDim.x - 1 - blockIdx.x) * 128;   // heavy tiles first
    const size_t head = (size_t)bh * T_ * HD_;

    const uint32_t QS = sb;
    auto KV = [&](int buf, int t) -> uint32_t { return sb + 16384 + buf * 16384 + t * 8192; };

    {
#pragma unroll
        for (int i = 0; i < 4; i++) {
            int u = tid + 256 * i, r = u >> 3, ch = u & 7;
            uint32_t so = SWZ128(r * 128 + ch * 16);
            cp_async16(QS + so, qh + head + (size_t)(q0 + r) * HD_ + ch * 8);
        }
#pragma unroll
        for (int i = 0; i < 2; i++) {
            int u = tid + 256 * i, r = u >> 3, ch = u & 7;
            uint32_t so = SWZ128(r * 128 + ch * 16);
            size_t go = head + (size_t)r * HD_ + ch * 8;
            cp_async16(KV(0, 0) + so, kh + go);
            cp_async16(KV(0, 1) + so, vh + go);
        }
        asm volatile("cp.async.commit_group;");
    }

    float O[8][4];
#pragma unroll
    for (int nt = 0; nt < 8; nt++)
#pragma unroll
        for (int e = 0; e < 4; e++) O[nt][e] = 0.f;
    float mrow0 = -1e30f, mrow1 = -1e30f, lrow0 = 0.f, lrow1 = 0.f;

    const int warp_top = q0 + wid * 16;
    const int niter = (q0 + 128) / 64;

    for (int it = 0; it < niter; it++) {
        asm volatile("cp.async.wait_group 0;");
        __syncthreads();
        const int cur = it & 1;
        if (it + 1 < niter) {
            const int nxt = 1 - cur;
            const size_t koff = head + (size_t)(it + 1) * 64 * HD_;
#pragma unroll
            for (int i = 0; i < 2; i++) {
                int u = tid + 256 * i, r = u >> 3, ch = u & 7;
                uint32_t so = SWZ128(r * 128 + ch * 16);
                size_t go = koff + (size_t)r * HD_ + ch * 8;
                cp_async16(KV(nxt, 0) + so, kh + go);
                cp_async16(KV(nxt, 1) + so, vh + go);
            }
            asm volatile("cp.async.commit_group;");
        }

        const int j0 = it * 64;
        if (j0 > warp_top + 15) continue;   // warp fully masked this tile

        // ---- S = scale * (Q K^T) ----
        float S[8][4];
#pragma unroll
        for (int nt = 0; nt < 8; nt++)
#pragma unroll
            for (int e = 0; e < 4; e++) S[nt][e] = 0.f;

        const uint32_t Kb = KV(cur, 0);
#pragma unroll
        for (int ks = 0; ks < 4; ks++) {
            const int k0 = ks * 16;
            uint32_t b[8][2];
#pragma unroll
            for (int p = 0; p < 4; p++) {
                const int g = lane >> 3;
                const int r = p * 16 + (g >> 1) * 8 + (lane & 7);
                ldsm4(b[2 * p][0], b[2 * p][1], b[2 * p + 1][0], b[2 * p + 1][1],
                      Kb + SWZ128(r * 128 + (k0 + (g & 1) * 8) * 2));
            }
            uint32_t a[4];
            ldsm4(a[0], a[1], a[2], a[3],
                  QS + SWZ128((wid * 16 + (lane & 15)) * 128 + (k0 + (lane >> 4) * 8) * 2));
#pragma unroll
            for (int nt = 0; nt < 8; nt++) mma16816h(S[nt], a, b[nt]);
        }

        // ---- scale + causal mask ----
        const int qi0 = warp_top + gid;
        if (j0 + 63 > warp_top) {
#pragma unroll
            for (int nt = 0; nt < 8; nt++)
#pragma unroll
                for (int e = 0; e < 4; e++) {
                    const int kj = j0 + nt * 8 + 2 * tig + (e & 1);
                    const int qi = qi0 + ((e >= 2) ? 8 : 0);
                    S[nt][e] = (kj <= qi) ? S[nt][e] * 0.125f : -1e30f;
                }
        } else {
#pragma unroll
            for (int nt = 0; nt < 8; nt++)
#pragma unroll
                for (int e = 0; e < 4; e++) S[nt][e] *= 0.125f;
        }

        // ---- online softmax (2 rows per thread) ----
        float mx0 = -1e30f, mx1 = -1e30f;
#pragma unroll
        for (int nt = 0; nt < 8; nt++) {
            mx0 = fmaxf(mx0, fmaxf(S[nt][0], S[nt][1]));
            mx1 = fmaxf(mx1, fmaxf(S[nt][2], S[nt][3]));
        }
        mx0 = fmaxf(mx0, __shfl_xor_sync(0xffffffffu, mx0, 1));
        mx0 = fmaxf(mx0, __shfl_xor_sync(0xffffffffu, mx0, 2));
        mx1 = fmaxf(mx1, __shfl_xor_sync(0xffffffffu, mx1, 1));
        mx1 = fmaxf(mx1, __shfl_xor_sync(0xffffffffu, mx1, 2));
        const float mn0 = fmaxf(mrow0, mx0), mn1 = fmaxf(mrow1, mx1);
        const float al0 = __expf(mrow0 - mn0), al1 = __expf(mrow1 - mn1);
        float ps0 = 0.f, ps1 = 0.f;
#pragma unroll
        for (int nt = 0; nt < 8; nt++) {
            S[nt][0] = __expf(S[nt][0] - mn0);
            S[nt][1] = __expf(S[nt][1] - mn0);
            S[nt][2] = __expf(S[nt][2] - mn1);
            S[nt][3] = __expf(S[nt][3] - mn1);
            ps0 += S[nt][0] + S[nt][1];
            ps1 += S[nt][2] + S[nt][3];
        }
        ps0 += __shfl_xor_sync(0xffffffffu, ps0, 1);
        ps0 += __shfl_xor_sync(0xffffffffu, ps0, 2);
        ps1 += __shfl_xor_sync(0xffffffffu, ps1, 1);
        ps1 += __shfl_xor_sync(0xffffffffu, ps1, 2);
        lrow0 = lrow0 * al0 + ps0;
        lrow1 = lrow1 * al1 + ps1;
        mrow0 = mn0;
        mrow1 = mn1;
#pragma unroll
        for (int nt = 0; nt < 8; nt++) {
            O[nt][0] *= al0; O[nt][1] *= al0;
            O[nt][2] *= al1; O[nt][3] *= al1;
        }

        // ---- pack P fp16 fragments (S acc layout == A frag layout) ----
        uint32_t P[4][4];
#pragma unroll
        for (int kt = 0; kt < 4; kt++) {
            P[kt][0] = pack_h2(S[2 * kt][0],     S[2 * kt][1]);
            P[kt][1] = pack_h2(S[2 * kt][2],     S[2 * kt][3]);
            P[kt][2] = pack_h2(S[2 * kt + 1][0], S[2 * kt + 1][1]);
            P[kt][3] = pack_h2(S[2 * kt + 1][2], S[2 * kt + 1][3]);
        }

        // ---- O += P V ----
        const uint32_t Vb = KV(cur, 1);
#pragma unroll
        for (int ks = 0; ks < 4; ks++) {
            uint32_t vb[8][2];
#pragma unroll
            for (int p = 0; p < 4; p++) {
                const int g = lane >> 3;
                const int r = ks * 16 + (g & 1) * 8 + (lane & 7);
                const int cb = (p * 16 + (g >> 1) * 8) * 2;
                ldsm4t(vb[2 * p][0], vb[2 * p][1], vb[2 * p + 1][0], vb[2 * p + 1][1],
                       Vb + SWZ128(r * 128 + cb));
            }
#pragma unroll
            for (int nt = 0; nt < 8; nt++) mma16816h(O[nt], P[ks], vb[nt]);
        }
    }

    // ---- epilogue: y = O / l -> fp16, layout [bt][h*64+d] ----
    const float inv0 = 1.0f / lrow0, inv1 = 1.0f / lrow1;
    const int b = bh >> 4, h = bh & 15;
    const size_t row0 = ((size_t)(b * T_ + warp_top + gid)) * C_ + h * HD_;
    const size_t row1 = row0 + (size_t)8 * C_;
#pragma unroll
    for (int nt = 0; nt < 8; nt++) {
        const int col = nt * 8 + 2 * tig;
        *reinterpret_cast<uint32_t*>(yf + row0 + col) = pack_h2(O[nt][0] * inv0, O[nt][1] * inv0);
        *reinterpret_cast<uint32_t*>(yf + row1 + col) = pack_h2(O[nt][2] * inv1, O[nt][3] * inv1);
    }
}

// ---------------------------------------------------------------------------
extern "C" void kernel_launch(void* const* d_in, const int* in_sizes, int n_in,
                              void* d_out, int out_size)
{
    const float* x      = (const float*)d_in[0];
    const float* fcos   = (const float*)d_in[1];
    const float* fsin   = (const float*)d_in[2];
    const float* w_attn = (const float*)d_in[3];
    const float* w_proj = (const float*)d_in[4];
    const float* qw     = (const float*)d_in[5];
    const float* kw     = (const float*)d_in[6];
    float* out = (float*)d_out;

    float* qkv;
    __half *xf, *waf, *wph, *wpl, *yf, *qh, *kh, *vh;
    cudaGetSymbolAddress((void**)&qkv, g_qkv);
    cudaGetSymbolAddress((void**)&xf,  g_xf);
    cudaGetSymbolAddress((void**)&waf, g_waf);
    cudaGetSymbolAddress((void**)&wph, g_wph);
    cudaGetSymbolAddress((void**)&wpl, g_wpl);
    cudaGetSymbolAddress((void**)&yf,  g_yf);
    cudaGetSymbolAddress((void**)&qh,  g_qh);
    cudaGetSymbolAddress((void**)&kh,  g_kh);
    cudaGetSymbolAddress((void**)&vh,  g_vh);

    cudaFuncSetAttribute(gemm_f16_1t, cudaFuncAttributeMaxDynamicSharedMemorySize, GSMEM1);
    cudaFuncSetAttribute(gemm_f16_2t, cudaFuncAttributeMaxDynamicSharedMemorySize, GSMEM2);
    cudaFuncSetAttribute(flash_mma, cudaFuncAttributeMaxDynamicSharedMemorySize, FSMEM);

    // 1) convert/split inputs
    {
        int n4 = (M_ * C_) / 4;
        conv_f16<<<(n4 + 255) / 256, 256>>>(x, xf, n4);
        n4 = (C3_ * C_) / 4;
        conv_f16<<<(n4 + 255) / 256, 256>>>(w_attn, waf, n4);
        n4 = (C_ * C_) / 4;
        split_f16<<<(n4 + 255) / 256, 256>>>(w_proj, wph, wpl, n4);
    }

    // 2) qkv = x @ w_attn^T  (plain fp16)
    {
        dim3 g(C3_ / 128, M_ / 128);
        gemm_f16_1t<<<g, 256, GSMEM1>>>(xf, waf, qkv, C3_, C_);
    }

    // 3) RMSNorm + RoPE + fp16 conversion, head-major
    norm_rope_split<<<(B_ * T_ * H_) / 8, 256>>>(qkv, fcos, fsin, qw, kw, qh, kh, vh);

    // 4) causal flash attention -> yf (fp16)
    {
        dim3 g(T_ / 128, B_ * H_);
        flash_mma<<<g, 256, FSMEM>>>(qh, kh, vh, yf);
    }

    // 5) out = y @ w_proj^T  (fp16 2-term)
    {
        dim3 g(C_ / 128, M_ / 128);
        gemm_f16_2t<<<g, 256, GSMEM2>>>(yf, wph, wpl, out, C_, C_);
    }
}

// round 11
// speedup vs baseline: 2.3588x; 1.1012x over previous
#include <cuda_runtime.h>
#include <cuda_fp16.h>
#include <cstdint>
#include <cstddef>

static constexpr int B_  = 2;
static constexpr int T_  = 2048;
static constexpr int C_  = 1024;
static constexpr int H_  = 16;
static constexpr int HD_ = 64;
static constexpr int C3_ = 3 * C_;
static constexpr int M_  = B_ * T_;      // 4096

// ---------------------------------------------------------------------------
// Scratch (__device__ globals; no allocation allowed)
// ---------------------------------------------------------------------------
__device__ __half g_qkv[(size_t)M_ * C3_];           // fp16 qkv (25 MB)
__device__ __half g_xf[(size_t)M_ * C_];             // x fp16
__device__ __half g_waf[(size_t)C3_ * C_];           // w_attn fp16
__device__ __half g_wpf[(size_t)C_ * C_];            // w_proj fp16
__device__ __half g_yf[(size_t)M_ * C_];             // attention out fp16
// head-major [B][H][T][64], 1-term fp16
__device__ __half g_qh[(size_t)M_ * C_];
__device__ __half g_kh[(size_t)M_ * C_];
__device__ __half g_vh[(size_t)M_ * C_];

// ---------------------------------------------------------------------------
// Helpers
// ---------------------------------------------------------------------------
__device__ __forceinline__ uint32_t smem_u32(const void* p) {
    uint32_t a;
    asm("{ .reg .u64 t; cvta.to.shared.u64 t, %1; cvt.u32.u64 %0, t; }" : "=r"(a) : "l"(p));
    return a;
}
#define SWZ128(o) ((o) ^ (((o) >> 3) & 0x70))

__device__ __forceinline__ void cp_async16(uint32_t dst, const void* src) {
    asm volatile("cp.async.cg.shared.global [%0], [%1], 16;" :: "r"(dst), "l"(src));
}
__device__ __forceinline__ void ldsm4(uint32_t& r0, uint32_t& r1, uint32_t& r2, uint32_t& r3,
                                      uint32_t addr) {
    asm volatile("ldmatrix.sync.aligned.m8n8.x4.shared.b16 {%0,%1,%2,%3}, [%4];"
                 : "=r"(r0), "=r"(r1), "=r"(r2), "=r"(r3) : "r"(addr));
}
__device__ __forceinline__ void ldsm4t(uint32_t& r0, uint32_t& r1, uint32_t& r2, uint32_t& r3,
                                       uint32_t addr) {
    asm volatile("ldmatrix.sync.aligned.m8n8.x4.trans.shared.b16 {%0,%1,%2,%3}, [%4];"
                 : "=r"(r0), "=r"(r1), "=r"(r2), "=r"(r3) : "r"(addr));
}
__device__ __forceinline__ void mma16816h(float* c, const uint32_t* a, const uint32_t* b) {
    asm volatile(
        "mma.sync.aligned.m16n8k16.row.col.f32.f16.f16.f32 "
        "{%0,%1,%2,%3}, {%4,%5,%6,%7}, {%8,%9}, {%0,%1,%2,%3};"
        : "+f"(c[0]), "+f"(c[1]), "+f"(c[2]), "+f"(c[3])
        : "r"(a[0]), "r"(a[1]), "r"(a[2]), "r"(a[3]), "r"(b[0]), "r"(b[1]));
}
__device__ __forceinline__ uint32_t pack_h2(float a, float b) {
    __half2 h(__float2half_rn(a), __float2half_rn(b));
    return *reinterpret_cast<uint32_t*>(&h);
}

// ---------------------------------------------------------------------------
// fp32 -> fp16 convert
// ---------------------------------------------------------------------------
__global__ __launch_bounds__(256)
void conv_f16(const float* __restrict__ in, __half* __restrict__ out, int n4)
{
    int i = blockIdx.x * blockDim.x + threadIdx.x;
    if (i >= n4) return;
    float4 v = reinterpret_cast<const float4*>(in)[i];
    reinterpret_cast<uint32_t*>(out)[2 * i]     = pack_h2(v.x, v.y);
    reinterpret_cast<uint32_t*>(out)[2 * i + 1] = pack_h2(v.z, v.w);
}

// ---------------------------------------------------------------------------
// Plain fp16 GEMM (NT): C = A @ B^T. 128x128 tile, BK=64, 8 warps,
// double-buffered 32KB stages. TOut = __half (qkv) or float (final out).
// ---------------------------------------------------------------------------
static constexpr int GSMEM1 = 65536;   // 2 x 32768

template <typename TOut>
__global__ __launch_bounds__(256, 2)
void gemm_f16_1t(const __half* __restrict__ A, const __half* __restrict__ Bw,
                 TOut* __restrict__ Cout, int N, int K)
{
    extern __shared__ char smem[];
    const uint32_t smem_base = smem_u32(smem);
    const int tid  = threadIdx.x;
    const int lane = tid & 31;
    const int wid  = tid >> 5;
    const int wr = (wid >> 2) * 64;
    const int wc = (wid & 3) * 32;
    const int m0 = blockIdx.y * 128;
    const int n0 = blockIdx.x * 128;

    float acc[4][4][4];
#pragma unroll
    for (int mi = 0; mi < 4; mi++)
#pragma unroll
        for (int ni = 0; ni < 4; ni++)
#pragma unroll
            for (int e = 0; e < 4; e++) acc[mi][ni][e] = 0.f;

    const int NC = K >> 6;

    auto load_chunk = [&](int cg) {
        const uint32_t base = smem_base + (cg & 1) * 32768;
        const int k0 = cg * 64;
#pragma unroll
        for (int i = 0; i < 4; i++) {
            const int u = tid + 256 * i;
            const int row = u >> 3, ch = u & 7;
            const uint32_t so = SWZ128(row * 128 + ch * 16);
            cp_async16(base + so,         A  + (size_t)(m0 + row) * K + k0 + ch * 8);
            cp_async16(base + 16384 + so, Bw + (size_t)(n0 + row) * K + k0 + ch * 8);
        }
        asm volatile("cp.async.commit_group;");
    };

    load_chunk(0);
    for (int cg = 0; cg < NC; cg++) {
        if (cg + 1 < NC) {
            load_chunk(cg + 1);
            asm volatile("cp.async.wait_group 1;");
        } else {
            asm volatile("cp.async.wait_group 0;");
        }
        __syncthreads();

        const uint32_t As = smem_base + (cg & 1) * 32768;
        const uint32_t Bs = As + 16384;
#pragma unroll
        for (int ks = 0; ks < 4; ks++) {
            const int cbb = ks * 32;
            uint32_t b[4][2];
#pragma unroll
            for (int p = 0; p < 2; p++) {
                const int g = lane >> 3;
                const int r = wc + p * 16 + (g >> 1) * 8 + (lane & 7);
                const int cb = cbb + (g & 1) * 16;
                ldsm4(b[2 * p][0], b[2 * p][1], b[2 * p + 1][0], b[2 * p + 1][1],
                      Bs + SWZ128(r * 128 + cb));
            }
#pragma unroll
            for (int mi = 0; mi < 4; mi++) {
                const int r = wr + mi * 16 + (lane & 15);
                const int cb = cbb + (lane >> 4) * 16;
                uint32_t a[4];
                ldsm4(a[0], a[1], a[2], a[3], As + SWZ128(r * 128 + cb));
#pragma unroll
                for (int ni = 0; ni < 4; ni++)
                    mma16816h(acc[mi][ni], a, b[ni]);
            }
        }
        __syncthreads();
    }

#pragma unroll
    for (int mi = 0; mi < 4; mi++) {
        const int m = m0 + wr + mi * 16 + (lane >> 2);
#pragma unroll
        for (int ni = 0; ni < 4; ni++) {
            const int n = n0 + wc + ni * 8 + (lane & 3) * 2;
            if constexpr (sizeof(TOut) == 2) {
                *reinterpret_cast<uint32_t*>((__half*)Cout + (size_t)m * N + n) =
                    pack_h2(acc[mi][ni][0], acc[mi][ni][1]);
                *reinterpret_cast<uint32_t*>((__half*)Cout + (size_t)(m + 8) * N + n) =
                    pack_h2(acc[mi][ni][2], acc[mi][ni][3]);
            } else {
                *reinterpret_cast<float2*>((float*)Cout + (size_t)m * N + n) =
                    make_float2(acc[mi][ni][0], acc[mi][ni][1]);
                *reinterpret_cast<float2*>((float*)Cout + (size_t)(m + 8) * N + n) =
                    make_float2(acc[mi][ni][2], acc[mi][ni][3]);
            }
        }
    }
}

// ---------------------------------------------------------------------------
// Fused per-head RMSNorm + RoPE, fp16 in / fp16 out, head-major [B][H][T][64].
// One warp per (bt, h).
// ---------------------------------------------------------------------------
__global__ __launch_bounds__(256)
void norm_rope_split(const __half* __restrict__ qkv, const float* __restrict__ cosT,
                     const float* __restrict__ sinT, const float* __restrict__ qw,
                     const float* __restrict__ kw,
                     __half* __restrict__ qh, __half* __restrict__ kh,
                     __half* __restrict__ vh)
{
    const int gw = (blockIdx.x * blockDim.x + threadIdx.x) >> 5;
    const int lane = threadIdx.x & 31;
    const int h = gw & (H_ - 1);
    const int bt = gw >> 4;
    const int t = bt & (T_ - 1);
    const int b = bt >> 11;

    const __half* qp = qkv + (size_t)bt * C3_ + h * HD_;
    const __half* kp = qp + C_;
    const __half* vp = qp + 2 * C_;
    const size_t ho = (((size_t)(b * H_ + h) * T_) + t) * HD_ + 2 * lane;
    const float c = cosT[t * (HD_ / 2) + lane];
    const float s = sinT[t * (HD_ / 2) + lane];

    {
        float2 v = __half22float2(*reinterpret_cast<const __half2*>(qp + 2 * lane));
        float ss = v.x * v.x + v.y * v.y;
#pragma unroll
        for (int off = 16; off > 0; off >>= 1) ss += __shfl_xor_sync(0xffffffffu, ss, off);
        float rms = rsqrtf(ss * (1.f / HD_) + 1e-6f);
        float x0 = v.x * rms * qw[2 * lane];
        float x1 = v.y * rms * qw[2 * lane + 1];
        *reinterpret_cast<uint32_t*>(qh + ho) = pack_h2(x0 * c - x1 * s, x0 * s + x1 * c);
    }
    {
        float2 v = __half22float2(*reinterpret_cast<const __half2*>(kp + 2 * lane));
        float ss = v.x * v.x + v.y * v.y;
#pragma unroll
        for (int off = 16; off > 0; off >>= 1) ss += __shfl_xor_sync(0xffffffffu, ss, off);
        float rms = rsqrtf(ss * (1.f / HD_) + 1e-6f);
        float x0 = v.x * rms * kw[2 * lane];
        float x1 = v.y * rms * kw[2 * lane + 1];
        *reinterpret_cast<uint32_t*>(kh + ho) = pack_h2(x0 * c - x1 * s, x0 * s + x1 * c);
    }
    {
        // V: straight copy (already fp16)
        *reinterpret_cast<uint32_t*>(vh + ho) =
            *reinterpret_cast<const uint32_t*>(vp + 2 * lane);
    }
}

// ---------------------------------------------------------------------------
// fp16 flash attention, causal. Q, K, P, V all 1-term fp16.
// BQ=128 (8 warps x 16 rows), BKV=64.
// smem: Q 16K + 2 x (K 8K + V 8K) = 48 KB.
// ---------------------------------------------------------------------------
static constexpr int FSMEM = 49152;

__global__ __launch_bounds__(256, 2)
void flash_mma(const __half* __restrict__ qh, const __half* __restrict__ kh,
               const __half* __restrict__ vh, __half* __restrict__ yf)
{
    extern __shared__ char smem[];
    const uint32_t sb = smem_u32(smem);
    const int tid = threadIdx.x, lane = tid & 31, wid = tid >> 5;
    const int gid = lane >> 2, tig = lane & 3;
    const int bh = blockIdx.y;
    const int q0 = (gridDim.x - 1 - blockIdx.x) * 128;   // heavy tiles first
    const size_t head = (size_t)bh * T_ * HD_;

    const uint32_t QS = sb;
    auto KV = [&](int buf, int t) -> uint32_t { return sb + 16384 + buf * 16384 + t * 8192; };

    {
#pragma unroll
        for (int i = 0; i < 4; i++) {
            int u = tid + 256 * i, r = u >> 3, ch = u & 7;
            uint32_t so = SWZ128(r * 128 + ch * 16);
            cp_async16(QS + so, qh + head + (size_t)(q0 + r) * HD_ + ch * 8);
        }
#pragma unroll
        for (int i = 0; i < 2; i++) {
            int u = tid + 256 * i, r = u >> 3, ch = u & 7;
            uint32_t so = SWZ128(r * 128 + ch * 16);
            size_t go = head + (size_t)r * HD_ + ch * 8;
            cp_async16(KV(0, 0) + so, kh + go);
            cp_async16(KV(0, 1) + so, vh + go);
        }
        asm volatile("cp.async.commit_group;");
    }

    float O[8][4];
#pragma unroll
    for (int nt = 0; nt < 8; nt++)
#pragma unroll
        for (int e = 0; e < 4; e++) O[nt][e] = 0.f;
    float mrow0 = -1e30f, mrow1 = -1e30f, lrow0 = 0.f, lrow1 = 0.f;

    const int warp_top = q0 + wid * 16;
    const int niter = (q0 + 128) / 64;

    for (int it = 0; it < niter; it++) {
        asm volatile("cp.async.wait_group 0;");
        __syncthreads();
        const int cur = it & 1;
        if (it + 1 < niter) {
            const int nxt = 1 - cur;
            const size_t koff = head + (size_t)(it + 1) * 64 * HD_;
#pragma unroll
            for (int i = 0; i < 2; i++) {
                int u = tid + 256 * i, r = u >> 3, ch = u & 7;
                uint32_t so = SWZ128(r * 128 + ch * 16);
                size_t go = koff + (size_t)r * HD_ + ch * 8;
                cp_async16(KV(nxt, 0) + so, kh + go);
                cp_async16(KV(nxt, 1) + so, vh + go);
            }
            asm volatile("cp.async.commit_group;");
        }

        const int j0 = it * 64;
        if (j0 > warp_top + 15) continue;   // warp fully masked this tile

        // ---- S = scale * (Q K^T) ----
        float S[8][4];
#pragma unroll
        for (int nt = 0; nt < 8; nt++)
#pragma unroll
            for (int e = 0; e < 4; e++) S[nt][e] = 0.f;

        const uint32_t Kb = KV(cur, 0);
#pragma unroll
        for (int ks = 0; ks < 4; ks++) {
            const int k0 = ks * 16;
            uint32_t b[8][2];
#pragma unroll
            for (int p = 0; p < 4; p++) {
                const int g = lane >> 3;
                const int r = p * 16 + (g >> 1) * 8 + (lane & 7);
                ldsm4(b[2 * p][0], b[2 * p][1], b[2 * p + 1][0], b[2 * p + 1][1],
                      Kb + SWZ128(r * 128 + (k0 + (g & 1) * 8) * 2));
            }
            uint32_t a[4];
            ldsm4(a[0], a[1], a[2], a[3],
                  QS + SWZ128((wid * 16 + (lane & 15)) * 128 + (k0 + (lane >> 4) * 8) * 2));
#pragma unroll
            for (int nt = 0; nt < 8; nt++) mma16816h(S[nt], a, b[nt]);
        }

        // ---- scale + causal mask ----
        const int qi0 = warp_top + gid;
        if (j0 + 63 > warp_top) {
#pragma unroll
            for (int nt = 0; nt < 8; nt++)
#pragma unroll
                for (int e = 0; e < 4; e++) {
                    const int kj = j0 + nt * 8 + 2 * tig + (e & 1);
                    const int qi = qi0 + ((e >= 2) ? 8 : 0);
                    S[nt][e] = (kj <= qi) ? S[nt][e] * 0.125f : -1e30f;
                }
        } else {
#pragma unroll
            for (int nt = 0; nt < 8; nt++)
#pragma unroll
                for (int e = 0; e < 4; e++) S[nt][e] *= 0.125f;
        }

        // ---- online softmax (2 rows per thread) ----
        float mx0 = -1e30f, mx1 = -1e30f;
#pragma unroll
        for (int nt = 0; nt < 8; nt++) {
            mx0 = fmaxf(mx0, fmaxf(S[nt][0], S[nt][1]));
            mx1 = fmaxf(mx1, fmaxf(S[nt][2], S[nt][3]));
        }
        mx0 = fmaxf(mx0, __shfl_xor_sync(0xffffffffu, mx0, 1));
        mx0 = fmaxf(mx0, __shfl_xor_sync(0xffffffffu, mx0, 2));
        mx1 = fmaxf(mx1, __shfl_xor_sync(0xffffffffu, mx1, 1));
        mx1 = fmaxf(mx1, __shfl_xor_sync(0xffffffffu, mx1, 2));
        const float mn0 = fmaxf(mrow0, mx0), mn1 = fmaxf(mrow1, mx1);
        const float al0 = __expf(mrow0 - mn0), al1 = __expf(mrow1 - mn1);
        float ps0 = 0.f, ps1 = 0.f;
#pragma unroll
        for (int nt = 0; nt < 8; nt++) {
            S[nt][0] = __expf(S[nt][0] - mn0);
            S[nt][1] = __expf(S[nt][1] - mn0);
            S[nt][2] = __expf(S[nt][2] - mn1);
            S[nt][3] = __expf(S[nt][3] - mn1);
            ps0 += S[nt][0] + S[nt][1];
            ps1 += S[nt][2] + S[nt][3];
        }
        ps0 += __shfl_xor_sync(0xffffffffu, ps0, 1);
        ps0 += __shfl_xor_sync(0xffffffffu, ps0, 2);
        ps1 += __shfl_xor_sync(0xffffffffu, ps1, 1);
        ps1 += __shfl_xor_sync(0xffffffffu, ps1, 2);
        lrow0 = lrow0 * al0 + ps0;
        lrow1 = lrow1 * al1 + ps1;
        mrow0 = mn0;
        mrow1 = mn1;
#pragma unroll
        for (int nt = 0; nt < 8; nt++) {
            O[nt][0] *= al0; O[nt][1] *= al0;
            O[nt][2] *= al1; O[nt][3] *= al1;
        }

        // ---- pack P fp16 fragments (S acc layout == A frag layout) ----
        uint32_t P[4][4];
#pragma unroll
        for (int kt = 0; kt < 4; kt++) {
            P[kt][0] = pack_h2(S[2 * kt][0],     S[2 * kt][1]);
            P[kt][1] = pack_h2(S[2 * kt][2],     S[2 * kt][3]);
            P[kt][2] = pack_h2(S[2 * kt + 1][0], S[2 * kt + 1][1]);
            P[kt][3] = pack_h2(S[2 * kt + 1][2], S[2 * kt + 1][3]);
        }

        // ---- O += P V ----
        const uint32_t Vb = KV(cur, 1);
#pragma unroll
        for (int ks = 0; ks < 4; ks++) {
            uint32_t vb[8][2];
#pragma unroll
            for (int p = 0; p < 4; p++) {
                const int g = lane >> 3;
                const int r = ks * 16 + (g & 1) * 8 + (lane & 7);
                const int cb = (p * 16 + (g >> 1) * 8) * 2;
                ldsm4t(vb[2 * p][0], vb[2 * p][1], vb[2 * p + 1][0], vb[2 * p + 1][1],
                       Vb + SWZ128(r * 128 + cb));
            }
#pragma unroll
            for (int nt = 0; nt < 8; nt++) mma16816h(O[nt], P[ks], vb[nt]);
        }
    }

    // ---- epilogue: y = O / l -> fp16, layout [bt][h*64+d] ----
    const float inv0 = 1.0f / lrow0, inv1 = 1.0f / lrow1;
    const int b = bh >> 4, h = bh & 15;
    const size_t row0 = ((size_t)(b * T_ + warp_top + gid)) * C_ + h * HD_;
    const size_t row1 = row0 + (size_t)8 * C_;
#pragma unroll
    for (int nt = 0; nt < 8; nt++) {
        const int col = nt * 8 + 2 * tig;
        *reinterpret_cast<uint32_t*>(yf + row0 + col) = pack_h2(O[nt][0] * inv0, O[nt][1] * inv0);
        *reinterpret_cast<uint32_t*>(yf + row1 + col) = pack_h2(O[nt][2] * inv1, O[nt][3] * inv1);
    }
}

// ---------------------------------------------------------------------------
extern "C" void kernel_launch(void* const* d_in, const int* in_sizes, int n_in,
                              void* d_out, int out_size)
{
    const float* x      = (const float*)d_in[0];
    const float* fcos   = (const float*)d_in[1];
    const float* fsin   = (const float*)d_in[2];
    const float* w_attn = (const float*)d_in[3];
    const float* w_proj = (const float*)d_in[4];
    const float* qw     = (const float*)d_in[5];
    const float* kw     = (const float*)d_in[6];
    float* out = (float*)d_out;

    __half *qkv, *xf, *waf, *wpf, *yf, *qh, *kh, *vh;
    cudaGetSymbolAddress((void**)&qkv, g_qkv);
    cudaGetSymbolAddress((void**)&xf,  g_xf);
    cudaGetSymbolAddress((void**)&waf, g_waf);
    cudaGetSymbolAddress((void**)&wpf, g_wpf);
    cudaGetSymbolAddress((void**)&yf,  g_yf);
    cudaGetSymbolAddress((void**)&qh,  g_qh);
    cudaGetSymbolAddress((void**)&kh,  g_kh);
    cudaGetSymbolAddress((void**)&vh,  g_vh);

    cudaFuncSetAttribute(gemm_f16_1t<__half>, cudaFuncAttributeMaxDynamicSharedMemorySize, GSMEM1);
    cudaFuncSetAttribute(gemm_f16_1t<float>,  cudaFuncAttributeMaxDynamicSharedMemorySize, GSMEM1);
    cudaFuncSetAttribute(flash_mma, cudaFuncAttributeMaxDynamicSharedMemorySize, FSMEM);

    // 1) convert inputs to fp16
    {
        int n4 = (M_ * C_) / 4;
        conv_f16<<<(n4 + 255) / 256, 256>>>(x, xf, n4);
        n4 = (C3_ * C_) / 4;
        conv_f16<<<(n4 + 255) / 256, 256>>>(w_attn, waf, n4);
        n4 = (C_ * C_) / 4;
        conv_f16<<<(n4 + 255) / 256, 256>>>(w_proj, wpf, n4);
    }

    // 2) qkv = x @ w_attn^T  (fp16 out)
    {
        dim3 g(C3_ / 128, M_ / 128);
        gemm_f16_1t<__half><<<g, 256, GSMEM1>>>(xf, waf, qkv, C3_, C_);
    }

    // 3) RMSNorm + RoPE, head-major fp16
    norm_rope_split<<<(B_ * T_ * H_) / 8, 256>>>(qkv, fcos, fsin, qw, kw, qh, kh, vh);

    // 4) causal flash attention -> yf (fp16)
    {
        dim3 g(T_ / 128, B_ * H_);
        flash_mma<<<g, 256, FSMEM>>>(qh, kh, vh, yf);
    }

    // 5) out = y @ w_proj^T  (fp32 out)
    {
        dim3 g(C_ / 128, M_ / 128);
        gemm_f16_1t<float><<<g, 256, GSMEM1>>>(yf, wpf, out, C_, C_);
    }
}

// round 13
// speedup vs baseline: 2.4986x; 1.0593x over previous
#include <cuda_runtime.h>
#include <cuda_fp16.h>
#include <cstdint>
#include <cstddef>

static constexpr int B_  = 2;
static constexpr int T_  = 2048;
static constexpr int C_  = 1024;
static constexpr int H_  = 16;
static constexpr int HD_ = 64;
static constexpr int C3_ = 3 * C_;
static constexpr int M_  = B_ * T_;      // 4096

// ---------------------------------------------------------------------------
// Scratch (__device__ globals; no allocation allowed)
// ---------------------------------------------------------------------------
__device__ __half g_qkv[(size_t)M_ * C3_];           // fp16 qkv (25 MB)
__device__ __half g_xf[(size_t)M_ * C_];             // x fp16
__device__ __half g_waf[(size_t)C3_ * C_];           // w_attn fp16
__device__ __half g_wpf[(size_t)C_ * C_];            // w_proj fp16
__device__ __half g_yf[(size_t)M_ * C_];             // attention out fp16
// head-major [B][H][T][64], 1-term fp16
__device__ __half g_qh[(size_t)M_ * C_];
__device__ __half g_kh[(size_t)M_ * C_];
__device__ __half g_vh[(size_t)M_ * C_];

// ---------------------------------------------------------------------------
// Helpers
// ---------------------------------------------------------------------------
__device__ __forceinline__ uint32_t smem_u32(const void* p) {
    uint32_t a;
    asm("{ .reg .u64 t; cvta.to.shared.u64 t, %1; cvt.u32.u64 %0, t; }" : "=r"(a) : "l"(p));
    return a;
}
#define SWZ128(o) ((o) ^ (((o) >> 3) & 0x70))

__device__ __forceinline__ void cp_async16(uint32_t dst, const void* src) {
    asm volatile("cp.async.cg.shared.global [%0], [%1], 16;" :: "r"(dst), "l"(src));
}
__device__ __forceinline__ void ldsm4(uint32_t& r0, uint32_t& r1, uint32_t& r2, uint32_t& r3,
                                      uint32_t addr) {
    asm volatile("ldmatrix.sync.aligned.m8n8.x4.shared.b16 {%0,%1,%2,%3}, [%4];"
                 : "=r"(r0), "=r"(r1), "=r"(r2), "=r"(r3) : "r"(addr));
}
__device__ __forceinline__ void ldsm4t(uint32_t& r0, uint32_t& r1, uint32_t& r2, uint32_t& r3,
                                       uint32_t addr) {
    asm volatile("ldmatrix.sync.aligned.m8n8.x4.trans.shared.b16 {%0,%1,%2,%3}, [%4];"
                 : "=r"(r0), "=r"(r1), "=r"(r2), "=r"(r3) : "r"(addr));
}
__device__ __forceinline__ void mma16816h(float* c, const uint32_t* a, const uint32_t* b) {
    asm volatile(
        "mma.sync.aligned.m16n8k16.row.col.f32.f16.f16.f32 "
        "{%0,%1,%2,%3}, {%4,%5,%6,%7}, {%8,%9}, {%0,%1,%2,%3};"
        : "+f"(c[0]), "+f"(c[1]), "+f"(c[2]), "+f"(c[3])
        : "r"(a[0]), "r"(a[1]), "r"(a[2]), "r"(a[3]), "r"(b[0]), "r"(b[1]));
}
__device__ __forceinline__ uint32_t pack_h2(float a, float b) {
    __half2 h(__float2half_rn(a), __float2half_rn(b));
    return *reinterpret_cast<uint32_t*>(&h);
}

// ---------------------------------------------------------------------------
// fp32 -> fp16 convert
// ---------------------------------------------------------------------------
__global__ __launch_bounds__(256)
void conv_f16(const float* __restrict__ in, __half* __restrict__ out, int n4)
{
    int i = blockIdx.x * blockDim.x + threadIdx.x;
    if (i >= n4) return;
    float4 v = reinterpret_cast<const float4*>(in)[i];
    reinterpret_cast<uint32_t*>(out)[2 * i]     = pack_h2(v.x, v.y);
    reinterpret_cast<uint32_t*>(out)[2 * i + 1] = pack_h2(v.z, v.w);
}

// ---------------------------------------------------------------------------
// Plain fp16 GEMM (NT): C = A @ B^T. 128x128 tile, BK=64, 8 warps,
// double-buffered 32KB stages. TOut = __half (qkv) or float (final out).
// ---------------------------------------------------------------------------
static constexpr int GSMEM1 = 65536;   // 2 x 32768

template <typename TOut>
__global__ __launch_bounds__(256, 2)
void gemm_f16_1t(const __half* __restrict__ A, const __half* __restrict__ Bw,
                 TOut* __restrict__ Cout, int N, int K)
{
    extern __shared__ char smem[];
    const uint32_t smem_base = smem_u32(smem);
    const int tid  = threadIdx.x;
    const int lane = tid & 31;
    const int wid  = tid >> 5;
    const int wr = (wid >> 2) * 64;
    const int wc = (wid & 3) * 32;
    const int m0 = blockIdx.y * 128;
    const int n0 = blockIdx.x * 128;

    float acc[4][4][4];
#pragma unroll
    for (int mi = 0; mi < 4; mi++)
#pragma unroll
        for (int ni = 0; ni < 4; ni++)
#pragma unroll
            for (int e = 0; e < 4; e++) acc[mi][ni][e] = 0.f;

    const int NC = K >> 6;

    auto load_chunk = [&](int cg) {
        const uint32_t base = smem_base + (cg & 1) * 32768;
        const int k0 = cg * 64;
#pragma unroll
        for (int i = 0; i < 4; i++) {
            const int u = tid + 256 * i;
            const int row = u >> 3, ch = u & 7;
            const uint32_t so = SWZ128(row * 128 + ch * 16);
            cp_async16(base + so,         A  + (size_t)(m0 + row) * K + k0 + ch * 8);
            cp_async16(base + 16384 + so, Bw + (size_t)(n0 + row) * K + k0 + ch * 8);
        }
        asm volatile("cp.async.commit_group;");
    };

    load_chunk(0);
    for (int cg = 0; cg < NC; cg++) {
        if (cg + 1 < NC) {
            load_chunk(cg + 1);
            asm volatile("cp.async.wait_group 1;");
        } else {
            asm volatile("cp.async.wait_group 0;");
        }
        __syncthreads();

        const uint32_t As = smem_base + (cg & 1) * 32768;
        const uint32_t Bs = As + 16384;
#pragma unroll
        for (int ks = 0; ks < 4; ks++) {
            const int cbb = ks * 32;
            uint32_t b[4][2];
#pragma unroll
            for (int p = 0; p < 2; p++) {
                const int g = lane >> 3;
                const int r = wc + p * 16 + (g >> 1) * 8 + (lane & 7);
                const int cb = cbb + (g & 1) * 16;
                ldsm4(b[2 * p][0], b[2 * p][1], b[2 * p + 1][0], b[2 * p + 1][1],
                      Bs + SWZ128(r * 128 + cb));
            }
#pragma unroll
            for (int mi = 0; mi < 4; mi++) {
                const int r = wr + mi * 16 + (lane & 15);
                const int cb = cbb + (lane >> 4) * 16;
                uint32_t a[4];
                ldsm4(a[0], a[1], a[2], a[3], As + SWZ128(r * 128 + cb));
#pragma unroll
                for (int ni = 0; ni < 4; ni++)
                    mma16816h(acc[mi][ni], a, b[ni]);
            }
        }
        __syncthreads();
    }

#pragma unroll
    for (int mi = 0; mi < 4; mi++) {
        const int m = m0 + wr + mi * 16 + (lane >> 2);
#pragma unroll
        for (int ni = 0; ni < 4; ni++) {
            const int n = n0 + wc + ni * 8 + (lane & 3) * 2;
            if constexpr (sizeof(TOut) == 2) {
                *reinterpret_cast<uint32_t*>((__half*)Cout + (size_t)m * N + n) =
                    pack_h2(acc[mi][ni][0], acc[mi][ni][1]);
                *reinterpret_cast<uint32_t*>((__half*)Cout + (size_t)(m + 8) * N + n) =
                    pack_h2(acc[mi][ni][2], acc[mi][ni][3]);
            } else {
                *reinterpret_cast<float2*>((float*)Cout + (size_t)m * N + n) =
                    make_float2(acc[mi][ni][0], acc[mi][ni][1]);
                *reinterpret_cast<float2*>((float*)Cout + (size_t)(m + 8) * N + n) =
                    make_float2(acc[mi][ni][2], acc[mi][ni][3]);
            }
        }
    }
}

// ---------------------------------------------------------------------------
// Fused per-head RMSNorm + RoPE, fp16 in / fp16 out, head-major [B][H][T][64].
// ---------------------------------------------------------------------------
__global__ __launch_bounds__(256)
void norm_rope_split(const __half* __restrict__ qkv, const float* __restrict__ cosT,
                     const float* __restrict__ sinT, const float* __restrict__ qw,
                     const float* __restrict__ kw,
                     __half* __restrict__ qh, __half* __restrict__ kh,
                     __half* __restrict__ vh)
{
    const int gw = (blockIdx.x * blockDim.x + threadIdx.x) >> 5;
    const int lane = threadIdx.x & 31;
    const int h = gw & (H_ - 1);
    const int bt = gw >> 4;
    const int t = bt & (T_ - 1);
    const int b = bt >> 11;

    const __half* qp = qkv + (size_t)bt * C3_ + h * HD_;
    const __half* kp = qp + C_;
    const __half* vp = qp + 2 * C_;
    const size_t ho = (((size_t)(b * H_ + h) * T_) + t) * HD_ + 2 * lane;
    const float c = cosT[t * (HD_ / 2) + lane];
    const float s = sinT[t * (HD_ / 2) + lane];

    {
        float2 v = __half22float2(*reinterpret_cast<const __half2*>(qp + 2 * lane));
        float ss = v.x * v.x + v.y * v.y;
#pragma unroll
        for (int off = 16; off > 0; off >>= 1) ss += __shfl_xor_sync(0xffffffffu, ss, off);
        float rms = rsqrtf(ss * (1.f / HD_) + 1e-6f);
        float x0 = v.x * rms * qw[2 * lane];
        float x1 = v.y * rms * qw[2 * lane + 1];
        *reinterpret_cast<uint32_t*>(qh + ho) = pack_h2(x0 * c - x1 * s, x0 * s + x1 * c);
    }
    {
        float2 v = __half22float2(*reinterpret_cast<const __half2*>(kp + 2 * lane));
        float ss = v.x * v.x + v.y * v.y;
#pragma unroll
        for (int off = 16; off > 0; off >>= 1) ss += __shfl_xor_sync(0xffffffffu, ss, off);
        float rms = rsqrtf(ss * (1.f / HD_) + 1e-6f);
        float x0 = v.x * rms * kw[2 * lane];
        float x1 = v.y * rms * kw[2 * lane + 1];
        *reinterpret_cast<uint32_t*>(kh + ho) = pack_h2(x0 * c - x1 * s, x0 * s + x1 * c);
    }
    {
        *reinterpret_cast<uint32_t*>(vh + ho) =
            *reinterpret_cast<const uint32_t*>(vp + 2 * lane);
    }
}

// ---------------------------------------------------------------------------
// fp16 flash attention, causal, NO max-tracking:
// RMSNorm bounds |q.k|*scale <= 8 -> exp(s) <= e^8 ~ 2981 fits fp16; row sums
// fit fp32. So softmax = exp2(s * 0.125*log2e) / deferred row-sum.
// BQ=128 (8 warps x 16 rows), BKV=64. smem: Q 16K + 2 x (K 8K + V 8K) = 48 KB.
// ---------------------------------------------------------------------------
static constexpr int FSMEM = 49152;
static constexpr float EXP2_SCALE = 0.125f * 1.4426950408889634f;   // log2(e)/8

__global__ __launch_bounds__(256, 2)
void flash_mma(const __half* __restrict__ qh, const __half* __restrict__ kh,
               const __half* __restrict__ vh, __half* __restrict__ yf)
{
    extern __shared__ char smem[];
    const uint32_t sb = smem_u32(smem);
    const int tid = threadIdx.x, lane = tid & 31, wid = tid >> 5;
    const int gid = lane >> 2, tig = lane & 3;
    const int bh = blockIdx.y;
    const int q0 = (gridDim.x - 1 - blockIdx.x) * 128;   // heavy tiles first
    const size_t head = (size_t)bh * T_ * HD_;

    const uint32_t QS = sb;
    auto KV = [&](int buf, int t) -> uint32_t { return sb + 16384 + buf * 16384 + t * 8192; };

    {
#pragma unroll
        for (int i = 0; i < 4; i++) {
            int u = tid + 256 * i, r = u >> 3, ch = u & 7;
            uint32_t so = SWZ128(r * 128 + ch * 16);
            cp_async16(QS + so, qh + head + (size_t)(q0 + r) * HD_ + ch * 8);
        }
#pragma unroll
        for (int i = 0; i < 2; i++) {
            int u = tid + 256 * i, r = u >> 3, ch = u & 7;
            uint32_t so = SWZ128(r * 128 + ch * 16);
            size_t go = head + (size_t)r * HD_ + ch * 8;
            cp_async16(KV(0, 0) + so, kh + go);
            cp_async16(KV(0, 1) + so, vh + go);
        }
        asm volatile("cp.async.commit_group;");
    }

    float O[8][4];
#pragma unroll
    for (int nt = 0; nt < 8; nt++)
#pragma unroll
        for (int e = 0; e < 4; e++) O[nt][e] = 0.f;
    float lrow0 = 0.f, lrow1 = 0.f;     // per-thread partial row sums

    const int warp_top = q0 + wid * 16;
    const int niter = (q0 + 128) / 64;

    for (int it = 0; it < niter; it++) {
        asm volatile("cp.async.wait_group 0;");
        __syncthreads();
        const int cur = it & 1;
        if (it + 1 < niter) {
            const int nxt = 1 - cur;
            const size_t koff = head + (size_t)(it + 1) * 64 * HD_;
#pragma unroll
            for (int i = 0; i < 2; i++) {
                int u = tid + 256 * i, r = u >> 3, ch = u & 7;
                uint32_t so = SWZ128(r * 128 + ch * 16);
                size_t go = koff + (size_t)r * HD_ + ch * 8;
                cp_async16(KV(nxt, 0) + so, kh + go);
                cp_async16(KV(nxt, 1) + so, vh + go);
            }
            asm volatile("cp.async.commit_group;");
        }

        const int j0 = it * 64;
        if (j0 > warp_top + 15) continue;   // warp fully masked this tile

        // ---- S = Q K^T (raw scores) ----
        float S[8][4];
#pragma unroll
        for (int nt = 0; nt < 8; nt++)
#pragma unroll
            for (int e = 0; e < 4; e++) S[nt][e] = 0.f;

        const uint32_t Kb = KV(cur, 0);
#pragma unroll
        for (int ks = 0; ks < 4; ks++) {
            const int k0 = ks * 16;
            uint32_t b[8][2];
#pragma unroll
            for (int p = 0; p < 4; p++) {
                const int g = lane >> 3;
                const int r = p * 16 + (g >> 1) * 8 + (lane & 7);
                ldsm4(b[2 * p][0], b[2 * p][1], b[2 * p + 1][0], b[2 * p + 1][1],
                      Kb + SWZ128(r * 128 + (k0 + (g & 1) * 8) * 2));
            }
            uint32_t a[4];
            ldsm4(a[0], a[1], a[2], a[3],
                  QS + SWZ128((wid * 16 + (lane & 15)) * 128 + (k0 + (lane >> 4) * 8) * 2));
#pragma unroll
            for (int nt = 0; nt < 8; nt++) mma16816h(S[nt], a, b[nt]);
        }

        // ---- p = exp2(s * log2e/8), masked -> 0; accumulate row partials ----
        const int qi0 = warp_top + gid;
        const bool need_mask = (j0 + 63 > warp_top);
#pragma unroll
        for (int nt = 0; nt < 8; nt++) {
#pragma unroll
            for (int e = 0; e < 4; e++) {
                float p = exp2f(S[nt][e] * EXP2_SCALE);
                if (need_mask) {
                    const int kj = j0 + nt * 8 + 2 * tig + (e & 1);
                    const int qi = qi0 + ((e >= 2) ? 8 : 0);
                    if (kj > qi) p = 0.f;
                }
                S[nt][e] = p;
            }
            lrow0 += S[nt][0] + S[nt][1];
            lrow1 += S[nt][2] + S[nt][3];
        }

        // ---- pack P fp16 fragments (S acc layout == A frag layout) ----
        uint32_t P[4][4];
#pragma unroll
        for (int kt = 0; kt < 4; kt++) {
            P[kt][0] = pack_h2(S[2 * kt][0],     S[2 * kt][1]);
            P[kt][1] = pack_h2(S[2 * kt][2],     S[2 * kt][3]);
            P[kt][2] = pack_h2(S[2 * kt + 1][0], S[2 * kt + 1][1]);
            P[kt][3] = pack_h2(S[2 * kt + 1][2], S[2 * kt + 1][3]);
        }

        // ---- O += P V ----
        const uint32_t Vb = KV(cur, 1);
#pragma unroll
        for (int ks = 0; ks < 4; ks++) {
            uint32_t vb[8][2];
#pragma unroll
            for (int p = 0; p < 4; p++) {
                const int g = lane >> 3;
                const int r = ks * 16 + (g & 1) * 8 + (lane & 7);
                const int cb = (p * 16 + (g >> 1) * 8) * 2;
                ldsm4t(vb[2 * p][0], vb[2 * p][1], vb[2 * p + 1][0], vb[2 * p + 1][1],
                       Vb + SWZ128(r * 128 + cb));
            }
#pragma unroll
            for (int nt = 0; nt < 8; nt++) mma16816h(O[nt], P[ks], vb[nt]);
        }
    }

    // ---- single deferred row-sum reduction (4 lanes per row) ----
    lrow0 += __shfl_xor_sync(0xffffffffu, lrow0, 1);
    lrow0 += __shfl_xor_sync(0xffffffffu, lrow0, 2);
    lrow1 += __shfl_xor_sync(0xffffffffu, lrow1, 1);
    lrow1 += __shfl_xor_sync(0xffffffffu, lrow1, 2);

    // ---- epilogue: y = O / l -> fp16, layout [bt][h*64+d] ----
    const float inv0 = 1.0f / lrow0, inv1 = 1.0f / lrow1;
    const int b = bh >> 4, h = bh & 15;
    const size_t row0 = ((size_t)(b * T_ + warp_top + gid)) * C_ + h * HD_;
    const size_t row1 = row0 + (size_t)8 * C_;
#pragma unroll
    for (int nt = 0; nt < 8; nt++) {
        const int col = nt * 8 + 2 * tig;
        *reinterpret_cast<uint32_t*>(yf + row0 + col) = pack_h2(O[nt][0] * inv0, O[nt][1] * inv0);
        *reinterpret_cast<uint32_t*>(yf + row1 + col) = pack_h2(O[nt][2] * inv1, O[nt][3] * inv1);
    }
}

// ---------------------------------------------------------------------------
extern "C" void kernel_launch(void* const* d_in, const int* in_sizes, int n_in,
                              void* d_out, int out_size)
{
    const float* x      = (const float*)d_in[0];
    const float* fcos   = (const float*)d_in[1];
    const float* fsin   = (const float*)d_in[2];
    const float* w_attn = (const float*)d_in[3];
    const float* w_proj = (const float*)d_in[4];
    const float* qw     = (const float*)d_in[5];
    const float* kw     = (const float*)d_in[6];
    float* out = (float*)d_out;

    __half *qkv, *xf, *waf, *wpf, *yf, *qh, *kh, *vh;
    cudaGetSymbolAddress((void**)&qkv, g_qkv);
    cudaGetSymbolAddress((void**)&xf,  g_xf);
    cudaGetSymbolAddress((void**)&waf, g_waf);
    cudaGetSymbolAddress((void**)&wpf, g_wpf);
    cudaGetSymbolAddress((void**)&yf,  g_yf);
    cudaGetSymbolAddress((void**)&qh,  g_qh);
    cudaGetSymbolAddress((void**)&kh,  g_kh);
    cudaGetSymbolAddress((void**)&vh,  g_vh);

    cudaFuncSetAttribute(gemm_f16_1t<__half>, cudaFuncAttributeMaxDynamicSharedMemorySize, GSMEM1);
    cudaFuncSetAttribute(gemm_f16_1t<float>,  cudaFuncAttributeMaxDynamicSharedMemorySize, GSMEM1);
    cudaFuncSetAttribute(flash_mma, cudaFuncAttributeMaxDynamicSharedMemorySize, FSMEM);

    // 1) convert inputs to fp16
    {
        int n4 = (M_ * C_) / 4;
        conv_f16<<<(n4 + 255) / 256, 256>>>(x, xf, n4);
        n4 = (C3_ * C_) / 4;
        conv_f16<<<(n4 + 255) / 256, 256>>>(w_attn, waf, n4);
        n4 = (C_ * C_) / 4;
        conv_f16<<<(n4 + 255) / 256, 256>>>(w_proj, wpf, n4);
    }

    // 2) qkv = x @ w_attn^T  (fp16 out)
    {
        dim3 g(C3_ / 128, M_ / 128);
        gemm_f16_1t<__half><<<g, 256, GSMEM1>>>(xf, waf, qkv, C3_, C_);
    }

    // 3) RMSNorm + RoPE, head-major fp16
    norm_rope_split<<<(B_ * T_ * H_) / 8, 256>>>(qkv, fcos, fsin, qw, kw, qh, kh, vh);

    // 4) causal flash attention -> yf (fp16)
    {
        dim3 g(T_ / 128, B_ * H_);
        flash_mma<<<g, 256, FSMEM>>>(qh, kh, vh, yf);
    }

    // 5) out = y @ w_proj^T  (fp32 out)
    {
        dim3 g(C_ / 128, M_ / 128);
        gemm_f16_1t<float><<<g, 256, GSMEM1>>>(yf, wpf, out, C_, C_);
    }
}

// round 15
// speedup vs baseline: 2.6026x; 1.0416x over previous
#include <cuda_runtime.h>
#include <cuda_fp16.h>
#include <cstdint>
#include <cstddef>

static constexpr int B_  = 2;
static constexpr int T_  = 2048;
static constexpr int C_  = 1024;
static constexpr int H_  = 16;
static constexpr int HD_ = 64;
static constexpr int C3_ = 3 * C_;
static constexpr int M_  = B_ * T_;      // 4096

// ---------------------------------------------------------------------------
// Scratch (__device__ globals; no allocation allowed)
// ---------------------------------------------------------------------------
__device__ __half g_qkv[(size_t)M_ * C3_];           // fp16 qkv (25 MB)
__device__ __half g_xf[(size_t)M_ * C_];             // x fp16
__device__ __half g_waf[(size_t)C3_ * C_];           // w_attn fp16
__device__ __half g_wpf[(size_t)C_ * C_];            // w_proj fp16
__device__ __half g_yf[(size_t)M_ * C_];             // attention out fp16
// head-major [B][H][T][64], 1-term fp16  (q pre-scaled by log2e/8)
__device__ __half g_qh[(size_t)M_ * C_];
__device__ __half g_kh[(size_t)M_ * C_];
__device__ __half g_vh[(size_t)M_ * C_];

// ---------------------------------------------------------------------------
// Helpers
// ---------------------------------------------------------------------------
__device__ __forceinline__ uint32_t smem_u32(const void* p) {
    uint32_t a;
    asm("{ .reg .u64 t; cvta.to.shared.u64 t, %1; cvt.u32.u64 %0, t; }" : "=r"(a) : "l"(p));
    return a;
}
#define SWZ128(o) ((o) ^ (((o) >> 3) & 0x70))

__device__ __forceinline__ void cp_async16(uint32_t dst, const void* src) {
    asm volatile("cp.async.cg.shared.global [%0], [%1], 16;" :: "r"(dst), "l"(src));
}
__device__ __forceinline__ void ldsm4(uint32_t& r0, uint32_t& r1, uint32_t& r2, uint32_t& r3,
                                      uint32_t addr) {
    asm volatile("ldmatrix.sync.aligned.m8n8.x4.shared.b16 {%0,%1,%2,%3}, [%4];"
                 : "=r"(r0), "=r"(r1), "=r"(r2), "=r"(r3) : "r"(addr));
}
__device__ __forceinline__ void ldsm4t(uint32_t& r0, uint32_t& r1, uint32_t& r2, uint32_t& r3,
                                       uint32_t addr) {
    asm volatile("ldmatrix.sync.aligned.m8n8.x4.trans.shared.b16 {%0,%1,%2,%3}, [%4];"
                 : "=r"(r0), "=r"(r1), "=r"(r2), "=r"(r3) : "r"(addr));
}
__device__ __forceinline__ void mma16816h(float* c, const uint32_t* a, const uint32_t* b) {
    asm volatile(
        "mma.sync.aligned.m16n8k16.row.col.f32.f16.f16.f32 "
        "{%0,%1,%2,%3}, {%4,%5,%6,%7}, {%8,%9}, {%0,%1,%2,%3};"
        : "+f"(c[0]), "+f"(c[1]), "+f"(c[2]), "+f"(c[3])
        : "r"(a[0]), "r"(a[1]), "r"(a[2]), "r"(a[3]), "r"(b[0]), "r"(b[1]));
}
__device__ __forceinline__ uint32_t pack_h2(float a, float b) {
    __half2 h(__float2half_rn(a), __float2half_rn(b));
    return *reinterpret_cast<uint32_t*>(&h);
}
__device__ __forceinline__ uint32_t ex2_h2(uint32_t x) {
    uint32_t y;
    asm("ex2.approx.f16x2 %0, %1;" : "=r"(y) : "r"(x));
    return y;
}

// ---------------------------------------------------------------------------
// fp32 -> fp16 convert
// ---------------------------------------------------------------------------
__global__ __launch_bounds__(256)
void conv_f16(const float* __restrict__ in, __half* __restrict__ out, int n4)
{
    int i = blockIdx.x * blockDim.x + threadIdx.x;
    if (i >= n4) return;
    float4 v = reinterpret_cast<const float4*>(in)[i];
    reinterpret_cast<uint32_t*>(out)[2 * i]     = pack_h2(v.x, v.y);
    reinterpret_cast<uint32_t*>(out)[2 * i + 1] = pack_h2(v.z, v.w);
}

// ---------------------------------------------------------------------------
// Plain fp16 GEMM (NT): C = A @ B^T. 128x128 tile, BK=64, 8 warps.
// 3-stage cp.async ring (3 x 32KB), ONE __syncthreads per chunk, depth-2
// prefetch. TOut = __half (qkv) or float (final out).
// ---------------------------------------------------------------------------
static constexpr int GSMEM1 = 98304;   // 3 x 32768

template <typename TOut>
__global__ __launch_bounds__(256, 2)
void gemm_f16_1t(const __half* __restrict__ A, const __half* __restrict__ Bw,
                 TOut* __restrict__ Cout, int N, int K)
{
    extern __shared__ char smem[];
    const uint32_t smem_base = smem_u32(smem);
    const int tid  = threadIdx.x;
    const int lane = tid & 31;
    const int wid  = tid >> 5;
    const int wr = (wid >> 2) * 64;
    const int wc = (wid & 3) * 32;
    const int m0 = blockIdx.y * 128;
    const int n0 = blockIdx.x * 128;

    float acc[4][4][4];
#pragma unroll
    for (int mi = 0; mi < 4; mi++)
#pragma unroll
        for (int ni = 0; ni < 4; ni++)
#pragma unroll
            for (int e = 0; e < 4; e++) acc[mi][ni][e] = 0.f;

    const int NC = K >> 6;

    auto load_chunk = [&](int cg) {
        const uint32_t base = smem_base + (cg % 3) * 32768;
        const int k0 = cg * 64;
#pragma unroll
        for (int i = 0; i < 4; i++) {
            const int u = tid + 256 * i;
            const int row = u >> 3, ch = u & 7;
            const uint32_t so = SWZ128(row * 128 + ch * 16);
            cp_async16(base + so,         A  + (size_t)(m0 + row) * K + k0 + ch * 8);
            cp_async16(base + 16384 + so, Bw + (size_t)(n0 + row) * K + k0 + ch * 8);
        }
        asm volatile("cp.async.commit_group;");
    };

    load_chunk(0);
    load_chunk(1);
    for (int cg = 0; cg < NC; cg++) {
        if (cg + 1 < NC) asm volatile("cp.async.wait_group 1;");
        else             asm volatile("cp.async.wait_group 0;");
        __syncthreads();                 // single barrier per chunk
        if (cg + 2 < NC) load_chunk(cg + 2);

        const uint32_t As = smem_base + (cg % 3) * 32768;
        const uint32_t Bs = As + 16384;
#pragma unroll
        for (int ks = 0; ks < 4; ks++) {
            const int cbb = ks * 32;
            uint32_t b[4][2];
#pragma unroll
            for (int p = 0; p < 2; p++) {
                const int g = lane >> 3;
                const int r = wc + p * 16 + (g >> 1) * 8 + (lane & 7);
                const int cb = cbb + (g & 1) * 16;
                ldsm4(b[2 * p][0], b[2 * p][1], b[2 * p + 1][0], b[2 * p + 1][1],
                      Bs + SWZ128(r * 128 + cb));
            }
#pragma unroll
            for (int mi = 0; mi < 4; mi++) {
                const int r = wr + mi * 16 + (lane & 15);
                const int cb = cbb + (lane >> 4) * 16;
                uint32_t a[4];
                ldsm4(a[0], a[1], a[2], a[3], As + SWZ128(r * 128 + cb));
#pragma unroll
                for (int ni = 0; ni < 4; ni++)
                    mma16816h(acc[mi][ni], a, b[ni]);
            }
        }
    }

#pragma unroll
    for (int mi = 0; mi < 4; mi++) {
        const int m = m0 + wr + mi * 16 + (lane >> 2);
#pragma unroll
        for (int ni = 0; ni < 4; ni++) {
            const int n = n0 + wc + ni * 8 + (lane & 3) * 2;
            if constexpr (sizeof(TOut) == 2) {
                *reinterpret_cast<uint32_t*>((__half*)Cout + (size_t)m * N + n) =
                    pack_h2(acc[mi][ni][0], acc[mi][ni][1]);
                *reinterpret_cast<uint32_t*>((__half*)Cout + (size_t)(m + 8) * N + n) =
                    pack_h2(acc[mi][ni][2], acc[mi][ni][3]);
            } else {
                *reinterpret_cast<float2*>((float*)Cout + (size_t)m * N + n) =
                    make_float2(acc[mi][ni][0], acc[mi][ni][1]);
                *reinterpret_cast<float2*>((float*)Cout + (size_t)(m + 8) * N + n) =
                    make_float2(acc[mi][ni][2], acc[mi][ni][3]);
            }
        }
    }
}

// ---------------------------------------------------------------------------
// Fused per-head RMSNorm + RoPE, fp16 in / fp16 out, head-major [B][H][T][64].
// Q is pre-scaled by log2(e)/8 so flash scores land directly in exp2 domain.
// ---------------------------------------------------------------------------
static constexpr float EXP2_SCALE = 0.125f * 1.4426950408889634f;   // log2(e)/8

__global__ __launch_bounds__(256)
void norm_rope_split(const __half* __restrict__ qkv, const float* __restrict__ cosT,
                     const float* __restrict__ sinT, const float* __restrict__ qw,
                     const float* __restrict__ kw,
                     __half* __restrict__ qh, __half* __restrict__ kh,
                     __half* __restrict__ vh)
{
    const int gw = (blockIdx.x * blockDim.x + threadIdx.x) >> 5;
    const int lane = threadIdx.x & 31;
    const int h = gw & (H_ - 1);
    const int bt = gw >> 4;
    const int t = bt & (T_ - 1);
    const int b = bt >> 11;

    const __half* qp = qkv + (size_t)bt * C3_ + h * HD_;
    const __half* kp = qp + C_;
    const __half* vp = qp + 2 * C_;
    const size_t ho = (((size_t)(b * H_ + h) * T_) + t) * HD_ + 2 * lane;
    const float c = cosT[t * (HD_ / 2) + lane];
    const float s = sinT[t * (HD_ / 2) + lane];

    {
        float2 v = __half22float2(*reinterpret_cast<const __half2*>(qp + 2 * lane));
        float ss = v.x * v.x + v.y * v.y;
#pragma unroll
        for (int off = 16; off > 0; off >>= 1) ss += __shfl_xor_sync(0xffffffffu, ss, off);
        float rms = rsqrtf(ss * (1.f / HD_) + 1e-6f) * EXP2_SCALE;
        float x0 = v.x * rms * qw[2 * lane];
        float x1 = v.y * rms * qw[2 * lane + 1];
        *reinterpret_cast<uint32_t*>(qh + ho) = pack_h2(x0 * c - x1 * s, x0 * s + x1 * c);
    }
    {
        float2 v = __half22float2(*reinterpret_cast<const __half2*>(kp + 2 * lane));
        float ss = v.x * v.x + v.y * v.y;
#pragma unroll
        for (int off = 16; off > 0; off >>= 1) ss += __shfl_xor_sync(0xffffffffu, ss, off);
        float rms = rsqrtf(ss * (1.f / HD_) + 1e-6f);
        float x0 = v.x * rms * kw[2 * lane];
        float x1 = v.y * rms * kw[2 * lane + 1];
        *reinterpret_cast<uint32_t*>(kh + ho) = pack_h2(x0 * c - x1 * s, x0 * s + x1 * c);
    }
    {
        *reinterpret_cast<uint32_t*>(vh + ho) =
            *reinterpret_cast<const uint32_t*>(vp + 2 * lane);
    }
}

// ---------------------------------------------------------------------------
// fp16 flash attention, causal, max-free softmax in the exp2 domain:
// Q pre-scaled by log2e/8 -> S = log2-domain scores, |S| <= 8*log2e ~ 11.5;
// P = ex2.approx.f16x2(S) directly yields the fp16 P fragments.
// BQ=128 (8 warps x 16 rows), BKV=64. smem: Q 16K + 2 x (K 8K + V 8K) = 48 KB.
// ---------------------------------------------------------------------------
static constexpr int FSMEM = 49152;

__global__ __launch_bounds__(256, 2)
void flash_mma(const __half* __restrict__ qh, const __half* __restrict__ kh,
               const __half* __restrict__ vh, __half* __restrict__ yf)
{
    extern __shared__ char smem[];
    const uint32_t sb = smem_u32(smem);
    const int tid = threadIdx.x, lane = tid & 31, wid = tid >> 5;
    const int gid = lane >> 2, tig = lane & 3;
    const int bh = blockIdx.y;
    const int q0 = (gridDim.x - 1 - blockIdx.x) * 128;   // heavy tiles first
    const size_t head = (size_t)bh * T_ * HD_;

    const uint32_t QS = sb;
    auto KV = [&](int buf, int t) -> uint32_t { return sb + 16384 + buf * 16384 + t * 8192; };

    {
#pragma unroll
        for (int i = 0; i < 4; i++) {
            int u = tid + 256 * i, r = u >> 3, ch = u & 7;
            uint32_t so = SWZ128(r * 128 + ch * 16);
            cp_async16(QS + so, qh + head + (size_t)(q0 + r) * HD_ + ch * 8);
        }
#pragma unroll
        for (int i = 0; i < 2; i++) {
            int u = tid + 256 * i, r = u >> 3, ch = u & 7;
            uint32_t so = SWZ128(r * 128 + ch * 16);
            size_t go = head + (size_t)r * HD_ + ch * 8;
            cp_async16(KV(0, 0) + so, kh + go);
            cp_async16(KV(0, 1) + so, vh + go);
        }
        asm volatile("cp.async.commit_group;");
    }

    float O[8][4];
#pragma unroll
    for (int nt = 0; nt < 8; nt++)
#pragma unroll
        for (int e = 0; e < 4; e++) O[nt][e] = 0.f;
    float lrow0 = 0.f, lrow1 = 0.f;     // per-thread partial row sums

    const int warp_top = q0 + wid * 16;
    const int niter = (q0 + 128) / 64;

    for (int it = 0; it < niter; it++) {
        asm volatile("cp.async.wait_group 0;");
        __syncthreads();
        const int cur = it & 1;
        if (it + 1 < niter) {
            const int nxt = 1 - cur;
            const size_t koff = head + (size_t)(it + 1) * 64 * HD_;
#pragma unroll
            for (int i = 0; i < 2; i++) {
                int u = tid + 256 * i, r = u >> 3, ch = u & 7;
                uint32_t so = SWZ128(r * 128 + ch * 16);
                size_t go = koff + (size_t)r * HD_ + ch * 8;
                cp_async16(KV(nxt, 0) + so, kh + go);
                cp_async16(KV(nxt, 1) + so, vh + go);
            }
            asm volatile("cp.async.commit_group;");
        }

        const int j0 = it * 64;
        if (j0 > warp_top + 15) continue;   // warp fully masked this tile

        // ---- S = Q K^T (log2-domain scores) ----
        float S[8][4];
#pragma unroll
        for (int nt = 0; nt < 8; nt++)
#pragma unroll
            for (int e = 0; e < 4; e++) S[nt][e] = 0.f;

        const uint32_t Kb = KV(cur, 0);
#pragma unroll
        for (int ks = 0; ks < 4; ks++) {
            const int k0 = ks * 16;
            uint32_t b[8][2];
#pragma unroll
            for (int p = 0; p < 4; p++) {
                const int g = lane >> 3;
                const int r = p * 16 + (g >> 1) * 8 + (lane & 7);
                ldsm4(b[2 * p][0], b[2 * p][1], b[2 * p + 1][0], b[2 * p + 1][1],
                      Kb + SWZ128(r * 128 + (k0 + (g & 1) * 8) * 2));
            }
            uint32_t a[4];
            ldsm4(a[0], a[1], a[2], a[3],
                  QS + SWZ128((wid * 16 + (lane & 15)) * 128 + (k0 + (lane >> 4) * 8) * 2));
#pragma unroll
            for (int nt = 0; nt < 8; nt++) mma16816h(S[nt], a, b[nt]);
        }

        // ---- mask (fp32) ----
        const int qi0 = warp_top + gid;
        if (j0 + 63 > warp_top) {
#pragma unroll
            for (int nt = 0; nt < 8; nt++)
#pragma unroll
                for (int e = 0; e < 4; e++) {
                    const int kj = j0 + nt * 8 + 2 * tig + (e & 1);
                    const int qi = qi0 + ((e >= 2) ? 8 : 0);
                    if (kj > qi) S[nt][e] = -100000.f;   // -> fp16 -inf -> ex2 = 0
                }
        }

        // ---- P = ex2(S) in fp16x2; accumulate row partials; P frags direct ----
        uint32_t P[4][4];
#pragma unroll
        for (int kt = 0; kt < 4; kt++) {
            uint32_t p00 = ex2_h2(pack_h2(S[2 * kt][0],     S[2 * kt][1]));
            uint32_t p01 = ex2_h2(pack_h2(S[2 * kt][2],     S[2 * kt][3]));
            uint32_t p10 = ex2_h2(pack_h2(S[2 * kt + 1][0], S[2 * kt + 1][1]));
            uint32_t p11 = ex2_h2(pack_h2(S[2 * kt + 1][2], S[2 * kt + 1][3]));
            P[kt][0] = p00; P[kt][1] = p01; P[kt][2] = p10; P[kt][3] = p11;
            float2 f;
            f = __half22float2(*reinterpret_cast<__half2*>(&p00)); lrow0 += f.x + f.y;
            f = __half22float2(*reinterpret_cast<__half2*>(&p10)); lrow0 += f.x + f.y;
            f = __half22float2(*reinterpret_cast<__half2*>(&p01)); lrow1 += f.x + f.y;
            f = __half22float2(*reinterpret_cast<__half2*>(&p11)); lrow1 += f.x + f.y;
        }

        // ---- O += P V ----
        const uint32_t Vb = KV(cur, 1);
#pragma unroll
        for (int ks = 0; ks < 4; ks++) {
            uint32_t vb[8][2];
#pragma unroll
            for (int p = 0; p < 4; p++) {
                const int g = lane >> 3;
                const int r = ks * 16 + (g & 1) * 8 + (lane & 7);
                const int cb = (p * 16 + (g >> 1) * 8) * 2;
                ldsm4t(vb[2 * p][0], vb[2 * p][1], vb[2 * p + 1][0], vb[2 * p + 1][1],
                       Vb + SWZ128(r * 128 + cb));
            }
#pragma unroll
            for (int nt = 0; nt < 8; nt++) mma16816h(O[nt], P[ks], vb[nt]);
        }
    }

    // ---- single deferred row-sum reduction (4 lanes per row) ----
    lrow0 += __shfl_xor_sync(0xffffffffu, lrow0, 1);
    lrow0 += __shfl_xor_sync(0xffffffffu, lrow0, 2);
    lrow1 += __shfl_xor_sync(0xffffffffu, lrow1, 1);
    lrow1 += __shfl_xor_sync(0xffffffffu, lrow1, 2);

    // ---- epilogue: y = O / l -> fp16, layout [bt][h*64+d] ----
    const float inv0 = 1.0f / lrow0, inv1 = 1.0f / lrow1;
    const int b = bh >> 4, h = bh & 15;
    const size_t row0 = ((size_t)(b * T_ + warp_top + gid)) * C_ + h * HD_;
    const size_t row1 = row0 + (size_t)8 * C_;
#pragma unroll
    for (int nt = 0; nt < 8; nt++) {
        const int col = nt * 8 + 2 * tig;
        *reinterpret_cast<uint32_t*>(yf + row0 + col) = pack_h2(O[nt][0] * inv0, O[nt][1] * inv0);
        *reinterpret_cast<uint32_t*>(yf + row1 + col) = pack_h2(O[nt][2] * inv1, O[nt][3] * inv1);
    }
}

// ---------------------------------------------------------------------------
extern "C" void kernel_launch(void* const* d_in, const int* in_sizes, int n_in,
                              void* d_out, int out_size)
{
    const float* x      = (const float*)d_in[0];
    const float* fcos   = (const float*)d_in[1];
    const float* fsin   = (const float*)d_in[2];
    const float* w_attn = (const float*)d_in[3];
    const float* w_proj = (const float*)d_in[4];
    const float* qw     = (const float*)d_in[5];
    const float* kw     = (const float*)d_in[6];
    float* out = (float*)d_out;

    __half *qkv, *xf, *waf, *wpf, *yf, *qh, *kh, *vh;
    cudaGetSymbolAddress((void**)&qkv, g_qkv);
    cudaGetSymbolAddress((void**)&xf,  g_xf);
    cudaGetSymbolAddress((void**)&waf, g_waf);
    cudaGetSymbolAddress((void**)&wpf, g_wpf);
    cudaGetSymbolAddress((void**)&yf,  g_yf);
    cudaGetSymbolAddress((void**)&qh,  g_qh);
    cudaGetSymbolAddress((void**)&kh,  g_kh);
    cudaGetSymbolAddress((void**)&vh,  g_vh);

    cudaFuncSetAttribute(gemm_f16_1t<__half>, cudaFuncAttributeMaxDynamicSharedMemorySize, GSMEM1);
    cudaFuncSetAttribute(gemm_f16_1t<float>,  cudaFuncAttributeMaxDynamicSharedMemorySize, GSMEM1);
    cudaFuncSetAttribute(flash_mma, cudaFuncAttributeMaxDynamicSharedMemorySize, FSMEM);

    // 1) convert inputs to fp16
    {
        int n4 = (M_ * C_) / 4;
        conv_f16<<<(n4 + 255) / 256, 256>>>(x, xf, n4);
        n4 = (C3_ * C_) / 4;
        conv_f16<<<(n4 + 255) / 256, 256>>>(w_attn, waf, n4);
        n4 = (C_ * C_) / 4;
        conv_f16<<<(n4 + 255) / 256, 256>>>(w_proj, wpf, n4);
    }

    // 2) qkv = x @ w_attn^T  (fp16 out)
    {
        dim3 g(C3_ / 128, M_ / 128);
        gemm_f16_1t<__half><<<g, 256, GSMEM1>>>(xf, waf, qkv, C3_, C_);
    }

    // 3) RMSNorm + RoPE, head-major fp16 (q pre-scaled into exp2 domain)
    norm_rope_split<<<(B_ * T_ * H_) / 8, 256>>>(qkv, fcos, fsin, qw, kw, qh, kh, vh);

    // 4) causal flash attention -> yf (fp16)
    {
        dim3 g(T_ / 128, B_ * H_);
        flash_mma<<<g, 256, FSMEM>>>(qh, kh, vh, yf);
    }

    // 5) out = y @ w_proj^T  (fp32 out)
    {
        dim3 g(C_ / 128, M_ / 128);
        gemm_f16_1t<float><<<g, 256, GSMEM1>>>(yf, wpf, out, C_, C_);
    }
}

// round 16
// speedup vs baseline: 2.6936x; 1.0350x over previous
#include <cuda_runtime.h>
#include <cuda_fp16.h>
#include <cstdint>
#include <cstddef>

static constexpr int B_  = 2;
static constexpr int T_  = 2048;
static constexpr int C_  = 1024;
static constexpr int H_  = 16;
static constexpr int HD_ = 64;
static constexpr int C3_ = 3 * C_;
static constexpr int M_  = B_ * T_;      // 4096

// ---------------------------------------------------------------------------
// Scratch (__device__ globals; no allocation allowed)
// ---------------------------------------------------------------------------
__device__ __half g_qkv[(size_t)M_ * C3_];           // fp16 qkv (25 MB)
__device__ __half g_xf[(size_t)M_ * C_];             // x fp16
__device__ __half g_waf[(size_t)C3_ * C_];           // w_attn fp16
__device__ __half g_wpf[(size_t)C_ * C_];            // w_proj fp16
__device__ __half g_yf[(size_t)M_ * C_];             // attention out fp16
// head-major [B][H][T][64], 1-term fp16  (q pre-scaled by log2e/8)
__device__ __half g_qh[(size_t)M_ * C_];
__device__ __half g_kh[(size_t)M_ * C_];
__device__ __half g_vh[(size_t)M_ * C_];

// ---------------------------------------------------------------------------
// Helpers
// ---------------------------------------------------------------------------
__device__ __forceinline__ uint32_t smem_u32(const void* p) {
    uint32_t a;
    asm("{ .reg .u64 t; cvta.to.shared.u64 t, %1; cvt.u32.u64 %0, t; }" : "=r"(a) : "l"(p));
    return a;
}
#define SWZ128(o) ((o) ^ (((o) >> 3) & 0x70))

__device__ __forceinline__ void cp_async16(uint32_t dst, const void* src) {
    asm volatile("cp.async.cg.shared.global [%0], [%1], 16;" :: "r"(dst), "l"(src));
}
__device__ __forceinline__ void ldsm4(uint32_t& r0, uint32_t& r1, uint32_t& r2, uint32_t& r3,
                                      uint32_t addr) {
    asm volatile("ldmatrix.sync.aligned.m8n8.x4.shared.b16 {%0,%1,%2,%3}, [%4];"
                 : "=r"(r0), "=r"(r1), "=r"(r2), "=r"(r3) : "r"(addr));
}
__device__ __forceinline__ void ldsm4t(uint32_t& r0, uint32_t& r1, uint32_t& r2, uint32_t& r3,
                                       uint32_t addr) {
    asm volatile("ldmatrix.sync.aligned.m8n8.x4.trans.shared.b16 {%0,%1,%2,%3}, [%4];"
                 : "=r"(r0), "=r"(r1), "=r"(r2), "=r"(r3) : "r"(addr));
}
__device__ __forceinline__ void mma16816h(float* c, const uint32_t* a, const uint32_t* b) {
    asm volatile(
        "mma.sync.aligned.m16n8k16.row.col.f32.f16.f16.f32 "
        "{%0,%1,%2,%3}, {%4,%5,%6,%7}, {%8,%9}, {%0,%1,%2,%3};"
        : "+f"(c[0]), "+f"(c[1]), "+f"(c[2]), "+f"(c[3])
        : "r"(a[0]), "r"(a[1]), "r"(a[2]), "r"(a[3]), "r"(b[0]), "r"(b[1]));
}
__device__ __forceinline__ uint32_t pack_h2(float a, float b) {
    __half2 h(__float2half_rn(a), __float2half_rn(b));
    return *reinterpret_cast<uint32_t*>(&h);
}
__device__ __forceinline__ uint32_t ex2_h2(uint32_t x) {
    uint32_t y;
    asm("ex2.approx.f16x2 %0, %1;" : "=r"(y) : "r"(x));
    return y;
}

// ---------------------------------------------------------------------------
// fp32 -> fp16 convert, 3 arrays in one launch
// ---------------------------------------------------------------------------
__global__ __launch_bounds__(256)
void conv_f16x3(const float* __restrict__ a, __half* __restrict__ ao, int na,
                const float* __restrict__ b, __half* __restrict__ bo, int nb,
                const float* __restrict__ c, __half* __restrict__ co, int nc)
{
    int i = blockIdx.x * blockDim.x + threadIdx.x;
    const float* in;
    __half* out;
    if (i < na) { in = a; out = ao; }
    else if (i < na + nb) { in = b; out = bo; i -= na; }
    else if (i < na + nb + nc) { in = c; out = co; i -= na + nb; }
    else return;
    float4 v = reinterpret_cast<const float4*>(in)[i];
    reinterpret_cast<uint32_t*>(out)[2 * i]     = pack_h2(v.x, v.y);
    reinterpret_cast<uint32_t*>(out)[2 * i + 1] = pack_h2(v.z, v.w);
}

// ---------------------------------------------------------------------------
// Plain fp16 GEMM (NT): C = A @ B^T. 128x128 tile, BK=64, 8 warps.
// 3-stage cp.async ring; next-chunk loads issued AFTER ks=0 compute so the
// cp.async burst doesn't collide with the chunk-head ldsm burst on the LSU.
// ---------------------------------------------------------------------------
static constexpr int GSMEM1 = 98304;   // 3 x 32768

template <typename TOut>
__global__ __launch_bounds__(256, 2)
void gemm_f16_1t(const __half* __restrict__ A, const __half* __restrict__ Bw,
                 TOut* __restrict__ Cout, int N, int K)
{
    extern __shared__ char smem[];
    const uint32_t smem_base = smem_u32(smem);
    const int tid  = threadIdx.x;
    const int lane = tid & 31;
    const int wid  = tid >> 5;
    const int wr = (wid >> 2) * 64;
    const int wc = (wid & 3) * 32;
    const int m0 = blockIdx.y * 128;
    const int n0 = blockIdx.x * 128;

    float acc[4][4][4];
#pragma unroll
    for (int mi = 0; mi < 4; mi++)
#pragma unroll
        for (int ni = 0; ni < 4; ni++)
#pragma unroll
            for (int e = 0; e < 4; e++) acc[mi][ni][e] = 0.f;

    const int NC = K >> 6;

    auto load_chunk = [&](int cg) {
        const uint32_t base = smem_base + (cg % 3) * 32768;
        const int k0 = cg * 64;
#pragma unroll
        for (int i = 0; i < 4; i++) {
            const int u = tid + 256 * i;
            const int row = u >> 3, ch = u & 7;
            const uint32_t so = SWZ128(row * 128 + ch * 16);
            cp_async16(base + so,         A  + (size_t)(m0 + row) * K + k0 + ch * 8);
            cp_async16(base + 16384 + so, Bw + (size_t)(n0 + row) * K + k0 + ch * 8);
        }
        asm volatile("cp.async.commit_group;");
    };

    auto ks_body = [&](uint32_t As, uint32_t Bs, int ks) {
        const int cbb = ks * 32;
        uint32_t b[4][2];
#pragma unroll
        for (int p = 0; p < 2; p++) {
            const int g = lane >> 3;
            const int r = wc + p * 16 + (g >> 1) * 8 + (lane & 7);
            const int cb = cbb + (g & 1) * 16;
            ldsm4(b[2 * p][0], b[2 * p][1], b[2 * p + 1][0], b[2 * p + 1][1],
                  Bs + SWZ128(r * 128 + cb));
        }
#pragma unroll
        for (int mi = 0; mi < 4; mi++) {
            const int r = wr + mi * 16 + (lane & 15);
            const int cb = cbb + (lane >> 4) * 16;
            uint32_t a[4];
            ldsm4(a[0], a[1], a[2], a[3], As + SWZ128(r * 128 + cb));
#pragma unroll
            for (int ni = 0; ni < 4; ni++)
                mma16816h(acc[mi][ni], a, b[ni]);
        }
    };

    load_chunk(0);
    load_chunk(1);
    for (int cg = 0; cg < NC; cg++) {
        if (cg + 1 < NC) asm volatile("cp.async.wait_group 1;");
        else             asm volatile("cp.async.wait_group 0;");
        __syncthreads();

        const uint32_t As = smem_base + (cg % 3) * 32768;
        const uint32_t Bs = As + 16384;
        ks_body(As, Bs, 0);
        if (cg + 2 < NC) load_chunk(cg + 2);   // spread LSU burst
#pragma unroll
        for (int ks = 1; ks < 4; ks++) ks_body(As, Bs, ks);
    }

#pragma unroll
    for (int mi = 0; mi < 4; mi++) {
        const int m = m0 + wr + mi * 16 + (lane >> 2);
#pragma unroll
        for (int ni = 0; ni < 4; ni++) {
            const int n = n0 + wc + ni * 8 + (lane & 3) * 2;
            if constexpr (sizeof(TOut) == 2) {
                *reinterpret_cast<uint32_t*>((__half*)Cout + (size_t)m * N + n) =
                    pack_h2(acc[mi][ni][0], acc[mi][ni][1]);
                *reinterpret_cast<uint32_t*>((__half*)Cout + (size_t)(m + 8) * N + n) =
                    pack_h2(acc[mi][ni][2], acc[mi][ni][3]);
            } else {
                *reinterpret_cast<float2*>((float*)Cout + (size_t)m * N + n) =
                    make_float2(acc[mi][ni][0], acc[mi][ni][1]);
                *reinterpret_cast<float2*>((float*)Cout + (size_t)(m + 8) * N + n) =
                    make_float2(acc[mi][ni][2], acc[mi][ni][3]);
            }
        }
    }
}

// ---------------------------------------------------------------------------
// Fused per-head RMSNorm + RoPE, fp16 in / fp16 out, head-major [B][H][T][64].
// Q is pre-scaled by log2(e)/8 so flash scores land directly in exp2 domain.
// ---------------------------------------------------------------------------
static constexpr float EXP2_SCALE = 0.125f * 1.4426950408889634f;   // log2(e)/8

__global__ __launch_bounds__(256)
void norm_rope_split(const __half* __restrict__ qkv, const float* __restrict__ cosT,
                     const float* __restrict__ sinT, const float* __restrict__ qw,
                     const float* __restrict__ kw,
                     __half* __restrict__ qh, __half* __restrict__ kh,
                     __half* __restrict__ vh)
{
    const int gw = (blockIdx.x * blockDim.x + threadIdx.x) >> 5;
    const int lane = threadIdx.x & 31;
    const int h = gw & (H_ - 1);
    const int bt = gw >> 4;
    const int t = bt & (T_ - 1);
    const int b = bt >> 11;

    const __half* qp = qkv + (size_t)bt * C3_ + h * HD_;
    const __half* kp = qp + C_;
    const __half* vp = qp + 2 * C_;
    const size_t ho = (((size_t)(b * H_ + h) * T_) + t) * HD_ + 2 * lane;
    const float c = cosT[t * (HD_ / 2) + lane];
    const float s = sinT[t * (HD_ / 2) + lane];

    {
        float2 v = __half22float2(*reinterpret_cast<const __half2*>(qp + 2 * lane));
        float ss = v.x * v.x + v.y * v.y;
#pragma unroll
        for (int off = 16; off > 0; off >>= 1) ss += __shfl_xor_sync(0xffffffffu, ss, off);
        float rms = rsqrtf(ss * (1.f / HD_) + 1e-6f) * EXP2_SCALE;
        float x0 = v.x * rms * qw[2 * lane];
        float x1 = v.y * rms * qw[2 * lane + 1];
        *reinterpret_cast<uint32_t*>(qh + ho) = pack_h2(x0 * c - x1 * s, x0 * s + x1 * c);
    }
    {
        float2 v = __half22float2(*reinterpret_cast<const __half2*>(kp + 2 * lane));
        float ss = v.x * v.x + v.y * v.y;
#pragma unroll
        for (int off = 16; off > 0; off >>= 1) ss += __shfl_xor_sync(0xffffffffu, ss, off);
        float rms = rsqrtf(ss * (1.f / HD_) + 1e-6f);
        float x0 = v.x * rms * kw[2 * lane];
        float x1 = v.y * rms * kw[2 * lane + 1];
        *reinterpret_cast<uint32_t*>(kh + ho) = pack_h2(x0 * c - x1 * s, x0 * s + x1 * c);
    }
    {
        *reinterpret_cast<uint32_t*>(vh + ho) =
            *reinterpret_cast<const uint32_t*>(vp + 2 * lane);
    }
}

// ---------------------------------------------------------------------------
// fp16 flash attention, causal, max-free exp2 softmax.
// BKV=128 per barrier (two 64-key sub-tiles), double-buffered.
// smem: Q 16K + 2 x 32K = 80 KB; 2 CTAs/SM.
// ---------------------------------------------------------------------------
static constexpr int FSMEM = 81920;

__global__ __launch_bounds__(256, 2)
void flash_mma(const __half* __restrict__ qh, const __half* __restrict__ kh,
               const __half* __restrict__ vh, __half* __restrict__ yf)
{
    extern __shared__ char smem[];
    const uint32_t sb = smem_u32(smem);
    const int tid = threadIdx.x, lane = tid & 31, wid = tid >> 5;
    const int gid = lane >> 2, tig = lane & 3;
    const int bh = blockIdx.y;
    const int q0 = (gridDim.x - 1 - blockIdx.x) * 128;   // heavy tiles first
    const size_t head = (size_t)bh * T_ * HD_;

    const uint32_t QS = sb;
    // buf in {0,1}, sub in {0,1}, which: 0=K, 1=V
    auto KV = [&](int buf, int sub, int which) -> uint32_t {
        return sb + 16384 + buf * 32768 + sub * 16384 + which * 8192;
    };

    auto load_tile128 = [&](int t128, int buf) {
        const int kr0 = t128 * 128;
#pragma unroll
        for (int i = 0; i < 4; i++) {
            int u = tid + 256 * i, r = u >> 3, ch = u & 7;   // r 0..127
            int sub = r >> 6, lr = r & 63;
            uint32_t so = SWZ128(lr * 128 + ch * 16);
            size_t go = head + (size_t)(kr0 + r) * HD_ + ch * 8;
            cp_async16(KV(buf, sub, 0) + so, kh + go);
            cp_async16(KV(buf, sub, 1) + so, vh + go);
        }
        asm volatile("cp.async.commit_group;");
    };

    {
#pragma unroll
        for (int i = 0; i < 4; i++) {
            int u = tid + 256 * i, r = u >> 3, ch = u & 7;
            uint32_t so = SWZ128(r * 128 + ch * 16);
            cp_async16(QS + so, qh + head + (size_t)(q0 + r) * HD_ + ch * 8);
        }
        load_tile128(0, 0);   // Q + first KV tile share one group
    }

    float O[8][4];
#pragma unroll
    for (int nt = 0; nt < 8; nt++)
#pragma unroll
        for (int e = 0; e < 4; e++) O[nt][e] = 0.f;
    float lrow0 = 0.f, lrow1 = 0.f;

    const int warp_top = q0 + wid * 16;
    const int niter = q0 / 128 + 1;      // 128-key tiles

    for (int it = 0; it < niter; it++) {
        asm volatile("cp.async.wait_group 0;");
        __syncthreads();
        const int buf = it & 1;

#pragma unroll
        for (int sub = 0; sub < 2; sub++) {
            const int j0 = it * 128 + sub * 64;
            if (j0 <= warp_top + 15) {
                // ---- S = Q K^T (log2-domain scores) ----
                float S[8][4];
#pragma unroll
                for (int nt = 0; nt < 8; nt++)
#pragma unroll
                    for (int e = 0; e < 4; e++) S[nt][e] = 0.f;

                const uint32_t Kb = KV(buf, sub, 0);
#pragma unroll
                for (int ks = 0; ks < 4; ks++) {
                    const int k0 = ks * 16;
                    uint32_t b[8][2];
#pragma unroll
                    for (int p = 0; p < 4; p++) {
                        const int g = lane >> 3;
                        const int r = p * 16 + (g >> 1) * 8 + (lane & 7);
                        ldsm4(b[2 * p][0], b[2 * p][1], b[2 * p + 1][0], b[2 * p + 1][1],
                              Kb + SWZ128(r * 128 + (k0 + (g & 1) * 8) * 2));
                    }
                    uint32_t a[4];
                    ldsm4(a[0], a[1], a[2], a[3],
                          QS + SWZ128((wid * 16 + (lane & 15)) * 128 +
                                      (k0 + (lane >> 4) * 8) * 2));
#pragma unroll
                    for (int nt = 0; nt < 8; nt++) mma16816h(S[nt], a, b[nt]);
                }

                // ---- mask ----
                const int qi0 = warp_top + gid;
                if (j0 + 63 > warp_top) {
#pragma unroll
                    for (int nt = 0; nt < 8; nt++)
#pragma unroll
                        for (int e = 0; e < 4; e++) {
                            const int kj = j0 + nt * 8 + 2 * tig + (e & 1);
                            const int qi = qi0 + ((e >= 2) ? 8 : 0);
                            if (kj > qi) S[nt][e] = -100000.f;
                        }
                }

                // ---- P = ex2(S) fp16x2; accumulate row partials ----
                uint32_t P[4][4];
#pragma unroll
                for (int kt = 0; kt < 4; kt++) {
                    uint32_t p00 = ex2_h2(pack_h2(S[2 * kt][0],     S[2 * kt][1]));
                    uint32_t p01 = ex2_h2(pack_h2(S[2 * kt][2],     S[2 * kt][3]));
                    uint32_t p10 = ex2_h2(pack_h2(S[2 * kt + 1][0], S[2 * kt + 1][1]));
                    uint32_t p11 = ex2_h2(pack_h2(S[2 * kt + 1][2], S[2 * kt + 1][3]));
                    P[kt][0] = p00; P[kt][1] = p01; P[kt][2] = p10; P[kt][3] = p11;
                    float2 f;
                    f = __half22float2(*reinterpret_cast<__half2*>(&p00)); lrow0 += f.x + f.y;
                    f = __half22float2(*reinterpret_cast<__half2*>(&p10)); lrow0 += f.x + f.y;
                    f = __half22float2(*reinterpret_cast<__half2*>(&p01)); lrow1 += f.x + f.y;
                    f = __half22float2(*reinterpret_cast<__half2*>(&p11)); lrow1 += f.x + f.y;
                }

                // ---- O += P V ----
                const uint32_t Vb = KV(buf, sub, 1);
#pragma unroll
                for (int ks = 0; ks < 4; ks++) {
                    uint32_t vb[8][2];
#pragma unroll
                    for (int p = 0; p < 4; p++) {
                        const int g = lane >> 3;
                        const int r = ks * 16 + (g & 1) * 8 + (lane & 7);
                        const int cb = (p * 16 + (g >> 1) * 8) * 2;
                        ldsm4t(vb[2 * p][0], vb[2 * p][1], vb[2 * p + 1][0], vb[2 * p + 1][1],
                               Vb + SWZ128(r * 128 + cb));
                    }
#pragma unroll
                    for (int nt = 0; nt < 8; nt++) mma16816h(O[nt], P[ks], vb[nt]);
                }
            }
            // prefetch next 128-tile between sub-tiles (all warps, uniform)
            if (sub == 0 && it + 1 < niter) load_tile128(it + 1, 1 - buf);
        }
    }

    // ---- single deferred row-sum reduction ----
    lrow0 += __shfl_xor_sync(0xffffffffu, lrow0, 1);
    lrow0 += __shfl_xor_sync(0xffffffffu, lrow0, 2);
    lrow1 += __shfl_xor_sync(0xffffffffu, lrow1, 1);
    lrow1 += __shfl_xor_sync(0xffffffffu, lrow1, 2);

    // ---- epilogue ----
    const float inv0 = 1.0f / lrow0, inv1 = 1.0f / lrow1;
    const int b = bh >> 4, h = bh & 15;
    const size_t row0 = ((size_t)(b * T_ + warp_top + gid)) * C_ + h * HD_;
    const size_t row1 = row0 + (size_t)8 * C_;
#pragma unroll
    for (int nt = 0; nt < 8; nt++) {
        const int col = nt * 8 + 2 * tig;
        *reinterpret_cast<uint32_t*>(yf + row0 + col) = pack_h2(O[nt][0] * inv0, O[nt][1] * inv0);
        *reinterpret_cast<uint32_t*>(yf + row1 + col) = pack_h2(O[nt][2] * inv1, O[nt][3] * inv1);
    }
}

// ---------------------------------------------------------------------------
extern "C" void kernel_launch(void* const* d_in, const int* in_sizes, int n_in,
                              void* d_out, int out_size)
{
    const float* x      = (const float*)d_in[0];
    const float* fcos   = (const float*)d_in[1];
    const float* fsin   = (const float*)d_in[2];
    const float* w_attn = (const float*)d_in[3];
    const float* w_proj = (const float*)d_in[4];
    const float* qw     = (const float*)d_in[5];
    const float* kw     = (const float*)d_in[6];
    float* out = (float*)d_out;

    __half *qkv, *xf, *waf, *wpf, *yf, *qh, *kh, *vh;
    cudaGetSymbolAddress((void**)&qkv, g_qkv);
    cudaGetSymbolAddress((void**)&xf,  g_xf);
    cudaGetSymbolAddress((void**)&waf, g_waf);
    cudaGetSymbolAddress((void**)&wpf, g_wpf);
    cudaGetSymbolAddress((void**)&yf,  g_yf);
    cudaGetSymbolAddress((void**)&qh,  g_qh);
    cudaGetSymbolAddress((void**)&kh,  g_kh);
    cudaGetSymbolAddress((void**)&vh,  g_vh);

    cudaFuncSetAttribute(gemm_f16_1t<__half>, cudaFuncAttributeMaxDynamicSharedMemorySize, GSMEM1);
    cudaFuncSetAttribute(gemm_f16_1t<float>,  cudaFuncAttributeMaxDynamicSharedMemorySize, GSMEM1);
    cudaFuncSetAttribute(flash_mma, cudaFuncAttributeMaxDynamicSharedMemorySize, FSMEM);

    // 1) convert inputs to fp16 (single launch)
    {
        const int na = (M_ * C_) / 4, nb = (C3_ * C_) / 4, nc = (C_ * C_) / 4;
        const int tot = na + nb + nc;
        conv_f16x3<<<(tot + 255) / 256, 256>>>(x, xf, na, w_attn, waf, nb, w_proj, wpf, nc);
    }

    // 2) qkv = x @ w_attn^T  (fp16 out)
    {
        dim3 g(C3_ / 128, M_ / 128);
        gemm_f16_1t<__half><<<g, 256, GSMEM1>>>(xf, waf, qkv, C3_, C_);
    }

    // 3) RMSNorm + RoPE, head-major fp16 (q pre-scaled into exp2 domain)
    norm_rope_split<<<(B_ * T_ * H_) / 8, 256>>>(qkv, fcos, fsin, qw, kw, qh, kh, vh);

    // 4) causal flash attention -> yf (fp16)
    {
        dim3 g(T_ / 128, B_ * H_);
        flash_mma<<<g, 256, FSMEM>>>(qh, kh, vh, yf);
    }

    // 5) out = y @ w_proj^T  (fp32 out)
    {
        dim3 g(C_ / 128, M_ / 128);
        gemm_f16_1t<float><<<g, 256, GSMEM1>>>(yf, wpf, out, C_, C_);
    }
}

// round 17
// speedup vs baseline: 2.7370x; 1.0161x over previous
#include <cuda_runtime.h>
#include <cuda_fp16.h>
#include <cstdint>
#include <cstddef>

static constexpr int B_  = 2;
static constexpr int T_  = 2048;
static constexpr int C_  = 1024;
static constexpr int H_  = 16;
static constexpr int HD_ = 64;
static constexpr int C3_ = 3 * C_;
static constexpr int M_  = B_ * T_;      // 4096

// ---------------------------------------------------------------------------
// Scratch (__device__ globals; no allocation allowed)
// ---------------------------------------------------------------------------
__device__ __half g_qkv[(size_t)M_ * C3_];           // fp16 qkv (25 MB)
__device__ __half g_xf[(size_t)M_ * C_];             // x fp16
__device__ __half g_waf[(size_t)C3_ * C_];           // w_attn fp16
__device__ __half g_wpf[(size_t)C_ * C_];            // w_proj fp16
__device__ __half g_yf[(size_t)M_ * C_];             // attention out fp16
// head-major [B][H][T][64], 1-term fp16  (q pre-scaled by log2e/8)
__device__ __half g_qh[(size_t)M_ * C_];
__device__ __half g_kh[(size_t)M_ * C_];
__device__ __half g_vh[(size_t)M_ * C_];

// ---------------------------------------------------------------------------
// Helpers
// ---------------------------------------------------------------------------
__device__ __forceinline__ uint32_t smem_u32(const void* p) {
    uint32_t a;
    asm("{ .reg .u64 t; cvta.to.shared.u64 t, %1; cvt.u32.u64 %0, t; }" : "=r"(a) : "l"(p));
    return a;
}
#define SWZ128(o) ((o) ^ (((o) >> 3) & 0x70))

__device__ __forceinline__ void cp_async16(uint32_t dst, const void* src) {
    asm volatile("cp.async.cg.shared.global [%0], [%1], 16;" :: "r"(dst), "l"(src));
}
__device__ __forceinline__ void ldsm4(uint32_t& r0, uint32_t& r1, uint32_t& r2, uint32_t& r3,
                                      uint32_t addr) {
    asm volatile("ldmatrix.sync.aligned.m8n8.x4.shared.b16 {%0,%1,%2,%3}, [%4];"
                 : "=r"(r0), "=r"(r1), "=r"(r2), "=r"(r3) : "r"(addr));
}
__device__ __forceinline__ void ldsm4t(uint32_t& r0, uint32_t& r1, uint32_t& r2, uint32_t& r3,
                                       uint32_t addr) {
    asm volatile("ldmatrix.sync.aligned.m8n8.x4.trans.shared.b16 {%0,%1,%2,%3}, [%4];"
                 : "=r"(r0), "=r"(r1), "=r"(r2), "=r"(r3) : "r"(addr));
}
__device__ __forceinline__ void mma16816h(float* c, const uint32_t* a, const uint32_t* b) {
    asm volatile(
        "mma.sync.aligned.m16n8k16.row.col.f32.f16.f16.f32 "
        "{%0,%1,%2,%3}, {%4,%5,%6,%7}, {%8,%9}, {%0,%1,%2,%3};"
        : "+f"(c[0]), "+f"(c[1]), "+f"(c[2]), "+f"(c[3])
        : "r"(a[0]), "r"(a[1]), "r"(a[2]), "r"(a[3]), "r"(b[0]), "r"(b[1]));
}
__device__ __forceinline__ uint32_t pack_h2(float a, float b) {
    __half2 h(__float2half_rn(a), __float2half_rn(b));
    return *reinterpret_cast<uint32_t*>(&h);
}
__device__ __forceinline__ uint32_t ex2_h2(uint32_t x) {
    uint32_t y;
    asm("ex2.approx.f16x2 %0, %1;" : "=r"(y) : "r"(x));
    return y;
}

// ---------------------------------------------------------------------------
// fp32 -> fp16 convert, 3 arrays in one launch
// ---------------------------------------------------------------------------
__global__ __launch_bounds__(256)
void conv_f16x3(const float* __restrict__ a, __half* __restrict__ ao, int na,
                const float* __restrict__ b, __half* __restrict__ bo, int nb,
                const float* __restrict__ c, __half* __restrict__ co, int nc)
{
    int i = blockIdx.x * blockDim.x + threadIdx.x;
    const float* in;
    __half* out;
    if (i < na) { in = a; out = ao; }
    else if (i < na + nb) { in = b; out = bo; i -= na; }
    else if (i < na + nb + nc) { in = c; out = co; i -= na + nb; }
    else return;
    float4 v = reinterpret_cast<const float4*>(in)[i];
    reinterpret_cast<uint32_t*>(out)[2 * i]     = pack_h2(v.x, v.y);
    reinterpret_cast<uint32_t*>(out)[2 * i + 1] = pack_h2(v.z, v.w);
}

// ---------------------------------------------------------------------------
// Plain fp16 GEMM (NT): C = A @ B^T. 128x128 tile, BK=64, 8 warps.
// 3-stage cp.async ring; next-chunk loads issued after ks=0 compute.
// ---------------------------------------------------------------------------
static constexpr int GSMEM1 = 98304;   // 3 x 32768

template <typename TOut>
__global__ __launch_bounds__(256, 2)
void gemm_f16_1t(const __half* __restrict__ A, const __half* __restrict__ Bw,
                 TOut* __restrict__ Cout, int N, int K)
{
    extern __shared__ char smem[];
    const uint32_t smem_base = smem_u32(smem);
    const int tid  = threadIdx.x;
    const int lane = tid & 31;
    const int wid  = tid >> 5;
    const int wr = (wid >> 2) * 64;
    const int wc = (wid & 3) * 32;
    const int m0 = blockIdx.y * 128;
    const int n0 = blockIdx.x * 128;

    float acc[4][4][4];
#pragma unroll
    for (int mi = 0; mi < 4; mi++)
#pragma unroll
        for (int ni = 0; ni < 4; ni++)
#pragma unroll
            for (int e = 0; e < 4; e++) acc[mi][ni][e] = 0.f;

    const int NC = K >> 6;

    auto load_chunk = [&](int cg) {
        const uint32_t base = smem_base + (cg % 3) * 32768;
        const int k0 = cg * 64;
#pragma unroll
        for (int i = 0; i < 4; i++) {
            const int u = tid + 256 * i;
            const int row = u >> 3, ch = u & 7;
            const uint32_t so = SWZ128(row * 128 + ch * 16);
            cp_async16(base + so,         A  + (size_t)(m0 + row) * K + k0 + ch * 8);
            cp_async16(base + 16384 + so, Bw + (size_t)(n0 + row) * K + k0 + ch * 8);
        }
        asm volatile("cp.async.commit_group;");
    };

    auto ks_body = [&](uint32_t As, uint32_t Bs, int ks) {
        const int cbb = ks * 32;
        uint32_t b[4][2];
#pragma unroll
        for (int p = 0; p < 2; p++) {
            const int g = lane >> 3;
            const int r = wc + p * 16 + (g >> 1) * 8 + (lane & 7);
            const int cb = cbb + (g & 1) * 16;
            ldsm4(b[2 * p][0], b[2 * p][1], b[2 * p + 1][0], b[2 * p + 1][1],
                  Bs + SWZ128(r * 128 + cb));
        }
#pragma unroll
        for (int mi = 0; mi < 4; mi++) {
            const int r = wr + mi * 16 + (lane & 15);
            const int cb = cbb + (lane >> 4) * 16;
            uint32_t a[4];
            ldsm4(a[0], a[1], a[2], a[3], As + SWZ128(r * 128 + cb));
#pragma unroll
            for (int ni = 0; ni < 4; ni++)
                mma16816h(acc[mi][ni], a, b[ni]);
        }
    };

    load_chunk(0);
    load_chunk(1);
    for (int cg = 0; cg < NC; cg++) {
        if (cg + 1 < NC) asm volatile("cp.async.wait_group 1;");
        else             asm volatile("cp.async.wait_group 0;");
        __syncthreads();

        const uint32_t As = smem_base + (cg % 3) * 32768;
        const uint32_t Bs = As + 16384;
        ks_body(As, Bs, 0);
        if (cg + 2 < NC) load_chunk(cg + 2);
#pragma unroll
        for (int ks = 1; ks < 4; ks++) ks_body(As, Bs, ks);
    }

#pragma unroll
    for (int mi = 0; mi < 4; mi++) {
        const int m = m0 + wr + mi * 16 + (lane >> 2);
#pragma unroll
        for (int ni = 0; ni < 4; ni++) {
            const int n = n0 + wc + ni * 8 + (lane & 3) * 2;
            if constexpr (sizeof(TOut) == 2) {
                *reinterpret_cast<uint32_t*>((__half*)Cout + (size_t)m * N + n) =
                    pack_h2(acc[mi][ni][0], acc[mi][ni][1]);
                *reinterpret_cast<uint32_t*>((__half*)Cout + (size_t)(m + 8) * N + n) =
                    pack_h2(acc[mi][ni][2], acc[mi][ni][3]);
            } else {
                *reinterpret_cast<float2*>((float*)Cout + (size_t)m * N + n) =
                    make_float2(acc[mi][ni][0], acc[mi][ni][1]);
                *reinterpret_cast<float2*>((float*)Cout + (size_t)(m + 8) * N + n) =
                    make_float2(acc[mi][ni][2], acc[mi][ni][3]);
            }
        }
    }
}

// ---------------------------------------------------------------------------
// Fused per-head RMSNorm + RoPE, fp16 in / fp16 out, head-major [B][H][T][64].
// Q is pre-scaled by log2(e)/8 so flash scores land directly in exp2 domain.
// ---------------------------------------------------------------------------
static constexpr float EXP2_SCALE = 0.125f * 1.4426950408889634f;   // log2(e)/8

__global__ __launch_bounds__(256)
void norm_rope_split(const __half* __restrict__ qkv, const float* __restrict__ cosT,
                     const float* __restrict__ sinT, const float* __restrict__ qw,
                     const float* __restrict__ kw,
                     __half* __restrict__ qh, __half* __restrict__ kh,
                     __half* __restrict__ vh)
{
    const int gw = (blockIdx.x * blockDim.x + threadIdx.x) >> 5;
    const int lane = threadIdx.x & 31;
    const int h = gw & (H_ - 1);
    const int bt = gw >> 4;
    const int t = bt & (T_ - 1);
    const int b = bt >> 11;

    const __half* qp = qkv + (size_t)bt * C3_ + h * HD_;
    const __half* kp = qp + C_;
    const __half* vp = qp + 2 * C_;
    const size_t ho = (((size_t)(b * H_ + h) * T_) + t) * HD_ + 2 * lane;
    const float c = cosT[t * (HD_ / 2) + lane];
    const float s = sinT[t * (HD_ / 2) + lane];

    {
        float2 v = __half22float2(*reinterpret_cast<const __half2*>(qp + 2 * lane));
        float ss = v.x * v.x + v.y * v.y;
#pragma unroll
        for (int off = 16; off > 0; off >>= 1) ss += __shfl_xor_sync(0xffffffffu, ss, off);
        float rms = rsqrtf(ss * (1.f / HD_) + 1e-6f) * EXP2_SCALE;
        float x0 = v.x * rms * qw[2 * lane];
        float x1 = v.y * rms * qw[2 * lane + 1];
        *reinterpret_cast<uint32_t*>(qh + ho) = pack_h2(x0 * c - x1 * s, x0 * s + x1 * c);
    }
    {
        float2 v = __half22float2(*reinterpret_cast<const __half2*>(kp + 2 * lane));
        float ss = v.x * v.x + v.y * v.y;
#pragma unroll
        for (int off = 16; off > 0; off >>= 1) ss += __shfl_xor_sync(0xffffffffu, ss, off);
        float rms = rsqrtf(ss * (1.f / HD_) + 1e-6f);
        float x0 = v.x * rms * kw[2 * lane];
        float x1 = v.y * rms * kw[2 * lane + 1];
        *reinterpret_cast<uint32_t*>(kh + ho) = pack_h2(x0 * c - x1 * s, x0 * s + x1 * c);
    }
    {
        *reinterpret_cast<uint32_t*>(vh + ho) =
            *reinterpret_cast<const uint32_t*>(vp + 2 * lane);
    }
}

// ---------------------------------------------------------------------------
// fp16 flash attention, causal, max-free exp2 softmax.
// Row sums via ones-vector MMA (l = P @ 1); Q fragments hoisted (loop-invariant).
// BKV=128 per barrier (two 64-key sub-tiles), double-buffered.
// smem: Q 16K + 2 x 32K = 80 KB; 2 CTAs/SM.
// ---------------------------------------------------------------------------
static constexpr int FSMEM = 81920;

__global__ __launch_bounds__(256, 2)
void flash_mma(const __half* __restrict__ qh, const __half* __restrict__ kh,
               const __half* __restrict__ vh, __half* __restrict__ yf)
{
    extern __shared__ char smem[];
    const uint32_t sb = smem_u32(smem);
    const int tid = threadIdx.x, lane = tid & 31, wid = tid >> 5;
    const int gid = lane >> 2, tig = lane & 3;
    const int bh = blockIdx.y;
    const int q0 = (gridDim.x - 1 - blockIdx.x) * 128;   // heavy tiles first
    const size_t head = (size_t)bh * T_ * HD_;

    const uint32_t QS = sb;
    auto KV = [&](int buf, int sub, int which) -> uint32_t {
        return sb + 16384 + buf * 32768 + sub * 16384 + which * 8192;
    };

    auto load_tile128 = [&](int t128, int buf) {
        const int kr0 = t128 * 128;
#pragma unroll
        for (int i = 0; i < 4; i++) {
            int u = tid + 256 * i, r = u >> 3, ch = u & 7;
            int sub = r >> 6, lr = r & 63;
            uint32_t so = SWZ128(lr * 128 + ch * 16);
            size_t go = head + (size_t)(kr0 + r) * HD_ + ch * 8;
            cp_async16(KV(buf, sub, 0) + so, kh + go);
            cp_async16(KV(buf, sub, 1) + so, vh + go);
        }
        asm volatile("cp.async.commit_group;");
    };

    {
#pragma unroll
        for (int i = 0; i < 4; i++) {
            int u = tid + 256 * i, r = u >> 3, ch = u & 7;
            uint32_t so = SWZ128(r * 128 + ch * 16);
            cp_async16(QS + so, qh + head + (size_t)(q0 + r) * HD_ + ch * 8);
        }
        load_tile128(0, 0);
    }

    float O[8][4];
#pragma unroll
    for (int nt = 0; nt < 8; nt++)
#pragma unroll
        for (int e = 0; e < 4; e++) O[nt][e] = 0.f;
    float lacc[4] = {0.f, 0.f, 0.f, 0.f};      // row sums via ones-MMA
    const uint32_t ones2 = 0x3C003C00u;        // (half)1.0 x2
    uint32_t bones[2] = { ones2, ones2 };

    uint32_t qa[4][4];                         // hoisted Q fragments

    const int warp_top = q0 + wid * 16;
    const int niter = q0 / 128 + 1;

    for (int it = 0; it < niter; it++) {
        asm volatile("cp.async.wait_group 0;");
        __syncthreads();
        const int buf = it & 1;

        if (it == 0) {
#pragma unroll
            for (int ks = 0; ks < 4; ks++)
                ldsm4(qa[ks][0], qa[ks][1], qa[ks][2], qa[ks][3],
                      QS + SWZ128((wid * 16 + (lane & 15)) * 128 +
                                  (ks * 16 + (lane >> 4) * 8) * 2));
        }

#pragma unroll
        for (int sub = 0; sub < 2; sub++) {
            const int j0 = it * 128 + sub * 64;
            if (j0 <= warp_top + 15) {
                // ---- S = Q K^T (log2-domain scores) ----
                float S[8][4];
#pragma unroll
                for (int nt = 0; nt < 8; nt++)
#pragma unroll
                    for (int e = 0; e < 4; e++) S[nt][e] = 0.f;

                const uint32_t Kb = KV(buf, sub, 0);
#pragma unroll
                for (int ks = 0; ks < 4; ks++) {
                    const int k0 = ks * 16;
                    uint32_t b[8][2];
#pragma unroll
                    for (int p = 0; p < 4; p++) {
                        const int g = lane >> 3;
                        const int r = p * 16 + (g >> 1) * 8 + (lane & 7);
                        ldsm4(b[2 * p][0], b[2 * p][1], b[2 * p + 1][0], b[2 * p + 1][1],
                              Kb + SWZ128(r * 128 + (k0 + (g & 1) * 8) * 2));
                    }
#pragma unroll
                    for (int nt = 0; nt < 8; nt++) mma16816h(S[nt], qa[ks], b[nt]);
                }

                // ---- mask ----
                const int qi0 = warp_top + gid;
                if (j0 + 63 > warp_top) {
#pragma unroll
                    for (int nt = 0; nt < 8; nt++)
#pragma unroll
                        for (int e = 0; e < 4; e++) {
                            const int kj = j0 + nt * 8 + 2 * tig + (e & 1);
                            const int qi = qi0 + ((e >= 2) ? 8 : 0);
                            if (kj > qi) S[nt][e] = -100000.f;
                        }
                }

                // ---- P = ex2(S) fp16x2 ----
                uint32_t P[4][4];
#pragma unroll
                for (int kt = 0; kt < 4; kt++) {
                    P[kt][0] = ex2_h2(pack_h2(S[2 * kt][0],     S[2 * kt][1]));
                    P[kt][1] = ex2_h2(pack_h2(S[2 * kt][2],     S[2 * kt][3]));
                    P[kt][2] = ex2_h2(pack_h2(S[2 * kt + 1][0], S[2 * kt + 1][1]));
                    P[kt][3] = ex2_h2(pack_h2(S[2 * kt + 1][2], S[2 * kt + 1][3]));
                }

                // ---- row sums: lacc += P @ ones ----
#pragma unroll
                for (int kt = 0; kt < 4; kt++) mma16816h(lacc, P[kt], bones);

                // ---- O += P V ----
                const uint32_t Vb = KV(buf, sub, 1);
#pragma unroll
                for (int ks = 0; ks < 4; ks++) {
                    uint32_t vb[8][2];
#pragma unroll
                    for (int p = 0; p < 4; p++) {
                        const int g = lane >> 3;
                        const int r = ks * 16 + (g & 1) * 8 + (lane & 7);
                        const int cb = (p * 16 + (g >> 1) * 8) * 2;
                        ldsm4t(vb[2 * p][0], vb[2 * p][1], vb[2 * p + 1][0], vb[2 * p + 1][1],
                               Vb + SWZ128(r * 128 + cb));
                    }
#pragma unroll
                    for (int nt = 0; nt < 8; nt++) mma16816h(O[nt], P[ks], vb[nt]);
                }
            }
            if (sub == 0 && it + 1 < niter) load_tile128(it + 1, 1 - buf);
        }
    }

    // ---- epilogue: y = O / l -> fp16, layout [bt][h*64+d] ----
    const float inv0 = 1.0f / lacc[0], inv1 = 1.0f / lacc[2];
    const int b = bh >> 4, h = bh & 15;
    const size_t row0 = ((size_t)(b * T_ + warp_top + gid)) * C_ + h * HD_;
    const size_t row1 = row0 + (size_t)8 * C_;
#pragma unroll
    for (int nt = 0; nt < 8; nt++) {
        const int col = nt * 8 + 2 * tig;
        *reinterpret_cast<uint32_t*>(yf + row0 + col) = pack_h2(O[nt][0] * inv0, O[nt][1] * inv0);
        *reinterpret_cast<uint32_t*>(yf + row1 + col) = pack_h2(O[nt][2] * inv1, O[nt][3] * inv1);
    }
}

// ---------------------------------------------------------------------------
extern "C" void kernel_launch(void* const* d_in, const int* in_sizes, int n_in,
                              void* d_out, int out_size)
{
    const float* x      = (const float*)d_in[0];
    const float* fcos   = (const float*)d_in[1];
    const float* fsin   = (const float*)d_in[2];
    const float* w_attn = (const float*)d_in[3];
    const float* w_proj = (const float*)d_in[4];
    const float* qw     = (const float*)d_in[5];
    const float* kw     = (const float*)d_in[6];
    float* out = (float*)d_out;

    __half *qkv, *xf, *waf, *wpf, *yf, *qh, *kh, *vh;
    cudaGetSymbolAddress((void**)&qkv, g_qkv);
    cudaGetSymbolAddress((void**)&xf,  g_xf);
    cudaGetSymbolAddress((void**)&waf, g_waf);
    cudaGetSymbolAddress((void**)&wpf, g_wpf);
    cudaGetSymbolAddress((void**)&yf,  g_yf);
    cudaGetSymbolAddress((void**)&qh,  g_qh);
    cudaGetSymbolAddress((void**)&kh,  g_kh);
    cudaGetSymbolAddress((void**)&vh,  g_vh);

    cudaFuncSetAttribute(gemm_f16_1t<__half>, cudaFuncAttributeMaxDynamicSharedMemorySize, GSMEM1);
    cudaFuncSetAttribute(gemm_f16_1t<float>,  cudaFuncAttributeMaxDynamicSharedMemorySize, GSMEM1);
    cudaFuncSetAttribute(flash_mma, cudaFuncAttributeMaxDynamicSharedMemorySize, FSMEM);

    // 1) convert inputs to fp16 (single launch)
    {
        const int na = (M_ * C_) / 4, nb = (C3_ * C_) / 4, nc = (C_ * C_) / 4;
        const int tot = na + nb + nc;
        conv_f16x3<<<(tot + 255) / 256, 256>>>(x, xf, na, w_attn, waf, nb, w_proj, wpf, nc);
    }

    // 2) qkv = x @ w_attn^T  (fp16 out)
    {
        dim3 g(C3_ / 128, M_ / 128);
        gemm_f16_1t<__half><<<g, 256, GSMEM1>>>(xf, waf, qkv, C3_, C_);
    }

    // 3) RMSNorm + RoPE, head-major fp16 (q pre-scaled into exp2 domain)
    norm_rope_split<<<(B_ * T_ * H_) / 8, 256>>>(qkv, fcos, fsin, qw, kw, qh, kh, vh);

    // 4) causal flash attention -> yf (fp16)
    {
        dim3 g(T_ / 128, B_ * H_);
        flash_mma<<<g, 256, FSMEM>>>(qh, kh, vh, yf);
    }

    // 5) out = y @ w_proj^T  (fp32 out)
    {
        dim3 g(C_ / 128, M_ / 128);
        gemm_f16_1t<float><<<g, 256, GSMEM1>>>(yf, wpf, out, C_, C_);
    }
}